// round 9
// baseline (speedup 1.0000x reference)
#include <cuda_runtime.h>
#include <cuda_fp16.h>
#include <cstdint>
#include <cstddef>

// Problem constants
constexpr int H_   = 32;
constexpr int D_   = 128;
constexpr int HID_ = 4096;   // H*D
constexpr int B_   = 4;
constexpr int S_   = 1024;
constexpr int T_   = 4096;   // B*S
constexpr float SCALE_ = 0.08838834764831845f;  // D^-0.5

// Scratch (allocation-free rule: __device__ globals)
__device__ __half g_Ah[(size_t)T_ * HID_];       // A hi (hidden, then ctx)
__device__ __half g_Bh[(size_t)HID_ * 3 * HID_]; // B^T hi, row-major [N][K]
__device__ __half g_Bl[(size_t)HID_ * 3 * HID_]; // B^T lo
// Attention fp16 operands (written by fused QKV epilogue)
__device__ __half g_Qh[(size_t)T_ * HID_];       // pre-scaled by SCALE_
__device__ __half g_Ql[(size_t)T_ * HID_];
__device__ __half g_Kh[(size_t)T_ * HID_];
__device__ __half g_Kl[(size_t)T_ * HID_];
__device__ __half g_Vh[(size_t)T_ * HID_];
__device__ __half g_Vl[(size_t)T_ * HID_];

// ---------------------------------------------------------------------------
// helpers
// ---------------------------------------------------------------------------
__device__ __forceinline__ uint32_t smem_u32(const void* p) {
    uint32_t a;
    asm("{ .reg .u64 t; cvta.to.shared.u64 t, %1; cvt.u32.u64 %0, t; }"
        : "=r"(a) : "l"(p));
    return a;
}
__device__ __forceinline__ void cp16(uint32_t dst, const void* src) {
    asm volatile("cp.async.cg.shared.global [%0], [%1], 16;" :: "r"(dst), "l"(src));
}
__device__ __forceinline__ void cp_commit() { asm volatile("cp.async.commit_group;"); }
template<int Ngrp> __device__ __forceinline__ void cp_wait() {
    asm volatile("cp.async.wait_group %0;" :: "n"(Ngrp));
}
__device__ __forceinline__ void ldsm4(uint32_t* r, uint32_t addr) {
    asm volatile("ldmatrix.sync.aligned.m8n8.x4.shared.b16 {%0,%1,%2,%3}, [%4];"
                 : "=r"(r[0]), "=r"(r[1]), "=r"(r[2]), "=r"(r[3]) : "r"(addr));
}
__device__ __forceinline__ void ldsm4t(uint32_t* r, uint32_t addr) {
    asm volatile("ldmatrix.sync.aligned.m8n8.x4.trans.shared.b16 {%0,%1,%2,%3}, [%4];"
                 : "=r"(r[0]), "=r"(r[1]), "=r"(r[2]), "=r"(r[3]) : "r"(addr));
}
__device__ __forceinline__ void mma16816(float* c, const uint32_t* a, const uint32_t* b) {
    asm volatile("mma.sync.aligned.m16n8k16.row.col.f32.f16.f16.f32 "
                 "{%0,%1,%2,%3}, {%4,%5,%6,%7}, {%8,%9}, {%0,%1,%2,%3};"
                 : "+f"(c[0]), "+f"(c[1]), "+f"(c[2]), "+f"(c[3])
                 : "r"(a[0]), "r"(a[1]), "r"(a[2]), "r"(a[3]), "r"(b[0]), "r"(b[1]));
}
__device__ __forceinline__ uint32_t packh2(float x, float y) {
    __half2 p = __halves2half2(__float2half_rn(x), __float2half_rn(y));
    return *(uint32_t*)&p;
}
__device__ __forceinline__ void emit_hilo(__half* hi, __half* lo, size_t off,
                                          float x, float y) {
    __half h0 = __float2half_rn(x), h1 = __float2half_rn(y);
    *(uint32_t*)(hi + off) = packh2(x, y);
    *(uint32_t*)(lo + off) = packh2(x - __half2float(h0), y - __half2float(h1));
}

// ---------------------------------------------------------------------------
// convH: fp32 row-major -> fp16 hi row-major (8 elems / thread)
// ---------------------------------------------------------------------------
__global__ __launch_bounds__(256)
void convH_kernel(const float* __restrict__ src, __half* __restrict__ hi)
{
    size_t base = ((size_t)blockIdx.x * 256 + threadIdx.x) * 8;
    const float4* s = (const float4*)(src + base);
    float4 a = s[0], b = s[1];
    float x[8] = {a.x, a.y, a.z, a.w, b.x, b.y, b.z, b.w};
    uint4 uh;
    uint32_t* ph = (uint32_t*)&uh;
    #pragma unroll
    for (int j = 0; j < 4; j++) ph[j] = packh2(x[2*j], x[2*j+1]);
    *(uint4*)(hi + base) = uh;
}

// ---------------------------------------------------------------------------
// convT: fp32 [K, N] -> transposed fp16 hi/lo [N, K].  32x32 smem tiles.
// ---------------------------------------------------------------------------
__global__ __launch_bounds__(256)
void convT_kernel(const float* __restrict__ w, __half* __restrict__ hi,
                  __half* __restrict__ lo, int K, int N)
{
    __shared__ float t[32][33];
    const int k0 = blockIdx.x * 32, n0 = blockIdx.y * 32;
    const int tx = threadIdx.x & 31, ty = threadIdx.x >> 5;
    #pragma unroll
    for (int i = 0; i < 32; i += 8)
        t[ty + i][tx] = w[(size_t)(k0 + ty + i) * N + n0 + tx];
    __syncthreads();
    #pragma unroll
    for (int i = 0; i < 32; i += 8) {
        float x = t[tx][ty + i];
        __half h = __float2half_rn(x);
        __half l = __float2half_rn(x - __half2float(h));
        size_t o = (size_t)(n0 + ty + i) * K + k0 + tx;
        hi[o] = h;
        lo[o] = l;
    }
}

// ---------------------------------------------------------------------------
// HGEMM: 2-term split (ah*bh + ah*bl), fp32 accum, 128x128 CTA tile, BK=32,
// 3-stage cp.async, 128 threads (2x2 warps, 64x64 warp tile), 2 CTAs/SM.
// FUSED=true (QKV): epilogue applies RoPE + emits attention operands + caches.
// FUSED=false (O-proj): plain fp32 C write.
// ---------------------------------------------------------------------------
constexpr int G_STAGE = 24576;
constexpr int G_SMEM  = 3 * G_STAGE;      // 72 KB

template<bool FUSED>
__global__ __launch_bounds__(128, 2)
void hgemm_kernel(const __half* __restrict__ Ah,
                  const __half* __restrict__ Bh, const __half* __restrict__ Bl,
                  float* __restrict__ C, int N, int K,
                  const float* __restrict__ cosT, const float* __restrict__ sinT,
                  float* __restrict__ kc, float* __restrict__ vc)
{
    extern __shared__ char sm[];
    const int tid  = threadIdx.x;
    const int wid  = tid >> 5, lane = tid & 31;
    const int bm = blockIdx.x, bn = blockIdx.y;
    const int wm = (wid >> 1) * 64;
    const int wn = (wid & 1) * 64;
    const int KT = K / 32;
    const uint32_t sb = smem_u32(sm);

    const __half* aop = Ah + (size_t)bm * 128 * K;
    const __half* bop[2] = {Bh + (size_t)bn * 128 * K, Bl + (size_t)bn * 128 * K};

    auto prefetch = [&](int kt) {
        const uint32_t st = sb + (kt % 3) * G_STAGE;
        #pragma unroll
        for (int op = 0; op < 3; op++) {
            const __half* src = (op == 0) ? aop : bop[op - 1];
            #pragma unroll
            for (int h4 = 0; h4 < 4; h4++) {
                int ch = h4 * 128 + tid;
                int row = ch >> 2, c = ch & 3;
                cp16(st + op * 8192 + row * 64 + ((c ^ (row & 3)) << 4),
                     src + (size_t)row * K + kt * 32 + c * 8);
            }
        }
        cp_commit();
    };

    prefetch(0);
    if (KT > 1) prefetch(1);

    float acc[4][8][4] = {};

    for (int kt = 0; kt < KT; kt++) {
        if (kt + 1 < KT) cp_wait<1>(); else cp_wait<0>();
        __syncthreads();
        if (kt + 2 < KT) prefetch(kt + 2);

        const uint32_t st = sb + (kt % 3) * G_STAGE;
        #pragma unroll
        for (int ks = 0; ks < 2; ks++) {
            uint32_t ahf[4][4], bhf[4][4], blf[4][4];
            #pragma unroll
            for (int mt = 0; mt < 4; mt++) {
                int row = wm + mt * 16 + (lane & 15);
                int c   = ks * 2 + (lane >> 4);
                ldsm4(ahf[mt], st + row * 64 + ((c ^ (row & 3)) << 4));
            }
            #pragma unroll
            for (int p = 0; p < 4; p++) {
                int n = wn + p * 16 + ((lane >> 4) << 3) + (lane & 7);
                int c = ks * 2 + ((lane >> 3) & 1);
                uint32_t addr = st + 8192 + n * 64 + ((c ^ (n & 3)) << 4);
                ldsm4(bhf[p], addr);
                ldsm4(blf[p], addr + 8192);
            }
            #pragma unroll
            for (int mt = 0; mt < 4; mt++)
                #pragma unroll
                for (int nt = 0; nt < 8; nt++) {
                    const uint32_t* bh2 = &bhf[nt >> 1][(nt & 1) * 2];
                    const uint32_t* bl2 = &blf[nt >> 1][(nt & 1) * 2];
                    mma16816(acc[mt][nt], ahf[mt], bh2);
                    mma16816(acc[mt][nt], ahf[mt], bl2);
                }
        }
    }

    if (!FUSED) {
        #pragma unroll
        for (int mt = 0; mt < 4; mt++)
            #pragma unroll
            for (int nt = 0; nt < 8; nt++) {
                int r0  = bm * 128 + wm + mt * 16 + (lane >> 2);
                int col = bn * 128 + wn + nt * 8 + (lane & 3) * 2;
                *(float2*)(C + (size_t)r0 * N + col) =
                    make_float2(acc[mt][nt][0], acc[mt][nt][1]);
                *(float2*)(C + (size_t)(r0 + 8) * N + col) =
                    make_float2(acc[mt][nt][2], acc[mt][nt][3]);
            }
    } else {
        // section: 0=Q, 1=K, 2=V (bn tile spans one head of one section)
        const int section = bn >> 5;            // bn / 32
        #pragma unroll
        for (int mt = 0; mt < 4; mt++) {
            const int r0 = bm * 128 + wm + mt * 16 + (lane >> 2);
            const int r1 = r0 + 8;
            #pragma unroll
            for (int nt = 0; nt < 8; nt++) {
                const int colh = (bn & 31) * 128 + wn + nt * 8 + (lane & 3) * 2;
                const size_t off0 = (size_t)r0 * HID_ + colh;
                const size_t off1 = (size_t)r1 * HID_ + colh;
                float v0 = acc[mt][nt][0], v1 = acc[mt][nt][1];
                float v2 = acc[mt][nt][2], v3 = acc[mt][nt][3];
                if (section == 2) {
                    *(float2*)(vc + off0) = make_float2(v0, v1);
                    *(float2*)(vc + off1) = make_float2(v2, v3);
                    emit_hilo(g_Vh, g_Vl, off0, v0, v1);
                    emit_hilo(g_Vh, g_Vl, off1, v2, v3);
                } else {
                    const int i = (colh & 127) >> 1;
                    float c0 = cosT[r0 * 64 + i], s0 = sinT[r0 * 64 + i];
                    float c1 = cosT[r1 * 64 + i], s1 = sinT[r1 * 64 + i];
                    float a0 = v0 * c0 - v1 * s0, a1 = v1 * c0 + v0 * s0;
                    float b0 = v2 * c1 - v3 * s1, b1 = v3 * c1 + v2 * s1;
                    if (section == 0) {
                        // Q: pre-scale by SCALE_ (fattn no longer scales)
                        a0 *= SCALE_; a1 *= SCALE_; b0 *= SCALE_; b1 *= SCALE_;
                        emit_hilo(g_Qh, g_Ql, off0, a0, a1);
                        emit_hilo(g_Qh, g_Ql, off1, b0, b1);
                    } else {
                        *(float2*)(kc + off0) = make_float2(a0, a1);
                        *(float2*)(kc + off1) = make_float2(b0, b1);
                        emit_hilo(g_Kh, g_Kl, off0, a0, a1);
                        emit_hilo(g_Kh, g_Kl, off1, b0, b1);
                    }
                }
            }
        }
    }
}

// ---------------------------------------------------------------------------
// Flash attention on mma.sync, fp16 hi/lo split (3-term).
// Q pre-scaled by SCALE_. Epilogue writes ctx fp16 hi into g_Ah.
// ---------------------------------------------------------------------------
constexpr int FA_ST = 34816;          // stage size in halfs (4 * 8704)
constexpr int FA_SMEM_BYTES = (34816 + 2 * 34816) * 2;   // 208896

__global__ __launch_bounds__(256, 1)
void fattn_kernel()
{
    extern __shared__ __half fsm[];
    const int tid = threadIdx.x;
    const int wid = tid >> 5, lane = tid & 31;
    const int qt = 7 - blockIdx.x;
    const int h = blockIdx.y, b = blockIdx.z;
    const int t0 = b * S_ + qt * 128;
    const int wrow = wid * 16;
    const uint32_t sb = smem_u32(fsm);

    {
        const __half* qsrc[2] = {g_Qh, g_Ql};
        #pragma unroll
        for (int a = 0; a < 2; a++)
            #pragma unroll
            for (int j = 0; j < 8; j++) {
                int ch = j * 256 + tid;
                int r = ch >> 4, c = ch & 15;
                cp16(sb + (a * 17408 + r * 136 + c * 8) * 2,
                     qsrc[a] + (size_t)(t0 + r) * HID_ + h * D_ + c * 8);
            }
    }

    auto kvload = [&](int kt) {
        const uint32_t dstb = sb + (FA_ST + (kt & 1) * FA_ST) * 2;
        const int tk0 = b * S_ + kt * 64;
        const __half* srcs[4] = {g_Kh, g_Kl, g_Vh, g_Vl};
        #pragma unroll
        for (int a = 0; a < 4; a++)
            #pragma unroll
            for (int j = 0; j < 4; j++) {
                int ch = j * 256 + tid;
                int r = ch >> 4, c = ch & 15;
                cp16(dstb + (a * 8704 + r * 136 + c * 8) * 2,
                     srcs[a] + (size_t)(tk0 + r) * HID_ + h * D_ + c * 8);
            }
        cp_commit();
    };

    const int ktmax = 2 * qt + 1;
    kvload(0);

    float acc[16][4] = {};
    float m_i[2] = {-1e30f, -1e30f};
    float l_i[2] = {0.f, 0.f};

    for (int kt = 0; kt <= ktmax; kt++) {
        if (kt + 1 <= ktmax) { kvload(kt + 1); cp_wait<1>(); }
        else cp_wait<0>();
        __syncthreads();

        const uint32_t stb = sb + (FA_ST + (kt & 1) * FA_ST) * 2;
        const bool active = (kt * 64 <= qt * 128 + wrow + 15);

        if (active) {
            float s[8][4] = {};
            #pragma unroll
            for (int ks = 0; ks < 8; ks++) {
                uint32_t qh[4], ql[4];
                {
                    int row = wrow + (lane & 15);
                    int seg = ks * 16 + 8 * (lane >> 4);
                    uint32_t addr = sb + (row * 136 + seg) * 2;
                    ldsm4(qh, addr);
                    ldsm4(ql, addr + 17408 * 2);
                }
                #pragma unroll
                for (int np = 0; np < 4; np++) {
                    uint32_t kh[4], kl[4];
                    int n = np * 16 + ((lane >> 4) << 3) + (lane & 7);
                    int seg = ks * 16 + 8 * ((lane >> 3) & 1);
                    uint32_t addr = stb + (n * 136 + seg) * 2;
                    ldsm4(kh, addr);
                    ldsm4(kl, addr + 8704 * 2);
                    #pragma unroll
                    for (int half_ = 0; half_ < 2; half_++) {
                        float* st_ = s[np * 2 + half_];
                        const uint32_t* bh2 = &kh[half_ * 2];
                        const uint32_t* bl2 = &kl[half_ * 2];
                        mma16816(st_, qh, bh2);
                        mma16816(st_, qh, bl2);
                        mma16816(st_, ql, bh2);
                    }
                }
            }

            const int rbase = qt * 128 + wrow + (lane >> 2);
            if (kt * 64 + 63 > qt * 128 + wrow) {
                #pragma unroll
                for (int j = 0; j < 8; j++)
                    #pragma unroll
                    for (int cc = 0; cc < 4; cc++) {
                        int colg = kt * 64 + j * 8 + (lane & 3) * 2 + (cc & 1);
                        int rowg = rbase + (cc >> 1) * 8;
                        if (colg > rowg) s[j][cc] = -1e30f;
                    }
            }

            #pragma unroll
            for (int hr = 0; hr < 2; hr++) {
                float rm = -1e30f;
                #pragma unroll
                for (int j = 0; j < 8; j++)
                    rm = fmaxf(rm, fmaxf(s[j][hr * 2], s[j][hr * 2 + 1]));
                rm = fmaxf(rm, __shfl_xor_sync(0xffffffffu, rm, 1));
                rm = fmaxf(rm, __shfl_xor_sync(0xffffffffu, rm, 2));
                float nm  = fmaxf(m_i[hr], rm);
                float fac = __expf(m_i[hr] - nm);
                m_i[hr] = nm;
                float rs = 0.f;
                #pragma unroll
                for (int j = 0; j < 8; j++) {
                    float p0 = __expf(s[j][hr * 2]     - nm);
                    float p1 = __expf(s[j][hr * 2 + 1] - nm);
                    s[j][hr * 2]     = p0;
                    s[j][hr * 2 + 1] = p1;
                    rs += p0 + p1;
                }
                rs += __shfl_xor_sync(0xffffffffu, rs, 1);
                rs += __shfl_xor_sync(0xffffffffu, rs, 2);
                l_i[hr] = l_i[hr] * fac + rs;
                #pragma unroll
                for (int nt = 0; nt < 16; nt++) {
                    acc[nt][hr * 2]     *= fac;
                    acc[nt][hr * 2 + 1] *= fac;
                }
            }

            uint32_t aH[4][4], aL[4][4];
            #pragma unroll
            for (int ks = 0; ks < 4; ks++) {
                #pragma unroll
                for (int half_ = 0; half_ < 2; half_++) {
                    const float* sj = s[ks * 2 + half_];
                    #pragma unroll
                    for (int rr = 0; rr < 2; rr++) {
                        float x0 = sj[rr * 2], x1 = sj[rr * 2 + 1];
                        __half h0 = __float2half_rn(x0), h1 = __float2half_rn(x1);
                        aH[ks][half_ * 2 + rr] = packh2(x0, x1);
                        aL[ks][half_ * 2 + rr] = packh2(x0 - __half2float(h0),
                                                        x1 - __half2float(h1));
                    }
                }
            }

            #pragma unroll
            for (int ks = 0; ks < 4; ks++) {
                #pragma unroll
                for (int ntp = 0; ntp < 8; ntp++) {
                    uint32_t vh[4], vl[4];
                    int kr = ks * 16 + (lane & 7) + 8 * ((lane >> 3) & 1);
                    int nc = ntp * 16 + 8 * (lane >> 4);
                    uint32_t addr = stb + (17408 + kr * 136 + nc) * 2;
                    ldsm4t(vh, addr);
                    ldsm4t(vl, addr + 8704 * 2);
                    #pragma unroll
                    for (int half_ = 0; half_ < 2; half_++) {
                        float* ot = acc[ntp * 2 + half_];
                        const uint32_t* bh2 = &vh[half_ * 2];
                        const uint32_t* bl2 = &vl[half_ * 2];
                        mma16816(ot, aH[ks], bh2);
                        mma16816(ot, aH[ks], bl2);
                        mma16816(ot, aL[ks], bh2);
                    }
                }
            }
        }
        __syncthreads();
    }

    float inv0 = 1.0f / l_i[0], inv1 = 1.0f / l_i[1];
    #pragma unroll
    for (int nt = 0; nt < 16; nt++) {
        float o0 = acc[nt][0] * inv0, o1 = acc[nt][1] * inv0;
        float o2 = acc[nt][2] * inv1, o3 = acc[nt][3] * inv1;
        size_t col = (size_t)h * D_ + nt * 8 + (lane & 3) * 2;
        size_t r0 = (size_t)(t0 + wrow + (lane >> 2)) * HID_ + col;
        size_t r1 = r0 + 8 * HID_;
        *(uint32_t*)(g_Ah + r0) = packh2(o0, o1);
        *(uint32_t*)(g_Ah + r1) = packh2(o2, o3);
    }
}

// ---------------------------------------------------------------------------
// Launch
// ---------------------------------------------------------------------------
extern "C" void kernel_launch(void* const* d_in, const int* in_sizes, int n_in,
                              void* d_out, int out_size)
{
    const float* hidden = (const float*)d_in[0];
    const float* cosT   = (const float*)d_in[1];
    const float* sinT   = (const float*)d_in[2];
    const float* w_qkv  = (const float*)d_in[3];
    const float* w_o    = (const float*)d_in[4];

    float* out = (float*)d_out;
    float* kc  = out + (size_t)T_ * HID_;
    float* vc  = kc + (size_t)T_ * HID_;

    __half *ahp = nullptr, *bhp = nullptr, *blp = nullptr;
    cudaGetSymbolAddress((void**)&ahp, g_Ah);
    cudaGetSymbolAddress((void**)&bhp, g_Bh);
    cudaGetSymbolAddress((void**)&blp, g_Bl);

    cudaFuncSetAttribute(hgemm_kernel<true>,
                         cudaFuncAttributeMaxDynamicSharedMemorySize, G_SMEM);
    cudaFuncSetAttribute(hgemm_kernel<false>,
                         cudaFuncAttributeMaxDynamicSharedMemorySize, G_SMEM);
    cudaFuncSetAttribute(fattn_kernel,
                         cudaFuncAttributeMaxDynamicSharedMemorySize, FA_SMEM_BYTES);

    // 1) convert hidden (hi only) + w_qkv (hi/lo, transposed)
    convH_kernel<<<(int)((size_t)T_ * HID_ / 8 / 256), 256>>>(hidden, ahp);
    convT_kernel<<<dim3(HID_ / 32, 3 * HID_ / 32), 256>>>(w_qkv, bhp, blp,
                                                          HID_, 3 * HID_);
    // 2) QKV GEMM with fused RoPE + cache + fp16 operand emit
    hgemm_kernel<true><<<dim3(T_ / 128, 3 * HID_ / 128), 128, G_SMEM>>>(
        ahp, bhp, blp, nullptr, 3 * HID_, HID_, cosT, sinT, kc, vc);
    // 3) flash attention (3-term mma.sync) -> ctx fp16 into g_Ah
    fattn_kernel<<<dim3(S_ / 128, H_, B_), 256, FA_SMEM_BYTES>>>();
    // 4) convert w_o, output projection (2-term) -> out
    convT_kernel<<<dim3(HID_ / 32, HID_ / 32), 256>>>(w_o, bhp, blp, HID_, HID_);
    hgemm_kernel<false><<<dim3(T_ / 128, HID_ / 128), 128, G_SMEM>>>(
        ahp, bhp, blp, out, HID_, HID_, nullptr, nullptr, nullptr, nullptr);
}

// round 10
// speedup vs baseline: 1.0355x; 1.0355x over previous
#include <cuda_runtime.h>
#include <cuda_fp16.h>
#include <cstdint>
#include <cstddef>

// Problem constants
constexpr int H_   = 32;
constexpr int D_   = 128;
constexpr int HID_ = 4096;   // H*D
constexpr int B_   = 4;
constexpr int S_   = 1024;
constexpr int T_   = 4096;   // B*S
constexpr float SCALE_ = 0.08838834764831845f;  // D^-0.5

// Scratch (allocation-free rule: __device__ globals)
__device__ float g_qkv[(size_t)T_ * 3 * HID_];   // [T, 3*HID]
// GEMM fp16 operands (A: hi only — 2-term split)
__device__ __half g_Ah[(size_t)T_ * HID_];       // A hi (hidden, then ctx)
__device__ __half g_Bh[(size_t)HID_ * 3 * HID_]; // B^T hi, row-major [N][K]
__device__ __half g_Bl[(size_t)HID_ * 3 * HID_]; // B^T lo
// Attention fp16 operands (written by rope kernel)
__device__ __half g_Qh[(size_t)T_ * HID_];
__device__ __half g_Ql[(size_t)T_ * HID_];
__device__ __half g_Kh[(size_t)T_ * HID_];
__device__ __half g_Kl[(size_t)T_ * HID_];
__device__ __half g_Vh[(size_t)T_ * HID_];
__device__ __half g_Vl[(size_t)T_ * HID_];

// ---------------------------------------------------------------------------
// helpers
// ---------------------------------------------------------------------------
__device__ __forceinline__ uint32_t smem_u32(const void* p) {
    uint32_t a;
    asm("{ .reg .u64 t; cvta.to.shared.u64 t, %1; cvt.u32.u64 %0, t; }"
        : "=r"(a) : "l"(p));
    return a;
}
__device__ __forceinline__ void cp16(uint32_t dst, const void* src) {
    asm volatile("cp.async.cg.shared.global [%0], [%1], 16;" :: "r"(dst), "l"(src));
}
__device__ __forceinline__ void cp_commit() { asm volatile("cp.async.commit_group;"); }
template<int Ngrp> __device__ __forceinline__ void cp_wait() {
    asm volatile("cp.async.wait_group %0;" :: "n"(Ngrp));
}
__device__ __forceinline__ void ldsm4(uint32_t* r, uint32_t addr) {
    asm volatile("ldmatrix.sync.aligned.m8n8.x4.shared.b16 {%0,%1,%2,%3}, [%4];"
                 : "=r"(r[0]), "=r"(r[1]), "=r"(r[2]), "=r"(r[3]) : "r"(addr));
}
__device__ __forceinline__ void ldsm4t(uint32_t* r, uint32_t addr) {
    asm volatile("ldmatrix.sync.aligned.m8n8.x4.trans.shared.b16 {%0,%1,%2,%3}, [%4];"
                 : "=r"(r[0]), "=r"(r[1]), "=r"(r[2]), "=r"(r[3]) : "r"(addr));
}
__device__ __forceinline__ void mma16816(float* c, const uint32_t* a, const uint32_t* b) {
    asm volatile("mma.sync.aligned.m16n8k16.row.col.f32.f16.f16.f32 "
                 "{%0,%1,%2,%3}, {%4,%5,%6,%7}, {%8,%9}, {%0,%1,%2,%3};"
                 : "+f"(c[0]), "+f"(c[1]), "+f"(c[2]), "+f"(c[3])
                 : "r"(a[0]), "r"(a[1]), "r"(a[2]), "r"(a[3]), "r"(b[0]), "r"(b[1]));
}
__device__ __forceinline__ uint32_t packh2(float x, float y) {
    __half2 p = __halves2half2(__float2half_rn(x), __float2half_rn(y));
    return *(uint32_t*)&p;
}
__device__ __forceinline__ uint32_t packlo2(float x, float y) {
    __half h0 = __float2half_rn(x), h1 = __float2half_rn(y);
    return packh2(x - __half2float(h0), y - __half2float(h1));
}

// ---------------------------------------------------------------------------
// convH: fp32 row-major -> fp16 hi row-major (8 elems / thread)
// ---------------------------------------------------------------------------
__global__ __launch_bounds__(256)
void convH_kernel(const float* __restrict__ src, __half* __restrict__ hi)
{
    size_t base = ((size_t)blockIdx.x * 256 + threadIdx.x) * 8;
    const float4* s = (const float4*)(src + base);
    float4 a = s[0], b = s[1];
    float x[8] = {a.x, a.y, a.z, a.w, b.x, b.y, b.z, b.w};
    uint4 uh;
    uint32_t* ph = (uint32_t*)&uh;
    #pragma unroll
    for (int j = 0; j < 4; j++) ph[j] = packh2(x[2*j], x[2*j+1]);
    *(uint4*)(hi + base) = uh;
}

// ---------------------------------------------------------------------------
// convT: fp32 [K, N] -> transposed fp16 hi/lo [N, K].
// 32(k) x 64(n) smem tiles; writes 2x uint4 (8 halfs) per thread.
// grid (K/32, N/64), 256 threads.
// ---------------------------------------------------------------------------
__global__ __launch_bounds__(256)
void convT_kernel(const float* __restrict__ w, __half* __restrict__ hi,
                  __half* __restrict__ lo, int K, int N)
{
    __shared__ float t[32][65];
    const int k0 = blockIdx.x * 32, n0 = blockIdx.y * 64;
    const int tx = threadIdx.x & 63, ty = threadIdx.x >> 6;   // ty 0..3
    #pragma unroll
    for (int i = 0; i < 32; i += 4)
        t[ty + i][tx] = w[(size_t)(k0 + ty + i) * N + n0 + tx];
    __syncthreads();

    const int nl = threadIdx.x >> 2;        // 0..63 local n
    const int kg = threadIdx.x & 3;         // k-group of 8
    float x[8];
    #pragma unroll
    for (int j = 0; j < 8; j++) x[j] = t[kg * 8 + j][nl];   // conflict-free
    uint4 uh, ul;
    uint32_t* ph = (uint32_t*)&uh;
    uint32_t* pl = (uint32_t*)&ul;
    #pragma unroll
    for (int j = 0; j < 4; j++) {
        ph[j] = packh2(x[2*j], x[2*j+1]);
        pl[j] = packlo2(x[2*j], x[2*j+1]);
    }
    size_t o = (size_t)(n0 + nl) * K + k0 + kg * 8;
    *(uint4*)(hi + o) = uh;
    *(uint4*)(lo + o) = ul;
}

// ---------------------------------------------------------------------------
// HGEMM: C[M,N] = A @ B, 2-term split: ah*bh + ah*bl, fp32 accum.
// A: [M,K] hi row-major.  B: [N,K] hi/lo row-major (B^T).
// 128x128 CTA tile, BK=32, 3-stage cp.async, 128 threads (2x2 warps,
// 64x64 warp tile), 72 KB smem, 2 CTAs/SM, 1 sync/stage.
// ---------------------------------------------------------------------------
constexpr int G_STAGE = 24576;
constexpr int G_SMEM  = 3 * G_STAGE;      // 72 KB

__global__ __launch_bounds__(128, 2)
void hgemm_kernel(const __half* __restrict__ Ah,
                  const __half* __restrict__ Bh, const __half* __restrict__ Bl,
                  float* __restrict__ C, int N, int K)
{
    extern __shared__ char sm[];
    const int tid  = threadIdx.x;
    const int wid  = tid >> 5, lane = tid & 31;
    const int bm = blockIdx.x, bn = blockIdx.y;
    const int wm = (wid >> 1) * 64;
    const int wn = (wid & 1) * 64;
    const int KT = K / 32;
    const uint32_t sb = smem_u32(sm);

    const __half* aop = Ah + (size_t)bm * 128 * K;
    const __half* bop[2] = {Bh + (size_t)bn * 128 * K, Bl + (size_t)bn * 128 * K};

    auto prefetch = [&](int kt) {
        const uint32_t st = sb + (kt % 3) * G_STAGE;
        #pragma unroll
        for (int op = 0; op < 3; op++) {
            const __half* src = (op == 0) ? aop : bop[op - 1];
            #pragma unroll
            for (int h4 = 0; h4 < 4; h4++) {
                int ch = h4 * 128 + tid;
                int row = ch >> 2, c = ch & 3;
                cp16(st + op * 8192 + row * 64 + ((c ^ (row & 3)) << 4),
                     src + (size_t)row * K + kt * 32 + c * 8);
            }
        }
        cp_commit();
    };

    prefetch(0);
    if (KT > 1) prefetch(1);

    float acc[4][8][4] = {};

    for (int kt = 0; kt < KT; kt++) {
        if (kt + 1 < KT) cp_wait<1>(); else cp_wait<0>();
        __syncthreads();
        if (kt + 2 < KT) prefetch(kt + 2);

        const uint32_t st = sb + (kt % 3) * G_STAGE;
        #pragma unroll
        for (int ks = 0; ks < 2; ks++) {
            uint32_t ahf[4][4], bhf[4][4], blf[4][4];
            #pragma unroll
            for (int mt = 0; mt < 4; mt++) {
                int row = wm + mt * 16 + (lane & 15);
                int c   = ks * 2 + (lane >> 4);
                ldsm4(ahf[mt], st + row * 64 + ((c ^ (row & 3)) << 4));
            }
            #pragma unroll
            for (int p = 0; p < 4; p++) {
                int n = wn + p * 16 + ((lane >> 4) << 3) + (lane & 7);
                int c = ks * 2 + ((lane >> 3) & 1);
                uint32_t addr = st + 8192 + n * 64 + ((c ^ (n & 3)) << 4);
                ldsm4(bhf[p], addr);
                ldsm4(blf[p], addr + 8192);
            }
            #pragma unroll
            for (int mt = 0; mt < 4; mt++)
                #pragma unroll
                for (int nt = 0; nt < 8; nt++) {
                    const uint32_t* bh2 = &bhf[nt >> 1][(nt & 1) * 2];
                    const uint32_t* bl2 = &blf[nt >> 1][(nt & 1) * 2];
                    mma16816(acc[mt][nt], ahf[mt], bh2);
                    mma16816(acc[mt][nt], ahf[mt], bl2);
                }
        }
    }

    #pragma unroll
    for (int mt = 0; mt < 4; mt++)
        #pragma unroll
        for (int nt = 0; nt < 8; nt++) {
            int r0  = bm * 128 + wm + mt * 16 + (lane >> 2);
            int col = bn * 128 + wn + nt * 8 + (lane & 3) * 2;
            *(float2*)(C + (size_t)r0 * N + col) =
                make_float2(acc[mt][nt][0], acc[mt][nt][1]);
            *(float2*)(C + (size_t)(r0 + 8) * N + col) =
                make_float2(acc[mt][nt][2], acc[mt][nt][3]);
        }
}

// ---------------------------------------------------------------------------
// RoPE + cache scatter + fp16 hi/lo emit. Warp per (t,h); 256-thread blocks.
// Thread `lane` handles rope pairs 2*lane, 2*lane+1 (elements 4l..4l+3).
// Same arithmetic/rounding as before — bit-identical output.
// ---------------------------------------------------------------------------
__global__ __launch_bounds__(256)
void rope_cache_kernel(const float* __restrict__ cosT,
                       const float* __restrict__ sinT,
                       float* __restrict__ kc,
                       float* __restrict__ vc)
{
    const int gw = blockIdx.x * 8 + (threadIdx.x >> 5);   // (t,h) index
    const int t = gw >> 5;
    const int h = gw & 31;
    const int lane = threadIdx.x & 31;

    const float2 c2 = *(const float2*)(cosT + t * 64 + 2 * lane);
    const float2 s2 = *(const float2*)(sinT + t * 64 + 2 * lane);

    const size_t base = (size_t)t * 3 * HID_ + h * D_ + 4 * lane;
    const size_t co   = (size_t)t * HID_ + h * D_ + 4 * lane;

    // q: rope -> fp16 hi/lo
    {
        float4 q = *(const float4*)(g_qkv + base);
        float a0 = q.x * c2.x - q.y * s2.x, a1 = q.y * c2.x + q.x * s2.x;
        float a2 = q.z * c2.y - q.w * s2.y, a3 = q.w * c2.y + q.z * s2.y;
        *(uint2*)(g_Qh + co) = make_uint2(packh2(a0, a1), packh2(a2, a3));
        *(uint2*)(g_Ql + co) = make_uint2(packlo2(a0, a1), packlo2(a2, a3));
    }
    // k: rope -> fp32 cache + fp16 hi/lo
    {
        float4 k = *(const float4*)(g_qkv + base + HID_);
        float b0 = k.x * c2.x - k.y * s2.x, b1 = k.y * c2.x + k.x * s2.x;
        float b2 = k.z * c2.y - k.w * s2.y, b3 = k.w * c2.y + k.z * s2.y;
        *(float4*)(kc + co) = make_float4(b0, b1, b2, b3);
        *(uint2*)(g_Kh + co) = make_uint2(packh2(b0, b1), packh2(b2, b3));
        *(uint2*)(g_Kl + co) = make_uint2(packlo2(b0, b1), packlo2(b2, b3));
    }
    // v: copy -> fp32 cache + fp16 hi/lo
    {
        float4 v = *(const float4*)(g_qkv + base + 2 * HID_);
        *(float4*)(vc + co) = v;
        *(uint2*)(g_Vh + co) = make_uint2(packh2(v.x, v.y), packh2(v.z, v.w));
        *(uint2*)(g_Vl + co) = make_uint2(packlo2(v.x, v.y), packlo2(v.z, v.w));
    }
}

// ---------------------------------------------------------------------------
// Flash attention on mma.sync, fp16 hi/lo split (3-term, round-8 version).
// Epilogue writes ctx as fp16 hi only into g_Ah (O-proj is 2-term).
// ---------------------------------------------------------------------------
constexpr int FA_ST = 34816;          // stage size in halfs (4 * 8704)
constexpr int FA_SMEM_BYTES = (34816 + 2 * 34816) * 2;   // 208896

__global__ __launch_bounds__(256, 1)
void fattn_kernel()
{
    extern __shared__ __half fsm[];
    const int tid = threadIdx.x;
    const int wid = tid >> 5, lane = tid & 31;
    const int qt = 7 - blockIdx.x;
    const int h = blockIdx.y, b = blockIdx.z;
    const int t0 = b * S_ + qt * 128;
    const int wrow = wid * 16;
    const uint32_t sb = smem_u32(fsm);

    {
        const __half* qsrc[2] = {g_Qh, g_Ql};
        #pragma unroll
        for (int a = 0; a < 2; a++)
            #pragma unroll
            for (int j = 0; j < 8; j++) {
                int ch = j * 256 + tid;
                int r = ch >> 4, c = ch & 15;
                cp16(sb + (a * 17408 + r * 136 + c * 8) * 2,
                     qsrc[a] + (size_t)(t0 + r) * HID_ + h * D_ + c * 8);
            }
    }

    auto kvload = [&](int kt) {
        const uint32_t dstb = sb + (FA_ST + (kt & 1) * FA_ST) * 2;
        const int tk0 = b * S_ + kt * 64;
        const __half* srcs[4] = {g_Kh, g_Kl, g_Vh, g_Vl};
        #pragma unroll
        for (int a = 0; a < 4; a++)
            #pragma unroll
            for (int j = 0; j < 4; j++) {
                int ch = j * 256 + tid;
                int r = ch >> 4, c = ch & 15;
                cp16(dstb + (a * 8704 + r * 136 + c * 8) * 2,
                     srcs[a] + (size_t)(tk0 + r) * HID_ + h * D_ + c * 8);
            }
        cp_commit();
    };

    const int ktmax = 2 * qt + 1;
    kvload(0);

    float acc[16][4] = {};
    float m_i[2] = {-1e30f, -1e30f};
    float l_i[2] = {0.f, 0.f};

    for (int kt = 0; kt <= ktmax; kt++) {
        if (kt + 1 <= ktmax) { kvload(kt + 1); cp_wait<1>(); }
        else cp_wait<0>();
        __syncthreads();

        const uint32_t stb = sb + (FA_ST + (kt & 1) * FA_ST) * 2;
        const bool active = (kt * 64 <= qt * 128 + wrow + 15);

        if (active) {
            float s[8][4] = {};
            #pragma unroll
            for (int ks = 0; ks < 8; ks++) {
                uint32_t qh[4], ql[4];
                {
                    int row = wrow + (lane & 15);
                    int seg = ks * 16 + 8 * (lane >> 4);
                    uint32_t addr = sb + (row * 136 + seg) * 2;
                    ldsm4(qh, addr);
                    ldsm4(ql, addr + 17408 * 2);
                }
                #pragma unroll
                for (int np = 0; np < 4; np++) {
                    uint32_t kh[4], kl[4];
                    int n = np * 16 + ((lane >> 4) << 3) + (lane & 7);
                    int seg = ks * 16 + 8 * ((lane >> 3) & 1);
                    uint32_t addr = stb + (n * 136 + seg) * 2;
                    ldsm4(kh, addr);
                    ldsm4(kl, addr + 8704 * 2);
                    #pragma unroll
                    for (int half_ = 0; half_ < 2; half_++) {
                        float* st_ = s[np * 2 + half_];
                        const uint32_t* bh2 = &kh[half_ * 2];
                        const uint32_t* bl2 = &kl[half_ * 2];
                        mma16816(st_, qh, bh2);
                        mma16816(st_, qh, bl2);
                        mma16816(st_, ql, bh2);
                    }
                }
            }

            const int rbase = qt * 128 + wrow + (lane >> 2);
            if (kt * 64 + 63 > qt * 128 + wrow) {
                #pragma unroll
                for (int j = 0; j < 8; j++)
                    #pragma unroll
                    for (int cc = 0; cc < 4; cc++) {
                        int colg = kt * 64 + j * 8 + (lane & 3) * 2 + (cc & 1);
                        int rowg = rbase + (cc >> 1) * 8;
                        if (colg > rowg) s[j][cc] = -1e30f;
                    }
            }
            #pragma unroll
            for (int j = 0; j < 8; j++)
                #pragma unroll
                for (int cc = 0; cc < 4; cc++) s[j][cc] *= SCALE_;

            #pragma unroll
            for (int hr = 0; hr < 2; hr++) {
                float rm = -1e30f;
                #pragma unroll
                for (int j = 0; j < 8; j++)
                    rm = fmaxf(rm, fmaxf(s[j][hr * 2], s[j][hr * 2 + 1]));
                rm = fmaxf(rm, __shfl_xor_sync(0xffffffffu, rm, 1));
                rm = fmaxf(rm, __shfl_xor_sync(0xffffffffu, rm, 2));
                float nm  = fmaxf(m_i[hr], rm);
                float fac = __expf(m_i[hr] - nm);
                m_i[hr] = nm;
                float rs = 0.f;
                #pragma unroll
                for (int j = 0; j < 8; j++) {
                    float p0 = __expf(s[j][hr * 2]     - nm);
                    float p1 = __expf(s[j][hr * 2 + 1] - nm);
                    s[j][hr * 2]     = p0;
                    s[j][hr * 2 + 1] = p1;
                    rs += p0 + p1;
                }
                rs += __shfl_xor_sync(0xffffffffu, rs, 1);
                rs += __shfl_xor_sync(0xffffffffu, rs, 2);
                l_i[hr] = l_i[hr] * fac + rs;
                #pragma unroll
                for (int nt = 0; nt < 16; nt++) {
                    acc[nt][hr * 2]     *= fac;
                    acc[nt][hr * 2 + 1] *= fac;
                }
            }

            uint32_t aH[4][4], aL[4][4];
            #pragma unroll
            for (int ks = 0; ks < 4; ks++) {
                #pragma unroll
                for (int half_ = 0; half_ < 2; half_++) {
                    const float* sj = s[ks * 2 + half_];
                    #pragma unroll
                    for (int rr = 0; rr < 2; rr++) {
                        float x0 = sj[rr * 2], x1 = sj[rr * 2 + 1];
                        aH[ks][half_ * 2 + rr] = packh2(x0, x1);
                        aL[ks][half_ * 2 + rr] = packlo2(x0, x1);
                    }
                }
            }

            #pragma unroll
            for (int ks = 0; ks < 4; ks++) {
                #pragma unroll
                for (int ntp = 0; ntp < 8; ntp++) {
                    uint32_t vh[4], vl[4];
                    int kr = ks * 16 + (lane & 7) + 8 * ((lane >> 3) & 1);
                    int nc = ntp * 16 + 8 * (lane >> 4);
                    uint32_t addr = stb + (17408 + kr * 136 + nc) * 2;
                    ldsm4t(vh, addr);
                    ldsm4t(vl, addr + 8704 * 2);
                    #pragma unroll
                    for (int half_ = 0; half_ < 2; half_++) {
                        float* ot = acc[ntp * 2 + half_];
                        const uint32_t* bh2 = &vh[half_ * 2];
                        const uint32_t* bl2 = &vl[half_ * 2];
                        mma16816(ot, aH[ks], bh2);
                        mma16816(ot, aH[ks], bl2);
                        mma16816(ot, aL[ks], bh2);
                    }
                }
            }
        }
        __syncthreads();
    }

    float inv0 = 1.0f / l_i[0], inv1 = 1.0f / l_i[1];
    #pragma unroll
    for (int nt = 0; nt < 16; nt++) {
        float o0 = acc[nt][0] * inv0, o1 = acc[nt][1] * inv0;
        float o2 = acc[nt][2] * inv1, o3 = acc[nt][3] * inv1;
        size_t col = (size_t)h * D_ + nt * 8 + (lane & 3) * 2;
        size_t r0 = (size_t)(t0 + wrow + (lane >> 2)) * HID_ + col;
        size_t r1 = r0 + 8 * HID_;
        *(uint32_t*)(g_Ah + r0) = packh2(o0, o1);
        *(uint32_t*)(g_Ah + r1) = packh2(o2, o3);
    }
}

// ---------------------------------------------------------------------------
// Launch
// ---------------------------------------------------------------------------
extern "C" void kernel_launch(void* const* d_in, const int* in_sizes, int n_in,
                              void* d_out, int out_size)
{
    const float* hidden = (const float*)d_in[0];
    const float* cosT   = (const float*)d_in[1];
    const float* sinT   = (const float*)d_in[2];
    const float* w_qkv  = (const float*)d_in[3];
    const float* w_o    = (const float*)d_in[4];

    float* out = (float*)d_out;
    float* kc  = out + (size_t)T_ * HID_;
    float* vc  = kc + (size_t)T_ * HID_;

    float* qkvp = nullptr;
    __half *ahp = nullptr, *bhp = nullptr, *blp = nullptr;
    cudaGetSymbolAddress((void**)&qkvp, g_qkv);
    cudaGetSymbolAddress((void**)&ahp, g_Ah);
    cudaGetSymbolAddress((void**)&bhp, g_Bh);
    cudaGetSymbolAddress((void**)&blp, g_Bl);

    cudaFuncSetAttribute(hgemm_kernel,
                         cudaFuncAttributeMaxDynamicSharedMemorySize, G_SMEM);
    cudaFuncSetAttribute(fattn_kernel,
                         cudaFuncAttributeMaxDynamicSharedMemorySize, FA_SMEM_BYTES);

    // 1) convert hidden (hi only) + w_qkv (hi/lo, transposed)
    convH_kernel<<<(int)((size_t)T_ * HID_ / 8 / 256), 256>>>(hidden, ahp);
    convT_kernel<<<dim3(HID_ / 32, 3 * HID_ / 64), 256>>>(w_qkv, bhp, blp,
                                                          HID_, 3 * HID_);
    // 2) QKV GEMM (2-term) -> g_qkv fp32
    hgemm_kernel<<<dim3(T_ / 128, 3 * HID_ / 128), 128, G_SMEM>>>(
        ahp, bhp, blp, qkvp, 3 * HID_, HID_);
    // 3) RoPE + caches + fp16 attention operands (vectorized)
    rope_cache_kernel<<<T_ * H_ / 8, 256>>>(cosT, sinT, kc, vc);
    // 4) flash attention (3-term mma.sync) -> ctx fp16 into g_Ah
    fattn_kernel<<<dim3(S_ / 128, H_, B_), 256, FA_SMEM_BYTES>>>();
    // 5) convert w_o, output projection (2-term) -> out
    convT_kernel<<<dim3(HID_ / 32, HID_ / 64), 256>>>(w_o, bhp, blp, HID_, HID_);
    hgemm_kernel<<<dim3(T_ / 128, HID_ / 128), 128, G_SMEM>>>(
        ahp, bhp, blp, out, HID_, HID_);
}

// round 11
// speedup vs baseline: 1.0541x; 1.0180x over previous
#include <cuda_runtime.h>
#include <cuda_fp16.h>
#include <cstdint>
#include <cstddef>

// Problem constants
constexpr int H_   = 32;
constexpr int D_   = 128;
constexpr int HID_ = 4096;   // H*D
constexpr int B_   = 4;
constexpr int S_   = 1024;
constexpr int T_   = 4096;   // B*S
constexpr float SCALE_ = 0.08838834764831845f;  // D^-0.5

// Scratch (allocation-free rule: __device__ globals)
__device__ float g_qkv[(size_t)T_ * 3 * HID_];   // [T, 3*HID]
// GEMM fp16 operands (A: hi only — 2-term split)
__device__ __half g_Ah[(size_t)T_ * HID_];       // A hi (hidden, then ctx)
__device__ __half g_Bh[(size_t)HID_ * 3 * HID_]; // B^T hi, row-major [N][K]
__device__ __half g_Bl[(size_t)HID_ * 3 * HID_]; // B^T lo
// Attention fp16 operands (written by rope kernel)
__device__ __half g_Qh[(size_t)T_ * HID_];
__device__ __half g_Ql[(size_t)T_ * HID_];
__device__ __half g_Kh[(size_t)T_ * HID_];
__device__ __half g_Kl[(size_t)T_ * HID_];
__device__ __half g_Vh[(size_t)T_ * HID_];       // V hi only (PV drops V-lo)

// ---------------------------------------------------------------------------
// helpers
// ---------------------------------------------------------------------------
__device__ __forceinline__ uint32_t smem_u32(const void* p) {
    uint32_t a;
    asm("{ .reg .u64 t; cvta.to.shared.u64 t, %1; cvt.u32.u64 %0, t; }"
        : "=r"(a) : "l"(p));
    return a;
}
__device__ __forceinline__ void cp16(uint32_t dst, const void* src) {
    asm volatile("cp.async.cg.shared.global [%0], [%1], 16;" :: "r"(dst), "l"(src));
}
__device__ __forceinline__ void cp_commit() { asm volatile("cp.async.commit_group;"); }
template<int Ngrp> __device__ __forceinline__ void cp_wait() {
    asm volatile("cp.async.wait_group %0;" :: "n"(Ngrp));
}
__device__ __forceinline__ void ldsm4(uint32_t* r, uint32_t addr) {
    asm volatile("ldmatrix.sync.aligned.m8n8.x4.shared.b16 {%0,%1,%2,%3}, [%4];"
                 : "=r"(r[0]), "=r"(r[1]), "=r"(r[2]), "=r"(r[3]) : "r"(addr));
}
__device__ __forceinline__ void ldsm4t(uint32_t* r, uint32_t addr) {
    asm volatile("ldmatrix.sync.aligned.m8n8.x4.trans.shared.b16 {%0,%1,%2,%3}, [%4];"
                 : "=r"(r[0]), "=r"(r[1]), "=r"(r[2]), "=r"(r[3]) : "r"(addr));
}
__device__ __forceinline__ void mma16816(float* c, const uint32_t* a, const uint32_t* b) {
    asm volatile("mma.sync.aligned.m16n8k16.row.col.f32.f16.f16.f32 "
                 "{%0,%1,%2,%3}, {%4,%5,%6,%7}, {%8,%9}, {%0,%1,%2,%3};"
                 : "+f"(c[0]), "+f"(c[1]), "+f"(c[2]), "+f"(c[3])
                 : "r"(a[0]), "r"(a[1]), "r"(a[2]), "r"(a[3]), "r"(b[0]), "r"(b[1]));
}
__device__ __forceinline__ uint32_t packh2(float x, float y) {
    __half2 p = __halves2half2(__float2half_rn(x), __float2half_rn(y));
    return *(uint32_t*)&p;
}
__device__ __forceinline__ uint32_t packlo2(float x, float y) {
    __half h0 = __float2half_rn(x), h1 = __float2half_rn(y);
    return packh2(x - __half2float(h0), y - __half2float(h1));
}

// ---------------------------------------------------------------------------
// convH: fp32 row-major -> fp16 hi row-major (8 elems / thread)
// ---------------------------------------------------------------------------
__global__ __launch_bounds__(256)
void convH_kernel(const float* __restrict__ src, __half* __restrict__ hi)
{
    size_t base = ((size_t)blockIdx.x * 256 + threadIdx.x) * 8;
    const float4* s = (const float4*)(src + base);
    float4 a = s[0], b = s[1];
    float x[8] = {a.x, a.y, a.z, a.w, b.x, b.y, b.z, b.w};
    uint4 uh;
    uint32_t* ph = (uint32_t*)&uh;
    #pragma unroll
    for (int j = 0; j < 4; j++) ph[j] = packh2(x[2*j], x[2*j+1]);
    *(uint4*)(hi + base) = uh;
}

// ---------------------------------------------------------------------------
// convT: fp32 [K, N] -> transposed fp16 hi/lo [N, K].
// 32(k) x 64(n) smem tiles; writes 2x uint4 (8 halfs) per thread.
// ---------------------------------------------------------------------------
__global__ __launch_bounds__(256)
void convT_kernel(const float* __restrict__ w, __half* __restrict__ hi,
                  __half* __restrict__ lo, int K, int N)
{
    __shared__ float t[32][65];
    const int k0 = blockIdx.x * 32, n0 = blockIdx.y * 64;
    const int tx = threadIdx.x & 63, ty = threadIdx.x >> 6;   // ty 0..3
    #pragma unroll
    for (int i = 0; i < 32; i += 4)
        t[ty + i][tx] = w[(size_t)(k0 + ty + i) * N + n0 + tx];
    __syncthreads();

    const int nl = threadIdx.x >> 2;        // 0..63 local n
    const int kg = threadIdx.x & 3;         // k-group of 8
    float x[8];
    #pragma unroll
    for (int j = 0; j < 8; j++) x[j] = t[kg * 8 + j][nl];   // conflict-free
    uint4 uh, ul;
    uint32_t* ph = (uint32_t*)&uh;
    uint32_t* pl = (uint32_t*)&ul;
    #pragma unroll
    for (int j = 0; j < 4; j++) {
        ph[j] = packh2(x[2*j], x[2*j+1]);
        pl[j] = packlo2(x[2*j], x[2*j+1]);
    }
    size_t o = (size_t)(n0 + nl) * K + k0 + kg * 8;
    *(uint4*)(hi + o) = uh;
    *(uint4*)(lo + o) = ul;
}

// ---------------------------------------------------------------------------
// HGEMM: C[M,N] = A @ B, 2-term split: ah*bh + ah*bl, fp32 accum.
// A: [M,K] hi row-major.  B: [N,K] hi/lo row-major (B^T).
// 128x128 CTA tile, BK=32, 4-stage cp.async, 128 threads (2x2 warps,
// 64x64 warp tile), 96 KB smem, 2 CTAs/SM, 1 sync/stage.
// ---------------------------------------------------------------------------
constexpr int G_STAGE = 24576;
constexpr int G_SMEM  = 4 * G_STAGE;      // 96 KB

__global__ __launch_bounds__(128, 2)
void hgemm_kernel(const __half* __restrict__ Ah,
                  const __half* __restrict__ Bh, const __half* __restrict__ Bl,
                  float* __restrict__ C, int N, int K)
{
    extern __shared__ char sm[];
    const int tid  = threadIdx.x;
    const int wid  = tid >> 5, lane = tid & 31;
    const int bm = blockIdx.x, bn = blockIdx.y;
    const int wm = (wid >> 1) * 64;
    const int wn = (wid & 1) * 64;
    const int KT = K / 32;
    const uint32_t sb = smem_u32(sm);

    const __half* aop = Ah + (size_t)bm * 128 * K;
    const __half* bop[2] = {Bh + (size_t)bn * 128 * K, Bl + (size_t)bn * 128 * K};

    auto prefetch = [&](int kt) {
        const uint32_t st = sb + (kt & 3) * G_STAGE;
        #pragma unroll
        for (int op = 0; op < 3; op++) {
            const __half* src = (op == 0) ? aop : bop[op - 1];
            #pragma unroll
            for (int h4 = 0; h4 < 4; h4++) {
                int ch = h4 * 128 + tid;
                int row = ch >> 2, c = ch & 3;
                cp16(st + op * 8192 + row * 64 + ((c ^ (row & 3)) << 4),
                     src + (size_t)row * K + kt * 32 + c * 8);
            }
        }
        cp_commit();
    };

    prefetch(0);
    if (KT > 1) prefetch(1);
    if (KT > 2) prefetch(2);

    float acc[4][8][4] = {};

    for (int kt = 0; kt < KT; kt++) {
        if (kt + 2 < KT)      cp_wait<2>();
        else if (kt + 1 < KT) cp_wait<1>();
        else                  cp_wait<0>();
        __syncthreads();                   // stage kt visible; iter kt-1 reads done
        if (kt + 3 < KT) prefetch(kt + 3); // overwrites buf (kt+3)&3, safe post-sync

        const uint32_t st = sb + (kt & 3) * G_STAGE;
        #pragma unroll
        for (int ks = 0; ks < 2; ks++) {
            uint32_t ahf[4][4], bhf[4][4], blf[4][4];
            #pragma unroll
            for (int mt = 0; mt < 4; mt++) {
                int row = wm + mt * 16 + (lane & 15);
                int c   = ks * 2 + (lane >> 4);
                ldsm4(ahf[mt], st + row * 64 + ((c ^ (row & 3)) << 4));
            }
            #pragma unroll
            for (int p = 0; p < 4; p++) {
                int n = wn + p * 16 + ((lane >> 4) << 3) + (lane & 7);
                int c = ks * 2 + ((lane >> 3) & 1);
                uint32_t addr = st + 8192 + n * 64 + ((c ^ (n & 3)) << 4);
                ldsm4(bhf[p], addr);
                ldsm4(blf[p], addr + 8192);
            }
            #pragma unroll
            for (int mt = 0; mt < 4; mt++)
                #pragma unroll
                for (int nt = 0; nt < 8; nt++) {
                    const uint32_t* bh2 = &bhf[nt >> 1][(nt & 1) * 2];
                    const uint32_t* bl2 = &blf[nt >> 1][(nt & 1) * 2];
                    mma16816(acc[mt][nt], ahf[mt], bh2);
                    mma16816(acc[mt][nt], ahf[mt], bl2);
                }
        }
    }

    #pragma unroll
    for (int mt = 0; mt < 4; mt++)
        #pragma unroll
        for (int nt = 0; nt < 8; nt++) {
            int r0  = bm * 128 + wm + mt * 16 + (lane >> 2);
            int col = bn * 128 + wn + nt * 8 + (lane & 3) * 2;
            *(float2*)(C + (size_t)r0 * N + col) =
                make_float2(acc[mt][nt][0], acc[mt][nt][1]);
            *(float2*)(C + (size_t)(r0 + 8) * N + col) =
                make_float2(acc[mt][nt][2], acc[mt][nt][3]);
        }
}

// ---------------------------------------------------------------------------
// RoPE + cache scatter + fp16 emit. Warp per (t,h); 256-thread blocks.
// V: hi only (fattn PV drops V-lo).
// ---------------------------------------------------------------------------
__global__ __launch_bounds__(256)
void rope_cache_kernel(const float* __restrict__ cosT,
                       const float* __restrict__ sinT,
                       float* __restrict__ kc,
                       float* __restrict__ vc)
{
    const int gw = blockIdx.x * 8 + (threadIdx.x >> 5);   // (t,h) index
    const int t = gw >> 5;
    const int h = gw & 31;
    const int lane = threadIdx.x & 31;

    const float2 c2 = *(const float2*)(cosT + t * 64 + 2 * lane);
    const float2 s2 = *(const float2*)(sinT + t * 64 + 2 * lane);

    const size_t base = (size_t)t * 3 * HID_ + h * D_ + 4 * lane;
    const size_t co   = (size_t)t * HID_ + h * D_ + 4 * lane;

    // q: rope -> fp16 hi/lo
    {
        float4 q = *(const float4*)(g_qkv + base);
        float a0 = q.x * c2.x - q.y * s2.x, a1 = q.y * c2.x + q.x * s2.x;
        float a2 = q.z * c2.y - q.w * s2.y, a3 = q.w * c2.y + q.z * s2.y;
        *(uint2*)(g_Qh + co) = make_uint2(packh2(a0, a1), packh2(a2, a3));
        *(uint2*)(g_Ql + co) = make_uint2(packlo2(a0, a1), packlo2(a2, a3));
    }
    // k: rope -> fp32 cache + fp16 hi/lo
    {
        float4 k = *(const float4*)(g_qkv + base + HID_);
        float b0 = k.x * c2.x - k.y * s2.x, b1 = k.y * c2.x + k.x * s2.x;
        float b2 = k.z * c2.y - k.w * s2.y, b3 = k.w * c2.y + k.z * s2.y;
        *(float4*)(kc + co) = make_float4(b0, b1, b2, b3);
        *(uint2*)(g_Kh + co) = make_uint2(packh2(b0, b1), packh2(b2, b3));
        *(uint2*)(g_Kl + co) = make_uint2(packlo2(b0, b1), packlo2(b2, b3));
    }
    // v: copy -> fp32 cache + fp16 hi
    {
        float4 v = *(const float4*)(g_qkv + base + 2 * HID_);
        *(float4*)(vc + co) = v;
        *(uint2*)(g_Vh + co) = make_uint2(packh2(v.x, v.y), packh2(v.z, v.w));
    }
}

// ---------------------------------------------------------------------------
// Flash attention on mma.sync. S = 3-term split; P·V = 2-term (P_hi+P_lo)·V_hi.
// Stage layout (halfs): Kh @0, Kl @8704, Vh @17408 (Vl slot unused).
// ---------------------------------------------------------------------------
constexpr int FA_ST = 34816;          // stage stride in halfs (layout unchanged)
constexpr int FA_SMEM_BYTES = (34816 + 2 * 34816) * 2;   // 208896

__global__ __launch_bounds__(256, 1)
void fattn_kernel()
{
    extern __shared__ __half fsm[];
    const int tid = threadIdx.x;
    const int wid = tid >> 5, lane = tid & 31;
    const int qt = 7 - blockIdx.x;
    const int h = blockIdx.y, b = blockIdx.z;
    const int t0 = b * S_ + qt * 128;
    const int wrow = wid * 16;
    const uint32_t sb = smem_u32(fsm);

    {
        const __half* qsrc[2] = {g_Qh, g_Ql};
        #pragma unroll
        for (int a = 0; a < 2; a++)
            #pragma unroll
            for (int j = 0; j < 8; j++) {
                int ch = j * 256 + tid;
                int r = ch >> 4, c = ch & 15;
                cp16(sb + (a * 17408 + r * 136 + c * 8) * 2,
                     qsrc[a] + (size_t)(t0 + r) * HID_ + h * D_ + c * 8);
            }
    }

    auto kvload = [&](int kt) {
        const uint32_t dstb = sb + (FA_ST + (kt & 1) * FA_ST) * 2;
        const int tk0 = b * S_ + kt * 64;
        const __half* srcs[3] = {g_Kh, g_Kl, g_Vh};
        #pragma unroll
        for (int a = 0; a < 3; a++)
            #pragma unroll
            for (int j = 0; j < 4; j++) {
                int ch = j * 256 + tid;
                int r = ch >> 4, c = ch & 15;
                cp16(dstb + (a * 8704 + r * 136 + c * 8) * 2,
                     srcs[a] + (size_t)(tk0 + r) * HID_ + h * D_ + c * 8);
            }
        cp_commit();
    };

    const int ktmax = 2 * qt + 1;
    kvload(0);

    float acc[16][4] = {};
    float m_i[2] = {-1e30f, -1e30f};
    float l_i[2] = {0.f, 0.f};

    for (int kt = 0; kt <= ktmax; kt++) {
        if (kt + 1 <= ktmax) { kvload(kt + 1); cp_wait<1>(); }
        else cp_wait<0>();
        __syncthreads();

        const uint32_t stb = sb + (FA_ST + (kt & 1) * FA_ST) * 2;
        const bool active = (kt * 64 <= qt * 128 + wrow + 15);

        if (active) {
            float s[8][4] = {};
            #pragma unroll
            for (int ks = 0; ks < 8; ks++) {
                uint32_t qh[4], ql[4];
                {
                    int row = wrow + (lane & 15);
                    int seg = ks * 16 + 8 * (lane >> 4);
                    uint32_t addr = sb + (row * 136 + seg) * 2;
                    ldsm4(qh, addr);
                    ldsm4(ql, addr + 17408 * 2);
                }
                #pragma unroll
                for (int np = 0; np < 4; np++) {
                    uint32_t kh[4], kl[4];
                    int n = np * 16 + ((lane >> 4) << 3) + (lane & 7);
                    int seg = ks * 16 + 8 * ((lane >> 3) & 1);
                    uint32_t addr = stb + (n * 136 + seg) * 2;
                    ldsm4(kh, addr);
                    ldsm4(kl, addr + 8704 * 2);
                    #pragma unroll
                    for (int half_ = 0; half_ < 2; half_++) {
                        float* st_ = s[np * 2 + half_];
                        const uint32_t* bh2 = &kh[half_ * 2];
                        const uint32_t* bl2 = &kl[half_ * 2];
                        mma16816(st_, qh, bh2);
                        mma16816(st_, qh, bl2);
                        mma16816(st_, ql, bh2);
                    }
                }
            }

            const int rbase = qt * 128 + wrow + (lane >> 2);
            if (kt * 64 + 63 > qt * 128 + wrow) {
                #pragma unroll
                for (int j = 0; j < 8; j++)
                    #pragma unroll
                    for (int cc = 0; cc < 4; cc++) {
                        int colg = kt * 64 + j * 8 + (lane & 3) * 2 + (cc & 1);
                        int rowg = rbase + (cc >> 1) * 8;
                        if (colg > rowg) s[j][cc] = -1e30f;
                    }
            }
            #pragma unroll
            for (int j = 0; j < 8; j++)
                #pragma unroll
                for (int cc = 0; cc < 4; cc++) s[j][cc] *= SCALE_;

            #pragma unroll
            for (int hr = 0; hr < 2; hr++) {
                float rm = -1e30f;
                #pragma unroll
                for (int j = 0; j < 8; j++)
                    rm = fmaxf(rm, fmaxf(s[j][hr * 2], s[j][hr * 2 + 1]));
                rm = fmaxf(rm, __shfl_xor_sync(0xffffffffu, rm, 1));
                rm = fmaxf(rm, __shfl_xor_sync(0xffffffffu, rm, 2));
                float nm  = fmaxf(m_i[hr], rm);
                float fac = __expf(m_i[hr] - nm);
                m_i[hr] = nm;
                float rs = 0.f;
                #pragma unroll
                for (int j = 0; j < 8; j++) {
                    float p0 = __expf(s[j][hr * 2]     - nm);
                    float p1 = __expf(s[j][hr * 2 + 1] - nm);
                    s[j][hr * 2]     = p0;
                    s[j][hr * 2 + 1] = p1;
                    rs += p0 + p1;
                }
                rs += __shfl_xor_sync(0xffffffffu, rs, 1);
                rs += __shfl_xor_sync(0xffffffffu, rs, 2);
                l_i[hr] = l_i[hr] * fac + rs;
                #pragma unroll
                for (int nt = 0; nt < 16; nt++) {
                    acc[nt][hr * 2]     *= fac;
                    acc[nt][hr * 2 + 1] *= fac;
                }
            }

            uint32_t aH[4][4], aL[4][4];
            #pragma unroll
            for (int ks = 0; ks < 4; ks++) {
                #pragma unroll
                for (int half_ = 0; half_ < 2; half_++) {
                    const float* sj = s[ks * 2 + half_];
                    #pragma unroll
                    for (int rr = 0; rr < 2; rr++) {
                        float x0 = sj[rr * 2], x1 = sj[rr * 2 + 1];
                        aH[ks][half_ * 2 + rr] = packh2(x0, x1);
                        aL[ks][half_ * 2 + rr] = packlo2(x0, x1);
                    }
                }
            }

            // O += (P_hi + P_lo) · V_hi   (2-term)
            #pragma unroll
            for (int ks = 0; ks < 4; ks++) {
                #pragma unroll
                for (int ntp = 0; ntp < 8; ntp++) {
                    uint32_t vh[4];
                    int kr = ks * 16 + (lane & 7) + 8 * ((lane >> 3) & 1);
                    int nc = ntp * 16 + 8 * (lane >> 4);
                    ldsm4t(vh, stb + (17408 + kr * 136 + nc) * 2);
                    #pragma unroll
                    for (int half_ = 0; half_ < 2; half_++) {
                        float* ot = acc[ntp * 2 + half_];
                        const uint32_t* vh2 = &vh[half_ * 2];
                        mma16816(ot, aH[ks], vh2);
                        mma16816(ot, aL[ks], vh2);
                    }
                }
            }
        }
        __syncthreads();
    }

    float inv0 = 1.0f / l_i[0], inv1 = 1.0f / l_i[1];
    #pragma unroll
    for (int nt = 0; nt < 16; nt++) {
        float o0 = acc[nt][0] * inv0, o1 = acc[nt][1] * inv0;
        float o2 = acc[nt][2] * inv1, o3 = acc[nt][3] * inv1;
        size_t col = (size_t)h * D_ + nt * 8 + (lane & 3) * 2;
        size_t r0 = (size_t)(t0 + wrow + (lane >> 2)) * HID_ + col;
        size_t r1 = r0 + 8 * HID_;
        *(uint32_t*)(g_Ah + r0) = packh2(o0, o1);
        *(uint32_t*)(g_Ah + r1) = packh2(o2, o3);
    }
}

// ---------------------------------------------------------------------------
// Launch
// ---------------------------------------------------------------------------
extern "C" void kernel_launch(void* const* d_in, const int* in_sizes, int n_in,
                              void* d_out, int out_size)
{
    const float* hidden = (const float*)d_in[0];
    const float* cosT   = (const float*)d_in[1];
    const float* sinT   = (const float*)d_in[2];
    const float* w_qkv  = (const float*)d_in[3];
    const float* w_o    = (const float*)d_in[4];

    float* out = (float*)d_out;
    float* kc  = out + (size_t)T_ * HID_;
    float* vc  = kc + (size_t)T_ * HID_;

    float* qkvp = nullptr;
    __half *ahp = nullptr, *bhp = nullptr, *blp = nullptr;
    cudaGetSymbolAddress((void**)&qkvp, g_qkv);
    cudaGetSymbolAddress((void**)&ahp, g_Ah);
    cudaGetSymbolAddress((void**)&bhp, g_Bh);
    cudaGetSymbolAddress((void**)&blp, g_Bl);

    cudaFuncSetAttribute(hgemm_kernel,
                         cudaFuncAttributeMaxDynamicSharedMemorySize, G_SMEM);
    cudaFuncSetAttribute(fattn_kernel,
                         cudaFuncAttributeMaxDynamicSharedMemorySize, FA_SMEM_BYTES);

    // 1) convert hidden (hi only) + w_qkv (hi/lo, transposed)
    convH_kernel<<<(int)((size_t)T_ * HID_ / 8 / 256), 256>>>(hidden, ahp);
    convT_kernel<<<dim3(HID_ / 32, 3 * HID_ / 64), 256>>>(w_qkv, bhp, blp,
                                                          HID_, 3 * HID_);
    // 2) QKV GEMM (2-term) -> g_qkv fp32
    hgemm_kernel<<<dim3(T_ / 128, 3 * HID_ / 128), 128, G_SMEM>>>(
        ahp, bhp, blp, qkvp, 3 * HID_, HID_);
    // 3) RoPE + caches + fp16 attention operands
    rope_cache_kernel<<<T_ * H_ / 8, 256>>>(cosT, sinT, kc, vc);
    // 4) flash attention -> ctx fp16 into g_Ah
    fattn_kernel<<<dim3(S_ / 128, H_, B_), 256, FA_SMEM_BYTES>>>();
    // 5) convert w_o, output projection (2-term) -> out
    convT_kernel<<<dim3(HID_ / 32, HID_ / 64), 256>>>(w_o, bhp, blp, HID_, HID_);
    hgemm_kernel<<<dim3(T_ / 128, HID_ / 128), 128, G_SMEM>>>(
        ahp, bhp, blp, out, HID_, HID_);
}

// round 12
// speedup vs baseline: 1.0646x; 1.0099x over previous
#include <cuda_runtime.h>
#include <cuda_fp16.h>
#include <cstdint>
#include <cstddef>

// Problem constants
constexpr int H_   = 32;
constexpr int D_   = 128;
constexpr int HID_ = 4096;   // H*D
constexpr int B_   = 4;
constexpr int S_   = 1024;
constexpr int T_   = 4096;   // B*S
constexpr float SCALE_ = 0.08838834764831845f;  // D^-0.5

// Scratch (allocation-free rule: __device__ globals)
__device__ float g_qkv[(size_t)T_ * 3 * HID_];   // [T, 3*HID]
// GEMM fp16 operands (A: hi only — 2-term split)
__device__ __half g_Ah[(size_t)T_ * HID_];       // A hi (hidden, then ctx)
__device__ __half g_Bh[(size_t)HID_ * 3 * HID_]; // w_qkv^T hi [N][K]
__device__ __half g_Bl[(size_t)HID_ * 3 * HID_]; // w_qkv^T lo
__device__ __half g_Wh[(size_t)HID_ * HID_];     // w_o^T hi
__device__ __half g_Wl[(size_t)HID_ * HID_];     // w_o^T lo
// Attention fp16 operands (written by rope kernel)
__device__ __half g_Qh[(size_t)T_ * HID_];
__device__ __half g_Ql[(size_t)T_ * HID_];
__device__ __half g_Kh[(size_t)T_ * HID_];
__device__ __half g_Kl[(size_t)T_ * HID_];
__device__ __half g_Vh[(size_t)T_ * HID_];       // V hi only

// ---------------------------------------------------------------------------
// helpers
// ---------------------------------------------------------------------------
__device__ __forceinline__ uint32_t smem_u32(const void* p) {
    uint32_t a;
    asm("{ .reg .u64 t; cvta.to.shared.u64 t, %1; cvt.u32.u64 %0, t; }"
        : "=r"(a) : "l"(p));
    return a;
}
__device__ __forceinline__ void cp16(uint32_t dst, const void* src) {
    asm volatile("cp.async.cg.shared.global [%0], [%1], 16;" :: "r"(dst), "l"(src));
}
__device__ __forceinline__ void cp_commit() { asm volatile("cp.async.commit_group;"); }
template<int Ngrp> __device__ __forceinline__ void cp_wait() {
    asm volatile("cp.async.wait_group %0;" :: "n"(Ngrp));
}
__device__ __forceinline__ void ldsm4(uint32_t* r, uint32_t addr) {
    asm volatile("ldmatrix.sync.aligned.m8n8.x4.shared.b16 {%0,%1,%2,%3}, [%4];"
                 : "=r"(r[0]), "=r"(r[1]), "=r"(r[2]), "=r"(r[3]) : "r"(addr));
}
__device__ __forceinline__ void ldsm4t(uint32_t* r, uint32_t addr) {
    asm volatile("ldmatrix.sync.aligned.m8n8.x4.trans.shared.b16 {%0,%1,%2,%3}, [%4];"
                 : "=r"(r[0]), "=r"(r[1]), "=r"(r[2]), "=r"(r[3]) : "r"(addr));
}
__device__ __forceinline__ void mma16816(float* c, const uint32_t* a, const uint32_t* b) {
    asm volatile("mma.sync.aligned.m16n8k16.row.col.f32.f16.f16.f32 "
                 "{%0,%1,%2,%3}, {%4,%5,%6,%7}, {%8,%9}, {%0,%1,%2,%3};"
                 : "+f"(c[0]), "+f"(c[1]), "+f"(c[2]), "+f"(c[3])
                 : "r"(a[0]), "r"(a[1]), "r"(a[2]), "r"(a[3]), "r"(b[0]), "r"(b[1]));
}
__device__ __forceinline__ uint32_t packh2(float x, float y) {
    __half2 p = __halves2half2(__float2half_rn(x), __float2half_rn(y));
    return *(uint32_t*)&p;
}
__device__ __forceinline__ uint32_t packlo2(float x, float y) {
    __half h0 = __float2half_rn(x), h1 = __float2half_rn(y);
    return packh2(x - __half2float(h0), y - __half2float(h1));
}

// ---------------------------------------------------------------------------
// conv_all: one grid for all conversions.
//   blocks [0, NB_WQKV):            w_qkv -> g_Bh/g_Bl (transposed hi/lo)
//   blocks [NB_WQKV, +NB_WO):       w_o   -> g_Wh/g_Wl (transposed hi/lo)
//   blocks [NB_WQKV+NB_WO, +NB_H):  hidden -> g_Ah (hi)
// ---------------------------------------------------------------------------
constexpr int NB_WQKV = (HID_ / 32) * (3 * HID_ / 64);   // 24576
constexpr int NB_WO   = (HID_ / 32) * (HID_ / 64);       // 8192
constexpr int NB_H    = (int)((size_t)T_ * HID_ / 8 / 256); // 8192

__device__ __forceinline__ void convT_body(const float* __restrict__ w,
                                           __half* __restrict__ hi,
                                           __half* __restrict__ lo,
                                           int K, int N, int bk, int bn,
                                           float (*t)[65])
{
    const int k0 = bk * 32, n0 = bn * 64;
    const int tx = threadIdx.x & 63, ty = threadIdx.x >> 6;   // ty 0..3
    #pragma unroll
    for (int i = 0; i < 32; i += 4)
        t[ty + i][tx] = w[(size_t)(k0 + ty + i) * N + n0 + tx];
    __syncthreads();

    const int nl = threadIdx.x >> 2;
    const int kg = threadIdx.x & 3;
    float x[8];
    #pragma unroll
    for (int j = 0; j < 8; j++) x[j] = t[kg * 8 + j][nl];   // conflict-free
    uint4 uh, ul;
    uint32_t* ph = (uint32_t*)&uh;
    uint32_t* pl = (uint32_t*)&ul;
    #pragma unroll
    for (int j = 0; j < 4; j++) {
        ph[j] = packh2(x[2*j], x[2*j+1]);
        pl[j] = packlo2(x[2*j], x[2*j+1]);
    }
    size_t o = (size_t)(n0 + nl) * K + k0 + kg * 8;
    *(uint4*)(hi + o) = uh;
    *(uint4*)(lo + o) = ul;
}

__global__ __launch_bounds__(256)
void conv_all_kernel(const float* __restrict__ hidden,
                     const float* __restrict__ w_qkv,
                     const float* __restrict__ w_o)
{
    __shared__ float t[32][65];
    const int bid = blockIdx.x;
    if (bid < NB_WQKV) {
        convT_body(w_qkv, g_Bh, g_Bl, HID_, 3 * HID_, bid & 127, bid >> 7, t);
    } else if (bid < NB_WQKV + NB_WO) {
        const int b2 = bid - NB_WQKV;
        convT_body(w_o, g_Wh, g_Wl, HID_, HID_, b2 & 127, b2 >> 7, t);
    } else {
        const int b2 = bid - NB_WQKV - NB_WO;
        size_t base = ((size_t)b2 * 256 + threadIdx.x) * 8;
        const float4* s = (const float4*)(hidden + base);
        float4 a = s[0], b = s[1];
        float x[8] = {a.x, a.y, a.z, a.w, b.x, b.y, b.z, b.w};
        uint4 uh;
        uint32_t* ph = (uint32_t*)&uh;
        #pragma unroll
        for (int j = 0; j < 4; j++) ph[j] = packh2(x[2*j], x[2*j+1]);
        *(uint4*)(g_Ah + base) = uh;
    }
}

// ---------------------------------------------------------------------------
// HGEMM: C[M,N] = A @ B, 2-term split: ah*bh + ah*bl, fp32 accum.
// 128x128 CTA tile, BK=32, 4-stage cp.async, 128 threads (2x2 warps,
// 64x64 warp tile), 96 KB smem, 2 CTAs/SM, 1 sync/stage.
// ---------------------------------------------------------------------------
constexpr int G_STAGE = 24576;
constexpr int G_SMEM  = 4 * G_STAGE;      // 96 KB

__global__ __launch_bounds__(128, 2)
void hgemm_kernel(const __half* __restrict__ Ah,
                  const __half* __restrict__ Bh, const __half* __restrict__ Bl,
                  float* __restrict__ C, int N, int K)
{
    extern __shared__ char sm[];
    const int tid  = threadIdx.x;
    const int wid  = tid >> 5, lane = tid & 31;
    const int bm = blockIdx.x, bn = blockIdx.y;
    const int wm = (wid >> 1) * 64;
    const int wn = (wid & 1) * 64;
    const int KT = K / 32;
    const uint32_t sb = smem_u32(sm);

    const __half* aop = Ah + (size_t)bm * 128 * K;
    const __half* bop[2] = {Bh + (size_t)bn * 128 * K, Bl + (size_t)bn * 128 * K};

    auto prefetch = [&](int kt) {
        const uint32_t st = sb + (kt & 3) * G_STAGE;
        #pragma unroll
        for (int op = 0; op < 3; op++) {
            const __half* src = (op == 0) ? aop : bop[op - 1];
            #pragma unroll
            for (int h4 = 0; h4 < 4; h4++) {
                int ch = h4 * 128 + tid;
                int row = ch >> 2, c = ch & 3;
                cp16(st + op * 8192 + row * 64 + ((c ^ (row & 3)) << 4),
                     src + (size_t)row * K + kt * 32 + c * 8);
            }
        }
        cp_commit();
    };

    prefetch(0);
    if (KT > 1) prefetch(1);
    if (KT > 2) prefetch(2);

    float acc[4][8][4] = {};

    for (int kt = 0; kt < KT; kt++) {
        if (kt + 2 < KT)      cp_wait<2>();
        else if (kt + 1 < KT) cp_wait<1>();
        else                  cp_wait<0>();
        __syncthreads();
        if (kt + 3 < KT) prefetch(kt + 3);

        const uint32_t st = sb + (kt & 3) * G_STAGE;
        #pragma unroll
        for (int ks = 0; ks < 2; ks++) {
            uint32_t ahf[4][4], bhf[4][4], blf[4][4];
            #pragma unroll
            for (int mt = 0; mt < 4; mt++) {
                int row = wm + mt * 16 + (lane & 15);
                int c   = ks * 2 + (lane >> 4);
                ldsm4(ahf[mt], st + row * 64 + ((c ^ (row & 3)) << 4));
            }
            #pragma unroll
            for (int p = 0; p < 4; p++) {
                int n = wn + p * 16 + ((lane >> 4) << 3) + (lane & 7);
                int c = ks * 2 + ((lane >> 3) & 1);
                uint32_t addr = st + 8192 + n * 64 + ((c ^ (n & 3)) << 4);
                ldsm4(bhf[p], addr);
                ldsm4(blf[p], addr + 8192);
            }
            #pragma unroll
            for (int mt = 0; mt < 4; mt++)
                #pragma unroll
                for (int nt = 0; nt < 8; nt++) {
                    const uint32_t* bh2 = &bhf[nt >> 1][(nt & 1) * 2];
                    const uint32_t* bl2 = &blf[nt >> 1][(nt & 1) * 2];
                    mma16816(acc[mt][nt], ahf[mt], bh2);
                    mma16816(acc[mt][nt], ahf[mt], bl2);
                }
        }
    }

    #pragma unroll
    for (int mt = 0; mt < 4; mt++)
        #pragma unroll
        for (int nt = 0; nt < 8; nt++) {
            int r0  = bm * 128 + wm + mt * 16 + (lane >> 2);
            int col = bn * 128 + wn + nt * 8 + (lane & 3) * 2;
            *(float2*)(C + (size_t)r0 * N + col) =
                make_float2(acc[mt][nt][0], acc[mt][nt][1]);
            *(float2*)(C + (size_t)(r0 + 8) * N + col) =
                make_float2(acc[mt][nt][2], acc[mt][nt][3]);
        }
}

// ---------------------------------------------------------------------------
// RoPE + cache scatter + fp16 emit. Warp per (t,h); 256-thread blocks.
// ---------------------------------------------------------------------------
__global__ __launch_bounds__(256)
void rope_cache_kernel(const float* __restrict__ cosT,
                       const float* __restrict__ sinT,
                       float* __restrict__ kc,
                       float* __restrict__ vc)
{
    const int gw = blockIdx.x * 8 + (threadIdx.x >> 5);   // (t,h) index
    const int t = gw >> 5;
    const int h = gw & 31;
    const int lane = threadIdx.x & 31;

    const float2 c2 = *(const float2*)(cosT + t * 64 + 2 * lane);
    const float2 s2 = *(const float2*)(sinT + t * 64 + 2 * lane);

    const size_t base = (size_t)t * 3 * HID_ + h * D_ + 4 * lane;
    const size_t co   = (size_t)t * HID_ + h * D_ + 4 * lane;

    {
        float4 q = *(const float4*)(g_qkv + base);
        float a0 = q.x * c2.x - q.y * s2.x, a1 = q.y * c2.x + q.x * s2.x;
        float a2 = q.z * c2.y - q.w * s2.y, a3 = q.w * c2.y + q.z * s2.y;
        *(uint2*)(g_Qh + co) = make_uint2(packh2(a0, a1), packh2(a2, a3));
        *(uint2*)(g_Ql + co) = make_uint2(packlo2(a0, a1), packlo2(a2, a3));
    }
    {
        float4 k = *(const float4*)(g_qkv + base + HID_);
        float b0 = k.x * c2.x - k.y * s2.x, b1 = k.y * c2.x + k.x * s2.x;
        float b2 = k.z * c2.y - k.w * s2.y, b3 = k.w * c2.y + k.z * s2.y;
        *(float4*)(kc + co) = make_float4(b0, b1, b2, b3);
        *(uint2*)(g_Kh + co) = make_uint2(packh2(b0, b1), packh2(b2, b3));
        *(uint2*)(g_Kl + co) = make_uint2(packlo2(b0, b1), packlo2(b2, b3));
    }
    {
        float4 v = *(const float4*)(g_qkv + base + 2 * HID_);
        *(float4*)(vc + co) = v;
        *(uint2*)(g_Vh + co) = make_uint2(packh2(v.x, v.y), packh2(v.z, v.w));
    }
}

// ---------------------------------------------------------------------------
// Flash attention. S = 3-term split; P·V = 2-term. 1D grid, heavy-first.
// ---------------------------------------------------------------------------
constexpr int FA_ST = 34816;          // stage stride in halfs
constexpr int FA_SMEM_BYTES = (34816 + 2 * 34816) * 2;   // 208896

__global__ __launch_bounds__(256, 1)
void fattn_kernel()
{
    extern __shared__ __half fsm[];
    const int tid = threadIdx.x;
    const int wid = tid >> 5, lane = tid & 31;
    const int bid = blockIdx.x;
    const int qt = 7 - (bid >> 7);            // all heavy tiles first, globally
    const int h = bid & 31;
    const int b = (bid >> 5) & 3;
    const int t0 = b * S_ + qt * 128;
    const int wrow = wid * 16;
    const uint32_t sb = smem_u32(fsm);

    {
        const __half* qsrc[2] = {g_Qh, g_Ql};
        #pragma unroll
        for (int a = 0; a < 2; a++)
            #pragma unroll
            for (int j = 0; j < 8; j++) {
                int ch = j * 256 + tid;
                int r = ch >> 4, c = ch & 15;
                cp16(sb + (a * 17408 + r * 136 + c * 8) * 2,
                     qsrc[a] + (size_t)(t0 + r) * HID_ + h * D_ + c * 8);
            }
    }

    auto kvload = [&](int kt) {
        const uint32_t dstb = sb + (FA_ST + (kt & 1) * FA_ST) * 2;
        const int tk0 = b * S_ + kt * 64;
        const __half* srcs[3] = {g_Kh, g_Kl, g_Vh};
        #pragma unroll
        for (int a = 0; a < 3; a++)
            #pragma unroll
            for (int j = 0; j < 4; j++) {
                int ch = j * 256 + tid;
                int r = ch >> 4, c = ch & 15;
                cp16(dstb + (a * 8704 + r * 136 + c * 8) * 2,
                     srcs[a] + (size_t)(tk0 + r) * HID_ + h * D_ + c * 8);
            }
        cp_commit();
    };

    const int ktmax = 2 * qt + 1;
    kvload(0);

    float acc[16][4] = {};
    float m_i[2] = {-1e30f, -1e30f};
    float l_i[2] = {0.f, 0.f};

    for (int kt = 0; kt <= ktmax; kt++) {
        if (kt + 1 <= ktmax) { kvload(kt + 1); cp_wait<1>(); }
        else cp_wait<0>();
        __syncthreads();

        const uint32_t stb = sb + (FA_ST + (kt & 1) * FA_ST) * 2;
        const bool active = (kt * 64 <= qt * 128 + wrow + 15);

        if (active) {
            float s[8][4] = {};
            #pragma unroll
            for (int ks = 0; ks < 8; ks++) {
                uint32_t qh[4], ql[4];
                {
                    int row = wrow + (lane & 15);
                    int seg = ks * 16 + 8 * (lane >> 4);
                    uint32_t addr = sb + (row * 136 + seg) * 2;
                    ldsm4(qh, addr);
                    ldsm4(ql, addr + 17408 * 2);
                }
                #pragma unroll
                for (int np = 0; np < 4; np++) {
                    uint32_t kh[4], kl[4];
                    int n = np * 16 + ((lane >> 4) << 3) + (lane & 7);
                    int seg = ks * 16 + 8 * ((lane >> 3) & 1);
                    uint32_t addr = stb + (n * 136 + seg) * 2;
                    ldsm4(kh, addr);
                    ldsm4(kl, addr + 8704 * 2);
                    #pragma unroll
                    for (int half_ = 0; half_ < 2; half_++) {
                        float* st_ = s[np * 2 + half_];
                        const uint32_t* bh2 = &kh[half_ * 2];
                        const uint32_t* bl2 = &kl[half_ * 2];
                        mma16816(st_, qh, bh2);
                        mma16816(st_, qh, bl2);
                        mma16816(st_, ql, bh2);
                    }
                }
            }

            const int rbase = qt * 128 + wrow + (lane >> 2);
            if (kt * 64 + 63 > qt * 128 + wrow) {
                #pragma unroll
                for (int j = 0; j < 8; j++)
                    #pragma unroll
                    for (int cc = 0; cc < 4; cc++) {
                        int colg = kt * 64 + j * 8 + (lane & 3) * 2 + (cc & 1);
                        int rowg = rbase + (cc >> 1) * 8;
                        if (colg > rowg) s[j][cc] = -1e30f;
                    }
            }
            #pragma unroll
            for (int j = 0; j < 8; j++)
                #pragma unroll
                for (int cc = 0; cc < 4; cc++) s[j][cc] *= SCALE_;

            #pragma unroll
            for (int hr = 0; hr < 2; hr++) {
                float rm = -1e30f;
                #pragma unroll
                for (int j = 0; j < 8; j++)
                    rm = fmaxf(rm, fmaxf(s[j][hr * 2], s[j][hr * 2 + 1]));
                rm = fmaxf(rm, __shfl_xor_sync(0xffffffffu, rm, 1));
                rm = fmaxf(rm, __shfl_xor_sync(0xffffffffu, rm, 2));
                float nm  = fmaxf(m_i[hr], rm);
                float fac = __expf(m_i[hr] - nm);
                m_i[hr] = nm;
                float rs = 0.f;
                #pragma unroll
                for (int j = 0; j < 8; j++) {
                    float p0 = __expf(s[j][hr * 2]     - nm);
                    float p1 = __expf(s[j][hr * 2 + 1] - nm);
                    s[j][hr * 2]     = p0;
                    s[j][hr * 2 + 1] = p1;
                    rs += p0 + p1;
                }
                rs += __shfl_xor_sync(0xffffffffu, rs, 1);
                rs += __shfl_xor_sync(0xffffffffu, rs, 2);
                l_i[hr] = l_i[hr] * fac + rs;
                #pragma unroll
                for (int nt = 0; nt < 16; nt++) {
                    acc[nt][hr * 2]     *= fac;
                    acc[nt][hr * 2 + 1] *= fac;
                }
            }

            uint32_t aH[4][4], aL[4][4];
            #pragma unroll
            for (int ks = 0; ks < 4; ks++) {
                #pragma unroll
                for (int half_ = 0; half_ < 2; half_++) {
                    const float* sj = s[ks * 2 + half_];
                    #pragma unroll
                    for (int rr = 0; rr < 2; rr++) {
                        float x0 = sj[rr * 2], x1 = sj[rr * 2 + 1];
                        aH[ks][half_ * 2 + rr] = packh2(x0, x1);
                        aL[ks][half_ * 2 + rr] = packlo2(x0, x1);
                    }
                }
            }

            // O += (P_hi + P_lo) · V_hi
            #pragma unroll
            for (int ks = 0; ks < 4; ks++) {
                #pragma unroll
                for (int ntp = 0; ntp < 8; ntp++) {
                    uint32_t vh[4];
                    int kr = ks * 16 + (lane & 7) + 8 * ((lane >> 3) & 1);
                    int nc = ntp * 16 + 8 * (lane >> 4);
                    ldsm4t(vh, stb + (17408 + kr * 136 + nc) * 2);
                    #pragma unroll
                    for (int half_ = 0; half_ < 2; half_++) {
                        float* ot = acc[ntp * 2 + half_];
                        const uint32_t* vh2 = &vh[half_ * 2];
                        mma16816(ot, aH[ks], vh2);
                        mma16816(ot, aL[ks], vh2);
                    }
                }
            }
        }
        __syncthreads();
    }

    float inv0 = 1.0f / l_i[0], inv1 = 1.0f / l_i[1];
    #pragma unroll
    for (int nt = 0; nt < 16; nt++) {
        float o0 = acc[nt][0] * inv0, o1 = acc[nt][1] * inv0;
        float o2 = acc[nt][2] * inv1, o3 = acc[nt][3] * inv1;
        size_t col = (size_t)h * D_ + nt * 8 + (lane & 3) * 2;
        size_t r0 = (size_t)(t0 + wrow + (lane >> 2)) * HID_ + col;
        size_t r1 = r0 + 8 * HID_;
        *(uint32_t*)(g_Ah + r0) = packh2(o0, o1);
        *(uint32_t*)(g_Ah + r1) = packh2(o2, o3);
    }
}

// ---------------------------------------------------------------------------
// Launch
// ---------------------------------------------------------------------------
extern "C" void kernel_launch(void* const* d_in, const int* in_sizes, int n_in,
                              void* d_out, int out_size)
{
    const float* hidden = (const float*)d_in[0];
    const float* cosT   = (const float*)d_in[1];
    const float* sinT   = (const float*)d_in[2];
    const float* w_qkv  = (const float*)d_in[3];
    const float* w_o    = (const float*)d_in[4];

    float* out = (float*)d_out;
    float* kc  = out + (size_t)T_ * HID_;
    float* vc  = kc + (size_t)T_ * HID_;

    float* qkvp = nullptr;
    __half *ahp = nullptr, *bhp = nullptr, *blp = nullptr, *whp = nullptr, *wlp = nullptr;
    cudaGetSymbolAddress((void**)&qkvp, g_qkv);
    cudaGetSymbolAddress((void**)&ahp, g_Ah);
    cudaGetSymbolAddress((void**)&bhp, g_Bh);
    cudaGetSymbolAddress((void**)&blp, g_Bl);
    cudaGetSymbolAddress((void**)&whp, g_Wh);
    cudaGetSymbolAddress((void**)&wlp, g_Wl);

    cudaFuncSetAttribute(hgemm_kernel,
                         cudaFuncAttributeMaxDynamicSharedMemorySize, G_SMEM);
    cudaFuncSetAttribute(fattn_kernel,
                         cudaFuncAttributeMaxDynamicSharedMemorySize, FA_SMEM_BYTES);

    // 1) ALL conversions in one grid (hidden, w_qkv, w_o)
    conv_all_kernel<<<NB_WQKV + NB_WO + NB_H, 256>>>(hidden, w_qkv, w_o);
    // 2) QKV GEMM (2-term) -> g_qkv fp32
    hgemm_kernel<<<dim3(T_ / 128, 3 * HID_ / 128), 128, G_SMEM>>>(
        ahp, bhp, blp, qkvp, 3 * HID_, HID_);
    // 3) RoPE + caches + fp16 attention operands
    rope_cache_kernel<<<T_ * H_ / 8, 256>>>(cosT, sinT, kc, vc);
    // 4) flash attention -> ctx fp16 into g_Ah
    fattn_kernel<<<1024, 256, FA_SMEM_BYTES>>>();
    // 5) output projection (2-term) -> out
    hgemm_kernel<<<dim3(T_ / 128, HID_ / 128), 128, G_SMEM>>>(
        ahp, whp, wlp, out, HID_, HID_);
}

// round 13
// speedup vs baseline: 1.8627x; 1.7497x over previous
#include <cuda_runtime.h>
#include <cuda_fp16.h>
#include <cstdint>
#include <cstddef>

// Problem constants
constexpr int H_   = 32;
constexpr int D_   = 128;
constexpr int HID_ = 4096;   // H*D
constexpr int B_   = 4;
constexpr int S_   = 1024;
constexpr int T_   = 4096;   // B*S
constexpr float SCALE_ = 0.08838834764831845f;  // D^-0.5

// Scratch (allocation-free rule: __device__ globals)
__device__ float g_qkv[(size_t)T_ * 3 * HID_];   // [T, 3*HID]
// GEMM fp16 operands (1-term: hi only on both sides)
__device__ __half g_Ah[(size_t)T_ * HID_];       // A hi (hidden, then ctx)
__device__ __half g_Bh[(size_t)HID_ * 3 * HID_]; // w_qkv^T hi [N][K]
__device__ __half g_Wh[(size_t)HID_ * HID_];     // w_o^T hi
// Attention fp16 operands (written by rope kernel)
__device__ __half g_Qh[(size_t)T_ * HID_];
__device__ __half g_Ql[(size_t)T_ * HID_];
__device__ __half g_Kh[(size_t)T_ * HID_];
__device__ __half g_Kl[(size_t)T_ * HID_];
__device__ __half g_Vh[(size_t)T_ * HID_];       // V hi only

// ---------------------------------------------------------------------------
// helpers
// ---------------------------------------------------------------------------
__device__ __forceinline__ uint32_t smem_u32(const void* p) {
    uint32_t a;
    asm("{ .reg .u64 t; cvta.to.shared.u64 t, %1; cvt.u32.u64 %0, t; }"
        : "=r"(a) : "l"(p));
    return a;
}
__device__ __forceinline__ void cp16(uint32_t dst, const void* src) {
    asm volatile("cp.async.cg.shared.global [%0], [%1], 16;" :: "r"(dst), "l"(src));
}
__device__ __forceinline__ void cp_commit() { asm volatile("cp.async.commit_group;"); }
template<int Ngrp> __device__ __forceinline__ void cp_wait() {
    asm volatile("cp.async.wait_group %0;" :: "n"(Ngrp));
}
__device__ __forceinline__ void ldsm4(uint32_t* r, uint32_t addr) {
    asm volatile("ldmatrix.sync.aligned.m8n8.x4.shared.b16 {%0,%1,%2,%3}, [%4];"
                 : "=r"(r[0]), "=r"(r[1]), "=r"(r[2]), "=r"(r[3]) : "r"(addr));
}
__device__ __forceinline__ void ldsm4t(uint32_t* r, uint32_t addr) {
    asm volatile("ldmatrix.sync.aligned.m8n8.x4.trans.shared.b16 {%0,%1,%2,%3}, [%4];"
                 : "=r"(r[0]), "=r"(r[1]), "=r"(r[2]), "=r"(r[3]) : "r"(addr));
}
__device__ __forceinline__ void mma16816(float* c, const uint32_t* a, const uint32_t* b) {
    asm volatile("mma.sync.aligned.m16n8k16.row.col.f32.f16.f16.f32 "
                 "{%0,%1,%2,%3}, {%4,%5,%6,%7}, {%8,%9}, {%0,%1,%2,%3};"
                 : "+f"(c[0]), "+f"(c[1]), "+f"(c[2]), "+f"(c[3])
                 : "r"(a[0]), "r"(a[1]), "r"(a[2]), "r"(a[3]), "r"(b[0]), "r"(b[1]));
}
__device__ __forceinline__ uint32_t packh2(float x, float y) {
    __half2 p = __halves2half2(__float2half_rn(x), __float2half_rn(y));
    return *(uint32_t*)&p;
}
__device__ __forceinline__ uint32_t packlo2(float x, float y) {
    __half h0 = __float2half_rn(x), h1 = __float2half_rn(y);
    return packh2(x - __half2float(h0), y - __half2float(h1));
}

// ---------------------------------------------------------------------------
// conv_all: one grid for all conversions (hi-only weights).
//   blocks [0, NB_WQKV):            w_qkv -> g_Bh (transposed hi)
//   blocks [NB_WQKV, +NB_WO):       w_o   -> g_Wh (transposed hi)
//   blocks [NB_WQKV+NB_WO, +NB_H):  hidden -> g_Ah (hi)
// ---------------------------------------------------------------------------
constexpr int NB_WQKV = (HID_ / 32) * (3 * HID_ / 64);   // 24576
constexpr int NB_WO   = (HID_ / 32) * (HID_ / 64);       // 8192
constexpr int NB_H    = (int)((size_t)T_ * HID_ / 8 / 256); // 8192

__device__ __forceinline__ void convT_body(const float* __restrict__ w,
                                           __half* __restrict__ hi,
                                           int K, int N, int bk, int bn,
                                           float (*t)[65])
{
    const int k0 = bk * 32, n0 = bn * 64;
    const int tx = threadIdx.x & 63, ty = threadIdx.x >> 6;   // ty 0..3
    #pragma unroll
    for (int i = 0; i < 32; i += 4)
        t[ty + i][tx] = w[(size_t)(k0 + ty + i) * N + n0 + tx];
    __syncthreads();

    const int nl = threadIdx.x >> 2;
    const int kg = threadIdx.x & 3;
    float x[8];
    #pragma unroll
    for (int j = 0; j < 8; j++) x[j] = t[kg * 8 + j][nl];   // conflict-free
    uint4 uh;
    uint32_t* ph = (uint32_t*)&uh;
    #pragma unroll
    for (int j = 0; j < 4; j++) ph[j] = packh2(x[2*j], x[2*j+1]);
    size_t o = (size_t)(n0 + nl) * K + k0 + kg * 8;
    *(uint4*)(hi + o) = uh;
}

__global__ __launch_bounds__(256)
void conv_all_kernel(const float* __restrict__ hidden,
                     const float* __restrict__ w_qkv,
                     const float* __restrict__ w_o)
{
    __shared__ float t[32][65];
    const int bid = blockIdx.x;
    if (bid < NB_WQKV) {
        convT_body(w_qkv, g_Bh, HID_, 3 * HID_, bid & 127, bid >> 7, t);
    } else if (bid < NB_WQKV + NB_WO) {
        const int b2 = bid - NB_WQKV;
        convT_body(w_o, g_Wh, HID_, HID_, b2 & 127, b2 >> 7, t);
    } else {
        const int b2 = bid - NB_WQKV - NB_WO;
        size_t base = ((size_t)b2 * 256 + threadIdx.x) * 8;
        const float4* s = (const float4*)(hidden + base);
        float4 a = s[0], b = s[1];
        float x[8] = {a.x, a.y, a.z, a.w, b.x, b.y, b.z, b.w};
        uint4 uh;
        uint32_t* ph = (uint32_t*)&uh;
        #pragma unroll
        for (int j = 0; j < 4; j++) ph[j] = packh2(x[2*j], x[2*j+1]);
        *(uint4*)(g_Ah + base) = uh;
    }
}

// ---------------------------------------------------------------------------
// HGEMM: C[M,N] = A @ B, 1-term fp16 (ah*bh), fp32 accum.
// A: [M,K] hi row-major.  B: [N,K] hi row-major (B^T).
// 128x128 CTA tile, BK=32, 4-stage cp.async, 128 threads (2x2 warps,
// 64x64 warp tile), 64 KB smem, 2 CTAs/SM, 1 sync/stage.
// ---------------------------------------------------------------------------
constexpr int G_STAGE = 16384;            // Ah 8K | Bh 8K
constexpr int G_SMEM  = 4 * G_STAGE;      // 64 KB

__global__ __launch_bounds__(128, 2)
void hgemm_kernel(const __half* __restrict__ Ah, const __half* __restrict__ Bh,
                  float* __restrict__ C, int N, int K)
{
    extern __shared__ char sm[];
    const int tid  = threadIdx.x;
    const int wid  = tid >> 5, lane = tid & 31;
    const int bm = blockIdx.x, bn = blockIdx.y;
    const int wm = (wid >> 1) * 64;
    const int wn = (wid & 1) * 64;
    const int KT = K / 32;
    const uint32_t sb = smem_u32(sm);

    const __half* aop = Ah + (size_t)bm * 128 * K;
    const __half* bop = Bh + (size_t)bn * 128 * K;

    auto prefetch = [&](int kt) {
        const uint32_t st = sb + (kt & 3) * G_STAGE;
        #pragma unroll
        for (int op = 0; op < 2; op++) {
            const __half* src = (op == 0) ? aop : bop;
            #pragma unroll
            for (int h4 = 0; h4 < 4; h4++) {
                int ch = h4 * 128 + tid;
                int row = ch >> 2, c = ch & 3;
                cp16(st + op * 8192 + row * 64 + ((c ^ (row & 3)) << 4),
                     src + (size_t)row * K + kt * 32 + c * 8);
            }
        }
        cp_commit();
    };

    prefetch(0);
    if (KT > 1) prefetch(1);
    if (KT > 2) prefetch(2);

    float acc[4][8][4] = {};

    for (int kt = 0; kt < KT; kt++) {
        if (kt + 2 < KT)      cp_wait<2>();
        else if (kt + 1 < KT) cp_wait<1>();
        else                  cp_wait<0>();
        __syncthreads();
        if (kt + 3 < KT) prefetch(kt + 3);

        const uint32_t st = sb + (kt & 3) * G_STAGE;
        #pragma unroll
        for (int ks = 0; ks < 2; ks++) {
            uint32_t ahf[4][4], bhf[4][4];
            #pragma unroll
            for (int mt = 0; mt < 4; mt++) {
                int row = wm + mt * 16 + (lane & 15);
                int c   = ks * 2 + (lane >> 4);
                ldsm4(ahf[mt], st + row * 64 + ((c ^ (row & 3)) << 4));
            }
            #pragma unroll
            for (int p = 0; p < 4; p++) {
                int n = wn + p * 16 + ((lane >> 4) << 3) + (lane & 7);
                int c = ks * 2 + ((lane >> 3) & 1);
                ldsm4(bhf[p], st + 8192 + n * 64 + ((c ^ (n & 3)) << 4));
            }
            #pragma unroll
            for (int mt = 0; mt < 4; mt++)
                #pragma unroll
                for (int nt = 0; nt < 8; nt++)
                    mma16816(acc[mt][nt], ahf[mt], &bhf[nt >> 1][(nt & 1) * 2]);
        }
    }

    #pragma unroll
    for (int mt = 0; mt < 4; mt++)
        #pragma unroll
        for (int nt = 0; nt < 8; nt++) {
            int r0  = bm * 128 + wm + mt * 16 + (lane >> 2);
            int col = bn * 128 + wn + nt * 8 + (lane & 3) * 2;
            *(float2*)(C + (size_t)r0 * N + col) =
                make_float2(acc[mt][nt][0], acc[mt][nt][1]);
            *(float2*)(C + (size_t)(r0 + 8) * N + col) =
                make_float2(acc[mt][nt][2], acc[mt][nt][3]);
        }
}

// ---------------------------------------------------------------------------
// RoPE + cache scatter + fp16 emit. Warp per (t,h); 256-thread blocks.
// ---------------------------------------------------------------------------
__global__ __launch_bounds__(256)
void rope_cache_kernel(const float* __restrict__ cosT,
                       const float* __restrict__ sinT,
                       float* __restrict__ kc,
                       float* __restrict__ vc)
{
    const int gw = blockIdx.x * 8 + (threadIdx.x >> 5);   // (t,h) index
    const int t = gw >> 5;
    const int h = gw & 31;
    const int lane = threadIdx.x & 31;

    const float2 c2 = *(const float2*)(cosT + t * 64 + 2 * lane);
    const float2 s2 = *(const float2*)(sinT + t * 64 + 2 * lane);

    const size_t base = (size_t)t * 3 * HID_ + h * D_ + 4 * lane;
    const size_t co   = (size_t)t * HID_ + h * D_ + 4 * lane;

    {
        float4 q = *(const float4*)(g_qkv + base);
        float a0 = q.x * c2.x - q.y * s2.x, a1 = q.y * c2.x + q.x * s2.x;
        float a2 = q.z * c2.y - q.w * s2.y, a3 = q.w * c2.y + q.z * s2.y;
        *(uint2*)(g_Qh + co) = make_uint2(packh2(a0, a1), packh2(a2, a3));
        *(uint2*)(g_Ql + co) = make_uint2(packlo2(a0, a1), packlo2(a2, a3));
    }
    {
        float4 k = *(const float4*)(g_qkv + base + HID_);
        float b0 = k.x * c2.x - k.y * s2.x, b1 = k.y * c2.x + k.x * s2.x;
        float b2 = k.z * c2.y - k.w * s2.y, b3 = k.w * c2.y + k.z * s2.y;
        *(float4*)(kc + co) = make_float4(b0, b1, b2, b3);
        *(uint2*)(g_Kh + co) = make_uint2(packh2(b0, b1), packh2(b2, b3));
        *(uint2*)(g_Kl + co) = make_uint2(packlo2(b0, b1), packlo2(b2, b3));
    }
    {
        float4 v = *(const float4*)(g_qkv + base + 2 * HID_);
        *(float4*)(vc + co) = v;
        *(uint2*)(g_Vh + co) = make_uint2(packh2(v.x, v.y), packh2(v.z, v.w));
    }
}

// ---------------------------------------------------------------------------
// Flash attention. S = 3-term split; P·V = 2-term. 1D grid, heavy-first.
// ---------------------------------------------------------------------------
constexpr int FA_ST = 34816;          // stage stride in halfs
constexpr int FA_SMEM_BYTES = (34816 + 2 * 34816) * 2;   // 208896

__global__ __launch_bounds__(256, 1)
void fattn_kernel()
{
    extern __shared__ __half fsm[];
    const int tid = threadIdx.x;
    const int wid = tid >> 5, lane = tid & 31;
    const int bid = blockIdx.x;
    const int qt = 7 - (bid >> 7);            // all heavy tiles first, globally
    const int h = bid & 31;
    const int b = (bid >> 5) & 3;
    const int t0 = b * S_ + qt * 128;
    const int wrow = wid * 16;
    const uint32_t sb = smem_u32(fsm);

    {
        const __half* qsrc[2] = {g_Qh, g_Ql};
        #pragma unroll
        for (int a = 0; a < 2; a++)
            #pragma unroll
            for (int j = 0; j < 8; j++) {
                int ch = j * 256 + tid;
                int r = ch >> 4, c = ch & 15;
                cp16(sb + (a * 17408 + r * 136 + c * 8) * 2,
                     qsrc[a] + (size_t)(t0 + r) * HID_ + h * D_ + c * 8);
            }
    }

    auto kvload = [&](int kt) {
        const uint32_t dstb = sb + (FA_ST + (kt & 1) * FA_ST) * 2;
        const int tk0 = b * S_ + kt * 64;
        const __half* srcs[3] = {g_Kh, g_Kl, g_Vh};
        #pragma unroll
        for (int a = 0; a < 3; a++)
            #pragma unroll
            for (int j = 0; j < 4; j++) {
                int ch = j * 256 + tid;
                int r = ch >> 4, c = ch & 15;
                cp16(dstb + (a * 8704 + r * 136 + c * 8) * 2,
                     srcs[a] + (size_t)(tk0 + r) * HID_ + h * D_ + c * 8);
            }
        cp_commit();
    };

    const int ktmax = 2 * qt + 1;
    kvload(0);

    float acc[16][4] = {};
    float m_i[2] = {-1e30f, -1e30f};
    float l_i[2] = {0.f, 0.f};

    for (int kt = 0; kt <= ktmax; kt++) {
        if (kt + 1 <= ktmax) { kvload(kt + 1); cp_wait<1>(); }
        else cp_wait<0>();
        __syncthreads();

        const uint32_t stb = sb + (FA_ST + (kt & 1) * FA_ST) * 2;
        const bool active = (kt * 64 <= qt * 128 + wrow + 15);

        if (active) {
            float s[8][4] = {};
            #pragma unroll
            for (int ks = 0; ks < 8; ks++) {
                uint32_t qh[4], ql[4];
                {
                    int row = wrow + (lane & 15);
                    int seg = ks * 16 + 8 * (lane >> 4);
                    uint32_t addr = sb + (row * 136 + seg) * 2;
                    ldsm4(qh, addr);
                    ldsm4(ql, addr + 17408 * 2);
                }
                #pragma unroll
                for (int np = 0; np < 4; np++) {
                    uint32_t kh[4], kl[4];
                    int n = np * 16 + ((lane >> 4) << 3) + (lane & 7);
                    int seg = ks * 16 + 8 * ((lane >> 3) & 1);
                    uint32_t addr = stb + (n * 136 + seg) * 2;
                    ldsm4(kh, addr);
                    ldsm4(kl, addr + 8704 * 2);
                    #pragma unroll
                    for (int half_ = 0; half_ < 2; half_++) {
                        float* st_ = s[np * 2 + half_];
                        const uint32_t* bh2 = &kh[half_ * 2];
                        const uint32_t* bl2 = &kl[half_ * 2];
                        mma16816(st_, qh, bh2);
                        mma16816(st_, qh, bl2);
                        mma16816(st_, ql, bh2);
                    }
                }
            }

            const int rbase = qt * 128 + wrow + (lane >> 2);
            if (kt * 64 + 63 > qt * 128 + wrow) {
                #pragma unroll
                for (int j = 0; j < 8; j++)
                    #pragma unroll
                    for (int cc = 0; cc < 4; cc++) {
                        int colg = kt * 64 + j * 8 + (lane & 3) * 2 + (cc & 1);
                        int rowg = rbase + (cc >> 1) * 8;
                        if (colg > rowg) s[j][cc] = -1e30f;
                    }
            }
            #pragma unroll
            for (int j = 0; j < 8; j++)
                #pragma unroll
                for (int cc = 0; cc < 4; cc++) s[j][cc] *= SCALE_;

            #pragma unroll
            for (int hr = 0; hr < 2; hr++) {
                float rm = -1e30f;
                #pragma unroll
                for (int j = 0; j < 8; j++)
                    rm = fmaxf(rm, fmaxf(s[j][hr * 2], s[j][hr * 2 + 1]));
                rm = fmaxf(rm, __shfl_xor_sync(0xffffffffu, rm, 1));
                rm = fmaxf(rm, __shfl_xor_sync(0xffffffffu, rm, 2));
                float nm  = fmaxf(m_i[hr], rm);
                float fac = __expf(m_i[hr] - nm);
                m_i[hr] = nm;
                float rs = 0.f;
                #pragma unroll
                for (int j = 0; j < 8; j++) {
                    float p0 = __expf(s[j][hr * 2]     - nm);
                    float p1 = __expf(s[j][hr * 2 + 1] - nm);
                    s[j][hr * 2]     = p0;
                    s[j][hr * 2 + 1] = p1;
                    rs += p0 + p1;
                }
                rs += __shfl_xor_sync(0xffffffffu, rs, 1);
                rs += __shfl_xor_sync(0xffffffffu, rs, 2);
                l_i[hr] = l_i[hr] * fac + rs;
                #pragma unroll
                for (int nt = 0; nt < 16; nt++) {
                    acc[nt][hr * 2]     *= fac;
                    acc[nt][hr * 2 + 1] *= fac;
                }
            }

            uint32_t aH[4][4], aL[4][4];
            #pragma unroll
            for (int ks = 0; ks < 4; ks++) {
                #pragma unroll
                for (int half_ = 0; half_ < 2; half_++) {
                    const float* sj = s[ks * 2 + half_];
                    #pragma unroll
                    for (int rr = 0; rr < 2; rr++) {
                        float x0 = sj[rr * 2], x1 = sj[rr * 2 + 1];
                        aH[ks][half_ * 2 + rr] = packh2(x0, x1);
                        aL[ks][half_ * 2 + rr] = packlo2(x0, x1);
                    }
                }
            }

            // O += (P_hi + P_lo) · V_hi
            #pragma unroll
            for (int ks = 0; ks < 4; ks++) {
                #pragma unroll
                for (int ntp = 0; ntp < 8; ntp++) {
                    uint32_t vh[4];
                    int kr = ks * 16 + (lane & 7) + 8 * ((lane >> 3) & 1);
                    int nc = ntp * 16 + 8 * (lane >> 4);
                    ldsm4t(vh, stb + (17408 + kr * 136 + nc) * 2);
                    #pragma unroll
                    for (int half_ = 0; half_ < 2; half_++) {
                        float* ot = acc[ntp * 2 + half_];
                        const uint32_t* vh2 = &vh[half_ * 2];
                        mma16816(ot, aH[ks], vh2);
                        mma16816(ot, aL[ks], vh2);
                    }
                }
            }
        }
        __syncthreads();
    }

    float inv0 = 1.0f / l_i[0], inv1 = 1.0f / l_i[1];
    #pragma unroll
    for (int nt = 0; nt < 16; nt++) {
        float o0 = acc[nt][0] * inv0, o1 = acc[nt][1] * inv0;
        float o2 = acc[nt][2] * inv1, o3 = acc[nt][3] * inv1;
        size_t col = (size_t)h * D_ + nt * 8 + (lane & 3) * 2;
        size_t r0 = (size_t)(t0 + wrow + (lane >> 2)) * HID_ + col;
        size_t r1 = r0 + 8 * HID_;
        *(uint32_t*)(g_Ah + r0) = packh2(o0, o1);
        *(uint32_t*)(g_Ah + r1) = packh2(o2, o3);
    }
}

// ---------------------------------------------------------------------------
// Launch
// ---------------------------------------------------------------------------
extern "C" void kernel_launch(void* const* d_in, const int* in_sizes, int n_in,
                              void* d_out, int out_size)
{
    const float* hidden = (const float*)d_in[0];
    const float* cosT   = (const float*)d_in[1];
    const float* sinT   = (const float*)d_in[2];
    const float* w_qkv  = (const float*)d_in[3];
    const float* w_o    = (const float*)d_in[4];

    float* out = (float*)d_out;
    float* kc  = out + (size_t)T_ * HID_;
    float* vc  = kc + (size_t)T_ * HID_;

    float* qkvp = nullptr;
    __half *ahp = nullptr, *bhp = nullptr, *whp = nullptr;
    cudaGetSymbolAddress((void**)&qkvp, g_qkv);
    cudaGetSymbolAddress((void**)&ahp, g_Ah);
    cudaGetSymbolAddress((void**)&bhp, g_Bh);
    cudaGetSymbolAddress((void**)&whp, g_Wh);

    cudaFuncSetAttribute(hgemm_kernel,
                         cudaFuncAttributeMaxDynamicSharedMemorySize, G_SMEM);
    cudaFuncSetAttribute(fattn_kernel,
                         cudaFuncAttributeMaxDynamicSharedMemorySize, FA_SMEM_BYTES);

    // 1) ALL conversions in one grid (hidden, w_qkv, w_o) — hi only
    conv_all_kernel<<<NB_WQKV + NB_WO + NB_H, 256>>>(hidden, w_qkv, w_o);
    // 2) QKV GEMM (1-term fp16) -> g_qkv fp32
    hgemm_kernel<<<dim3(T_ / 128, 3 * HID_ / 128), 128, G_SMEM>>>(
        ahp, bhp, qkvp, 3 * HID_, HID_);
    // 3) RoPE + caches + fp16 attention operands
    rope_cache_kernel<<<T_ * H_ / 8, 256>>>(cosT, sinT, kc, vc);
    // 4) flash attention -> ctx fp16 into g_Ah
    fattn_kernel<<<1024, 256, FA_SMEM_BYTES>>>();
    // 5) output projection (1-term fp16) -> out
    hgemm_kernel<<<dim3(T_ / 128, HID_ / 128), 128, G_SMEM>>>(
        ahp, whp, out, HID_, HID_);
}

// round 14
// speedup vs baseline: 2.0061x; 1.0770x over previous
#include <cuda_runtime.h>
#include <cuda_fp16.h>
#include <cstdint>
#include <cstddef>

// Problem constants
constexpr int H_   = 32;
constexpr int D_   = 128;
constexpr int HID_ = 4096;   // H*D
constexpr int B_   = 4;
constexpr int S_   = 1024;
constexpr int T_   = 4096;   // B*S
constexpr float SCALE_ = 0.08838834764831845f;  // D^-0.5
constexpr float SC2_   = 0.12752966089200528f;  // SCALE * log2(e)

// Scratch (allocation-free rule: __device__ globals)
__device__ float g_qkv[(size_t)T_ * 3 * HID_];   // [T, 3*HID]
// GEMM fp16 operands (1-term: hi only on both sides)
__device__ __half g_Ah[(size_t)T_ * HID_];       // A hi (hidden, then ctx)
__device__ __half g_Bh[(size_t)HID_ * 3 * HID_]; // w_qkv^T hi [N][K]
__device__ __half g_Wh[(size_t)HID_ * HID_];     // w_o^T hi
// Attention fp16 operands (hi only now)
__device__ __half g_Qh[(size_t)T_ * HID_];
__device__ __half g_Kh[(size_t)T_ * HID_];
__device__ __half g_Vh[(size_t)T_ * HID_];

// ---------------------------------------------------------------------------
// helpers
// ---------------------------------------------------------------------------
__device__ __forceinline__ uint32_t smem_u32(const void* p) {
    uint32_t a;
    asm("{ .reg .u64 t; cvta.to.shared.u64 t, %1; cvt.u32.u64 %0, t; }"
        : "=r"(a) : "l"(p));
    return a;
}
__device__ __forceinline__ void cp16(uint32_t dst, const void* src) {
    asm volatile("cp.async.cg.shared.global [%0], [%1], 16;" :: "r"(dst), "l"(src));
}
__device__ __forceinline__ void cp_commit() { asm volatile("cp.async.commit_group;"); }
template<int Ngrp> __device__ __forceinline__ void cp_wait() {
    asm volatile("cp.async.wait_group %0;" :: "n"(Ngrp));
}
__device__ __forceinline__ void ldsm4(uint32_t* r, uint32_t addr) {
    asm volatile("ldmatrix.sync.aligned.m8n8.x4.shared.b16 {%0,%1,%2,%3}, [%4];"
                 : "=r"(r[0]), "=r"(r[1]), "=r"(r[2]), "=r"(r[3]) : "r"(addr));
}
__device__ __forceinline__ void ldsm4t(uint32_t* r, uint32_t addr) {
    asm volatile("ldmatrix.sync.aligned.m8n8.x4.trans.shared.b16 {%0,%1,%2,%3}, [%4];"
                 : "=r"(r[0]), "=r"(r[1]), "=r"(r[2]), "=r"(r[3]) : "r"(addr));
}
__device__ __forceinline__ void mma16816(float* c, const uint32_t* a, const uint32_t* b) {
    asm volatile("mma.sync.aligned.m16n8k16.row.col.f32.f16.f16.f32 "
                 "{%0,%1,%2,%3}, {%4,%5,%6,%7}, {%8,%9}, {%0,%1,%2,%3};"
                 : "+f"(c[0]), "+f"(c[1]), "+f"(c[2]), "+f"(c[3])
                 : "r"(a[0]), "r"(a[1]), "r"(a[2]), "r"(a[3]), "r"(b[0]), "r"(b[1]));
}
__device__ __forceinline__ uint32_t packh2(float x, float y) {
    __half2 p = __halves2half2(__float2half_rn(x), __float2half_rn(y));
    return *(uint32_t*)&p;
}

// ---------------------------------------------------------------------------
// conv_all: one grid for all conversions (hi-only everywhere).
// ---------------------------------------------------------------------------
constexpr int NB_WQKV = (HID_ / 32) * (3 * HID_ / 64);      // 24576
constexpr int NB_WO   = (HID_ / 32) * (HID_ / 64);          // 8192
constexpr int NB_H    = (int)((size_t)T_ * HID_ / 8 / 256); // 8192

__device__ __forceinline__ void convT_body(const float* __restrict__ w,
                                           __half* __restrict__ hi,
                                           int K, int N, int bk, int bn,
                                           float (*t)[65])
{
    const int k0 = bk * 32, n0 = bn * 64;
    const int tx = threadIdx.x & 63, ty = threadIdx.x >> 6;
    #pragma unroll
    for (int i = 0; i < 32; i += 4)
        t[ty + i][tx] = w[(size_t)(k0 + ty + i) * N + n0 + tx];
    __syncthreads();

    const int nl = threadIdx.x >> 2;
    const int kg = threadIdx.x & 3;
    float x[8];
    #pragma unroll
    for (int j = 0; j < 8; j++) x[j] = t[kg * 8 + j][nl];   // conflict-free
    uint4 uh;
    uint32_t* ph = (uint32_t*)&uh;
    #pragma unroll
    for (int j = 0; j < 4; j++) ph[j] = packh2(x[2*j], x[2*j+1]);
    *(uint4*)(hi + (size_t)(n0 + nl) * K + k0 + kg * 8) = uh;
}

__global__ __launch_bounds__(256)
void conv_all_kernel(const float* __restrict__ hidden,
                     const float* __restrict__ w_qkv,
                     const float* __restrict__ w_o)
{
    __shared__ float t[32][65];
    const int bid = blockIdx.x;
    if (bid < NB_WQKV) {
        convT_body(w_qkv, g_Bh, HID_, 3 * HID_, bid & 127, bid >> 7, t);
    } else if (bid < NB_WQKV + NB_WO) {
        const int b2 = bid - NB_WQKV;
        convT_body(w_o, g_Wh, HID_, HID_, b2 & 127, b2 >> 7, t);
    } else {
        const int b2 = bid - NB_WQKV - NB_WO;
        size_t base = ((size_t)b2 * 256 + threadIdx.x) * 8;
        const float4* s = (const float4*)(hidden + base);
        float4 a = s[0], b = s[1];
        float x[8] = {a.x, a.y, a.z, a.w, b.x, b.y, b.z, b.w};
        uint4 uh;
        uint32_t* ph = (uint32_t*)&uh;
        #pragma unroll
        for (int j = 0; j < 4; j++) ph[j] = packh2(x[2*j], x[2*j+1]);
        *(uint4*)(g_Ah + base) = uh;
    }
}

// ---------------------------------------------------------------------------
// HGEMM: 1-term fp16 (ah*bh), fp32 accum. 128x128 CTA tile, BK=32,
// 4-stage cp.async, 128 threads (2x2 warps, 64x64 warp tile), 2 CTAs/SM.
// ---------------------------------------------------------------------------
constexpr int G_STAGE = 16384;
constexpr int G_SMEM  = 4 * G_STAGE;      // 64 KB

__global__ __launch_bounds__(128, 2)
void hgemm_kernel(const __half* __restrict__ Ah, const __half* __restrict__ Bh,
                  float* __restrict__ C, int N, int K)
{
    extern __shared__ char sm[];
    const int tid  = threadIdx.x;
    const int wid  = tid >> 5, lane = tid & 31;
    const int bm = blockIdx.x, bn = blockIdx.y;
    const int wm = (wid >> 1) * 64;
    const int wn = (wid & 1) * 64;
    const int KT = K / 32;
    const uint32_t sb = smem_u32(sm);

    const __half* aop = Ah + (size_t)bm * 128 * K;
    const __half* bop = Bh + (size_t)bn * 128 * K;

    auto prefetch = [&](int kt) {
        const uint32_t st = sb + (kt & 3) * G_STAGE;
        #pragma unroll
        for (int op = 0; op < 2; op++) {
            const __half* src = (op == 0) ? aop : bop;
            #pragma unroll
            for (int h4 = 0; h4 < 4; h4++) {
                int ch = h4 * 128 + tid;
                int row = ch >> 2, c = ch & 3;
                cp16(st + op * 8192 + row * 64 + ((c ^ (row & 3)) << 4),
                     src + (size_t)row * K + kt * 32 + c * 8);
            }
        }
        cp_commit();
    };

    prefetch(0);
    if (KT > 1) prefetch(1);
    if (KT > 2) prefetch(2);

    float acc[4][8][4] = {};

    for (int kt = 0; kt < KT; kt++) {
        if (kt + 2 < KT)      cp_wait<2>();
        else if (kt + 1 < KT) cp_wait<1>();
        else                  cp_wait<0>();
        __syncthreads();
        if (kt + 3 < KT) prefetch(kt + 3);

        const uint32_t st = sb + (kt & 3) * G_STAGE;
        #pragma unroll
        for (int ks = 0; ks < 2; ks++) {
            uint32_t ahf[4][4], bhf[4][4];
            #pragma unroll
            for (int mt = 0; mt < 4; mt++) {
                int row = wm + mt * 16 + (lane & 15);
                int c   = ks * 2 + (lane >> 4);
                ldsm4(ahf[mt], st + row * 64 + ((c ^ (row & 3)) << 4));
            }
            #pragma unroll
            for (int p = 0; p < 4; p++) {
                int n = wn + p * 16 + ((lane >> 4) << 3) + (lane & 7);
                int c = ks * 2 + ((lane >> 3) & 1);
                ldsm4(bhf[p], st + 8192 + n * 64 + ((c ^ (n & 3)) << 4));
            }
            #pragma unroll
            for (int mt = 0; mt < 4; mt++)
                #pragma unroll
                for (int nt = 0; nt < 8; nt++)
                    mma16816(acc[mt][nt], ahf[mt], &bhf[nt >> 1][(nt & 1) * 2]);
        }
    }

    #pragma unroll
    for (int mt = 0; mt < 4; mt++)
        #pragma unroll
        for (int nt = 0; nt < 8; nt++) {
            int r0  = bm * 128 + wm + mt * 16 + (lane >> 2);
            int col = bn * 128 + wn + nt * 8 + (lane & 3) * 2;
            *(float2*)(C + (size_t)r0 * N + col) =
                make_float2(acc[mt][nt][0], acc[mt][nt][1]);
            *(float2*)(C + (size_t)(r0 + 8) * N + col) =
                make_float2(acc[mt][nt][2], acc[mt][nt][3]);
        }
}

// ---------------------------------------------------------------------------
// RoPE + cache scatter + fp16 hi emit. Warp per (t,h); 256-thread blocks.
// ---------------------------------------------------------------------------
__global__ __launch_bounds__(256)
void rope_cache_kernel(const float* __restrict__ cosT,
                       const float* __restrict__ sinT,
                       float* __restrict__ kc,
                       float* __restrict__ vc)
{
    const int gw = blockIdx.x * 8 + (threadIdx.x >> 5);   // (t,h) index
    const int t = gw >> 5;
    const int h = gw & 31;
    const int lane = threadIdx.x & 31;

    const float2 c2 = *(const float2*)(cosT + t * 64 + 2 * lane);
    const float2 s2 = *(const float2*)(sinT + t * 64 + 2 * lane);

    const size_t base = (size_t)t * 3 * HID_ + h * D_ + 4 * lane;
    const size_t co   = (size_t)t * HID_ + h * D_ + 4 * lane;

    {
        float4 q = *(const float4*)(g_qkv + base);
        float a0 = q.x * c2.x - q.y * s2.x, a1 = q.y * c2.x + q.x * s2.x;
        float a2 = q.z * c2.y - q.w * s2.y, a3 = q.w * c2.y + q.z * s2.y;
        *(uint2*)(g_Qh + co) = make_uint2(packh2(a0, a1), packh2(a2, a3));
    }
    {
        float4 k = *(const float4*)(g_qkv + base + HID_);
        float b0 = k.x * c2.x - k.y * s2.x, b1 = k.y * c2.x + k.x * s2.x;
        float b2 = k.z * c2.y - k.w * s2.y, b3 = k.w * c2.y + k.z * s2.y;
        *(float4*)(kc + co) = make_float4(b0, b1, b2, b3);
        *(uint2*)(g_Kh + co) = make_uint2(packh2(b0, b1), packh2(b2, b3));
    }
    {
        float4 v = *(const float4*)(g_qkv + base + 2 * HID_);
        *(float4*)(vc + co) = v;
        *(uint2*)(g_Vh + co) = make_uint2(packh2(v.x, v.y), packh2(v.z, v.w));
    }
}

// ---------------------------------------------------------------------------
// Flash attention, pure fp16 MMA (1-term S, 1-term PV), fp32 accum + softmax.
// smem (halfs): Qh[128][136] @0; stage s @ 17408 + s*17408:
//   Kh[64][136] @+0, Vh[64][136] @+8704.
// 102 KB smem -> 2 CTAs/SM.
// ---------------------------------------------------------------------------
constexpr int FA_ST = 17408;                      // stage stride in halfs
constexpr int FA_SMEM_BYTES = (17408 + 2 * 17408) * 2;   // 104448

__global__ __launch_bounds__(256, 2)
void fattn_kernel()
{
    extern __shared__ __half fsm[];
    const int tid = threadIdx.x;
    const int wid = tid >> 5, lane = tid & 31;
    const int bid = blockIdx.x;
    const int qt = 7 - (bid >> 7);            // heavy tiles first, globally
    const int h = bid & 31;
    const int b = (bid >> 5) & 3;
    const int t0 = b * S_ + qt * 128;
    const int wrow = wid * 16;
    const uint32_t sb = smem_u32(fsm);

    // Q hi tile load
    #pragma unroll
    for (int j = 0; j < 8; j++) {
        int ch = j * 256 + tid;
        int r = ch >> 4, c = ch & 15;
        cp16(sb + (r * 136 + c * 8) * 2,
             g_Qh + (size_t)(t0 + r) * HID_ + h * D_ + c * 8);
    }

    auto kvload = [&](int kt) {
        const uint32_t dstb = sb + (FA_ST + (kt & 1) * FA_ST) * 2;
        const int tk0 = b * S_ + kt * 64;
        const __half* srcs[2] = {g_Kh, g_Vh};
        #pragma unroll
        for (int a = 0; a < 2; a++)
            #pragma unroll
            for (int j = 0; j < 4; j++) {
                int ch = j * 256 + tid;
                int r = ch >> 4, c = ch & 15;
                cp16(dstb + (a * 8704 + r * 136 + c * 8) * 2,
                     srcs[a] + (size_t)(tk0 + r) * HID_ + h * D_ + c * 8);
            }
        cp_commit();
    };

    const int ktmax = 2 * qt + 1;
    kvload(0);

    float acc[16][4] = {};
    float m_i[2] = {-1e30f, -1e30f};
    float l_i[2] = {0.f, 0.f};

    for (int kt = 0; kt <= ktmax; kt++) {
        if (kt + 1 <= ktmax) { kvload(kt + 1); cp_wait<1>(); }
        else cp_wait<0>();
        __syncthreads();

        const uint32_t stb = sb + (FA_ST + (kt & 1) * FA_ST) * 2;
        const bool active = (kt * 64 <= qt * 128 + wrow + 15);

        if (active) {
            // ---- S = Qh Kh^T (1 term)
            float s[8][4] = {};
            #pragma unroll
            for (int ks = 0; ks < 8; ks++) {
                uint32_t qh[4];
                {
                    int row = wrow + (lane & 15);
                    int seg = ks * 16 + 8 * (lane >> 4);
                    ldsm4(qh, sb + (row * 136 + seg) * 2);
                }
                #pragma unroll
                for (int np = 0; np < 4; np++) {
                    uint32_t kh[4];
                    int n = np * 16 + ((lane >> 4) << 3) + (lane & 7);
                    int seg = ks * 16 + 8 * ((lane >> 3) & 1);
                    ldsm4(kh, stb + (n * 136 + seg) * 2);
                    mma16816(s[np * 2 + 0], qh, &kh[0]);
                    mma16816(s[np * 2 + 1], qh, &kh[2]);
                }
            }

            // ---- causal mask + scale (base-2)
            const int rbase = qt * 128 + wrow + (lane >> 2);
            if (kt * 64 + 63 > qt * 128 + wrow) {
                #pragma unroll
                for (int j = 0; j < 8; j++)
                    #pragma unroll
                    for (int cc = 0; cc < 4; cc++) {
                        int colg = kt * 64 + j * 8 + (lane & 3) * 2 + (cc & 1);
                        int rowg = rbase + (cc >> 1) * 8;
                        if (colg > rowg) s[j][cc] = -1e30f;
                    }
            }
            #pragma unroll
            for (int j = 0; j < 8; j++)
                #pragma unroll
                for (int cc = 0; cc < 4; cc++) s[j][cc] *= SC2_;

            // ---- online softmax (base-2)
            #pragma unroll
            for (int hr = 0; hr < 2; hr++) {
                float rm = -1e30f;
                #pragma unroll
                for (int j = 0; j < 8; j++)
                    rm = fmaxf(rm, fmaxf(s[j][hr * 2], s[j][hr * 2 + 1]));
                rm = fmaxf(rm, __shfl_xor_sync(0xffffffffu, rm, 1));
                rm = fmaxf(rm, __shfl_xor_sync(0xffffffffu, rm, 2));
                float nm  = fmaxf(m_i[hr], rm);
                float fac = exp2f(m_i[hr] - nm);
                m_i[hr] = nm;
                float rs = 0.f;
                #pragma unroll
                for (int j = 0; j < 8; j++) {
                    float p0 = exp2f(s[j][hr * 2]     - nm);
                    float p1 = exp2f(s[j][hr * 2 + 1] - nm);
                    s[j][hr * 2]     = p0;
                    s[j][hr * 2 + 1] = p1;
                    rs += p0 + p1;
                }
                rs += __shfl_xor_sync(0xffffffffu, rs, 1);
                rs += __shfl_xor_sync(0xffffffffu, rs, 2);
                l_i[hr] = l_i[hr] * fac + rs;
                #pragma unroll
                for (int nt = 0; nt < 16; nt++) {
                    acc[nt][hr * 2]     *= fac;
                    acc[nt][hr * 2 + 1] *= fac;
                }
            }

            // ---- P hi fragments (reuse S C-layout as A-layout)
            uint32_t aH[4][4];
            #pragma unroll
            for (int ks = 0; ks < 4; ks++)
                #pragma unroll
                for (int half_ = 0; half_ < 2; half_++) {
                    const float* sj = s[ks * 2 + half_];
                    aH[ks][half_ * 2 + 0] = packh2(sj[0], sj[1]);
                    aH[ks][half_ * 2 + 1] = packh2(sj[2], sj[3]);
                }

            // ---- O += P_hi · V_hi (1 term)
            #pragma unroll
            for (int ks = 0; ks < 4; ks++) {
                #pragma unroll
                for (int ntp = 0; ntp < 8; ntp++) {
                    uint32_t vh[4];
                    int kr = ks * 16 + (lane & 7) + 8 * ((lane >> 3) & 1);
                    int nc = ntp * 16 + 8 * (lane >> 4);
                    ldsm4t(vh, stb + (8704 + kr * 136 + nc) * 2);
                    mma16816(acc[ntp * 2 + 0], aH[ks], &vh[0]);
                    mma16816(acc[ntp * 2 + 1], aH[ks], &vh[2]);
                }
            }
        }
        __syncthreads();
    }

    float inv0 = 1.0f / l_i[0], inv1 = 1.0f / l_i[1];
    #pragma unroll
    for (int nt = 0; nt < 16; nt++) {
        float o0 = acc[nt][0] * inv0, o1 = acc[nt][1] * inv0;
        float o2 = acc[nt][2] * inv1, o3 = acc[nt][3] * inv1;
        size_t col = (size_t)h * D_ + nt * 8 + (lane & 3) * 2;
        size_t r0 = (size_t)(t0 + wrow + (lane >> 2)) * HID_ + col;
        size_t r1 = r0 + 8 * HID_;
        *(uint32_t*)(g_Ah + r0) = packh2(o0, o1);
        *(uint32_t*)(g_Ah + r1) = packh2(o2, o3);
    }
}

// ---------------------------------------------------------------------------
// Launch
// ---------------------------------------------------------------------------
extern "C" void kernel_launch(void* const* d_in, const int* in_sizes, int n_in,
                              void* d_out, int out_size)
{
    const float* hidden = (const float*)d_in[0];
    const float* cosT   = (const float*)d_in[1];
    const float* sinT   = (const float*)d_in[2];
    const float* w_qkv  = (const float*)d_in[3];
    const float* w_o    = (const float*)d_in[4];

    float* out = (float*)d_out;
    float* kc  = out + (size_t)T_ * HID_;
    float* vc  = kc + (size_t)T_ * HID_;

    float* qkvp = nullptr;
    __half *ahp = nullptr, *bhp = nullptr, *whp = nullptr;
    cudaGetSymbolAddress((void**)&qkvp, g_qkv);
    cudaGetSymbolAddress((void**)&ahp, g_Ah);
    cudaGetSymbolAddress((void**)&bhp, g_Bh);
    cudaGetSymbolAddress((void**)&whp, g_Wh);

    cudaFuncSetAttribute(hgemm_kernel,
                         cudaFuncAttributeMaxDynamicSharedMemorySize, G_SMEM);
    cudaFuncSetAttribute(fattn_kernel,
                         cudaFuncAttributeMaxDynamicSharedMemorySize, FA_SMEM_BYTES);

    // 1) ALL conversions in one grid (hidden, w_qkv, w_o) — hi only
    conv_all_kernel<<<NB_WQKV + NB_WO + NB_H, 256>>>(hidden, w_qkv, w_o);
    // 2) QKV GEMM (1-term fp16) -> g_qkv fp32
    hgemm_kernel<<<dim3(T_ / 128, 3 * HID_ / 128), 128, G_SMEM>>>(
        ahp, bhp, qkvp, 3 * HID_, HID_);
    // 3) RoPE + caches + fp16 attention operands
    rope_cache_kernel<<<T_ * H_ / 8, 256>>>(cosT, sinT, kc, vc);
    // 4) flash attention (fp16 MMA) -> ctx fp16 into g_Ah
    fattn_kernel<<<1024, 256, FA_SMEM_BYTES>>>();
    // 5) output projection (1-term fp16) -> out
    hgemm_kernel<<<dim3(T_ / 128, HID_ / 128), 128, G_SMEM>>>(
        ahp, whp, out, HID_, HID_);
}

// round 15
// speedup vs baseline: 2.0153x; 1.0046x over previous
#include <cuda_runtime.h>
#include <cuda_fp16.h>
#include <cstdint>
#include <cstddef>

// Problem constants
constexpr int H_   = 32;
constexpr int D_   = 128;
constexpr int HID_ = 4096;   // H*D
constexpr int B_   = 4;
constexpr int S_   = 1024;
constexpr int T_   = 4096;   // B*S
constexpr float SCALE_ = 0.08838834764831845f;  // D^-0.5
constexpr float SC2_   = 0.12752966089200528f;  // SCALE * log2(e)

// Scratch (allocation-free rule: __device__ globals)
__device__ float g_qkv[(size_t)T_ * 3 * HID_];   // [T, 3*HID]
// GEMM fp16 operands (1-term: hi only on both sides)
__device__ __half g_Ah[(size_t)T_ * HID_];       // A hi (hidden, then ctx)
__device__ __half g_Bh[(size_t)HID_ * 3 * HID_]; // w_qkv^T hi [N][K]
__device__ __half g_Wh[(size_t)HID_ * HID_];     // w_o^T hi
// Attention fp16 operands (hi only)
__device__ __half g_Qh[(size_t)T_ * HID_];
__device__ __half g_Kh[(size_t)T_ * HID_];
__device__ __half g_Vh[(size_t)T_ * HID_];

// ---------------------------------------------------------------------------
// helpers
// ---------------------------------------------------------------------------
__device__ __forceinline__ uint32_t smem_u32(const void* p) {
    uint32_t a;
    asm("{ .reg .u64 t; cvta.to.shared.u64 t, %1; cvt.u32.u64 %0, t; }"
        : "=r"(a) : "l"(p));
    return a;
}
__device__ __forceinline__ void cp16(uint32_t dst, const void* src) {
    asm volatile("cp.async.cg.shared.global [%0], [%1], 16;" :: "r"(dst), "l"(src));
}
__device__ __forceinline__ void cp_commit() { asm volatile("cp.async.commit_group;"); }
template<int Ngrp> __device__ __forceinline__ void cp_wait() {
    asm volatile("cp.async.wait_group %0;" :: "n"(Ngrp));
}
__device__ __forceinline__ void ldsm4(uint32_t* r, uint32_t addr) {
    asm volatile("ldmatrix.sync.aligned.m8n8.x4.shared.b16 {%0,%1,%2,%3}, [%4];"
                 : "=r"(r[0]), "=r"(r[1]), "=r"(r[2]), "=r"(r[3]) : "r"(addr));
}
__device__ __forceinline__ void ldsm4t(uint32_t* r, uint32_t addr) {
    asm volatile("ldmatrix.sync.aligned.m8n8.x4.trans.shared.b16 {%0,%1,%2,%3}, [%4];"
                 : "=r"(r[0]), "=r"(r[1]), "=r"(r[2]), "=r"(r[3]) : "r"(addr));
}
__device__ __forceinline__ void mma16816(float* c, const uint32_t* a, const uint32_t* b) {
    asm volatile("mma.sync.aligned.m16n8k16.row.col.f32.f16.f16.f32 "
                 "{%0,%1,%2,%3}, {%4,%5,%6,%7}, {%8,%9}, {%0,%1,%2,%3};"
                 : "+f"(c[0]), "+f"(c[1]), "+f"(c[2]), "+f"(c[3])
                 : "r"(a[0]), "r"(a[1]), "r"(a[2]), "r"(a[3]), "r"(b[0]), "r"(b[1]));
}
__device__ __forceinline__ uint32_t packh2(float x, float y) {
    __half2 p = __halves2half2(__float2half_rn(x), __float2half_rn(y));
    return *(uint32_t*)&p;
}

// ---------------------------------------------------------------------------
// conv_all: one grid for all conversions (hi-only everywhere).
// ---------------------------------------------------------------------------
constexpr int NB_WQKV = (HID_ / 32) * (3 * HID_ / 64);      // 24576
constexpr int NB_WO   = (HID_ / 32) * (HID_ / 64);          // 8192
constexpr int NB_H    = (int)((size_t)T_ * HID_ / 8 / 256); // 8192

__device__ __forceinline__ void convT_body(const float* __restrict__ w,
                                           __half* __restrict__ hi,
                                           int K, int N, int bk, int bn,
                                           float (*t)[65])
{
    const int k0 = bk * 32, n0 = bn * 64;
    const int tx = threadIdx.x & 63, ty = threadIdx.x >> 6;
    #pragma unroll
    for (int i = 0; i < 32; i += 4)
        t[ty + i][tx] = w[(size_t)(k0 + ty + i) * N + n0 + tx];
    __syncthreads();

    const int nl = threadIdx.x >> 2;
    const int kg = threadIdx.x & 3;
    float x[8];
    #pragma unroll
    for (int j = 0; j < 8; j++) x[j] = t[kg * 8 + j][nl];   // conflict-free
    uint4 uh;
    uint32_t* ph = (uint32_t*)&uh;
    #pragma unroll
    for (int j = 0; j < 4; j++) ph[j] = packh2(x[2*j], x[2*j+1]);
    *(uint4*)(hi + (size_t)(n0 + nl) * K + k0 + kg * 8) = uh;
}

__global__ __launch_bounds__(256)
void conv_all_kernel(const float* __restrict__ hidden,
                     const float* __restrict__ w_qkv,
                     const float* __restrict__ w_o)
{
    __shared__ float t[32][65];
    const int bid = blockIdx.x;
    if (bid < NB_WQKV) {
        convT_body(w_qkv, g_Bh, HID_, 3 * HID_, bid & 127, bid >> 7, t);
    } else if (bid < NB_WQKV + NB_WO) {
        const int b2 = bid - NB_WQKV;
        convT_body(w_o, g_Wh, HID_, HID_, b2 & 127, b2 >> 7, t);
    } else {
        const int b2 = bid - NB_WQKV - NB_WO;
        size_t base = ((size_t)b2 * 256 + threadIdx.x) * 8;
        const float4* s = (const float4*)(hidden + base);
        float4 a = s[0], b = s[1];
        float x[8] = {a.x, a.y, a.z, a.w, b.x, b.y, b.z, b.w};
        uint4 uh;
        uint32_t* ph = (uint32_t*)&uh;
        #pragma unroll
        for (int j = 0; j < 4; j++) ph[j] = packh2(x[2*j], x[2*j+1]);
        *(uint4*)(g_Ah + base) = uh;
    }
}

// ---------------------------------------------------------------------------
// Persistent HGEMM: 1-term fp16 (ah*bh), fp32 accum. 128x128 tile, BK=32,
// 4-stage cp.async, 128 threads (2x2 warps, 64x64 warp tile), 2 CTAs/SM.
// Each CTA loops tile += gridDim.x (bm-fastest order for L2 B-reuse).
// Inter-tile smem safety: last stage read is (KT-1)&3=3; pre-sync prefetches
// of the next tile write stages 0..2 only; stage 3 rewritten after in-loop sync.
// ---------------------------------------------------------------------------
constexpr int G_STAGE = 16384;
constexpr int G_SMEM  = 4 * G_STAGE;      // 64 KB

__global__ __launch_bounds__(128, 2)
void hgemm_kernel(const __half* __restrict__ Ah, const __half* __restrict__ Bh,
                  float* __restrict__ C, int N, int K, int Mtiles, int numTiles)
{
    extern __shared__ char sm[];
    const int tid  = threadIdx.x;
    const int wid  = tid >> 5, lane = tid & 31;
    const int wm = (wid >> 1) * 64;
    const int wn = (wid & 1) * 64;
    const int KT = K / 32;
    const uint32_t sb = smem_u32(sm);

    for (int tile = blockIdx.x; tile < numTiles; tile += gridDim.x) {
        const int bm = tile % Mtiles;
        const int bn = tile / Mtiles;
        const __half* aop = Ah + (size_t)bm * 128 * K;
        const __half* bop = Bh + (size_t)bn * 128 * K;

        auto prefetch = [&](int kt) {
            const uint32_t st = sb + (kt & 3) * G_STAGE;
            #pragma unroll
            for (int op = 0; op < 2; op++) {
                const __half* src = (op == 0) ? aop : bop;
                #pragma unroll
                for (int h4 = 0; h4 < 4; h4++) {
                    int ch = h4 * 128 + tid;
                    int row = ch >> 2, c = ch & 3;
                    cp16(st + op * 8192 + row * 64 + ((c ^ (row & 3)) << 4),
                         src + (size_t)row * K + kt * 32 + c * 8);
                }
            }
            cp_commit();
        };

        prefetch(0);
        prefetch(1);
        prefetch(2);

        float acc[4][8][4] = {};

        for (int kt = 0; kt < KT; kt++) {
            if (kt + 2 < KT)      cp_wait<2>();
            else if (kt + 1 < KT) cp_wait<1>();
            else                  cp_wait<0>();
            __syncthreads();
            if (kt + 3 < KT) prefetch(kt + 3);

            const uint32_t st = sb + (kt & 3) * G_STAGE;
            #pragma unroll
            for (int ks = 0; ks < 2; ks++) {
                uint32_t ahf[4][4], bhf[4][4];
                #pragma unroll
                for (int mt = 0; mt < 4; mt++) {
                    int row = wm + mt * 16 + (lane & 15);
                    int c   = ks * 2 + (lane >> 4);
                    ldsm4(ahf[mt], st + row * 64 + ((c ^ (row & 3)) << 4));
                }
                #pragma unroll
                for (int p = 0; p < 4; p++) {
                    int n = wn + p * 16 + ((lane >> 4) << 3) + (lane & 7);
                    int c = ks * 2 + ((lane >> 3) & 1);
                    ldsm4(bhf[p], st + 8192 + n * 64 + ((c ^ (n & 3)) << 4));
                }
                #pragma unroll
                for (int mt = 0; mt < 4; mt++)
                    #pragma unroll
                    for (int nt = 0; nt < 8; nt++)
                        mma16816(acc[mt][nt], ahf[mt], &bhf[nt >> 1][(nt & 1) * 2]);
            }
        }

        #pragma unroll
        for (int mt = 0; mt < 4; mt++)
            #pragma unroll
            for (int nt = 0; nt < 8; nt++) {
                int r0  = bm * 128 + wm + mt * 16 + (lane >> 2);
                int col = bn * 128 + wn + nt * 8 + (lane & 3) * 2;
                *(float2*)(C + (size_t)r0 * N + col) =
                    make_float2(acc[mt][nt][0], acc[mt][nt][1]);
                *(float2*)(C + (size_t)(r0 + 8) * N + col) =
                    make_float2(acc[mt][nt][2], acc[mt][nt][3]);
            }
    }
}

// ---------------------------------------------------------------------------
// RoPE + cache scatter + fp16 hi emit. Warp per (t,h); 256-thread blocks.
// ---------------------------------------------------------------------------
__global__ __launch_bounds__(256)
void rope_cache_kernel(const float* __restrict__ cosT,
                       const float* __restrict__ sinT,
                       float* __restrict__ kc,
                       float* __restrict__ vc)
{
    const int gw = blockIdx.x * 8 + (threadIdx.x >> 5);   // (t,h) index
    const int t = gw >> 5;
    const int h = gw & 31;
    const int lane = threadIdx.x & 31;

    const float2 c2 = *(const float2*)(cosT + t * 64 + 2 * lane);
    const float2 s2 = *(const float2*)(sinT + t * 64 + 2 * lane);

    const size_t base = (size_t)t * 3 * HID_ + h * D_ + 4 * lane;
    const size_t co   = (size_t)t * HID_ + h * D_ + 4 * lane;

    {
        float4 q = *(const float4*)(g_qkv + base);
        float a0 = q.x * c2.x - q.y * s2.x, a1 = q.y * c2.x + q.x * s2.x;
        float a2 = q.z * c2.y - q.w * s2.y, a3 = q.w * c2.y + q.z * s2.y;
        *(uint2*)(g_Qh + co) = make_uint2(packh2(a0, a1), packh2(a2, a3));
    }
    {
        float4 k = *(const float4*)(g_qkv + base + HID_);
        float b0 = k.x * c2.x - k.y * s2.x, b1 = k.y * c2.x + k.x * s2.x;
        float b2 = k.z * c2.y - k.w * s2.y, b3 = k.w * c2.y + k.z * s2.y;
        *(float4*)(kc + co) = make_float4(b0, b1, b2, b3);
        *(uint2*)(g_Kh + co) = make_uint2(packh2(b0, b1), packh2(b2, b3));
    }
    {
        float4 v = *(const float4*)(g_qkv + base + 2 * HID_);
        *(float4*)(vc + co) = v;
        *(uint2*)(g_Vh + co) = make_uint2(packh2(v.x, v.y), packh2(v.z, v.w));
    }
}

// ---------------------------------------------------------------------------
// Flash attention, pure fp16 MMA (1-term S, 1-term PV), fp32 accum + softmax.
// ---------------------------------------------------------------------------
constexpr int FA_ST = 17408;                      // stage stride in halfs
constexpr int FA_SMEM_BYTES = (17408 + 2 * 17408) * 2;   // 104448

__global__ __launch_bounds__(256, 2)
void fattn_kernel()
{
    extern __shared__ __half fsm[];
    const int tid = threadIdx.x;
    const int wid = tid >> 5, lane = tid & 31;
    const int bid = blockIdx.x;
    const int qt = 7 - (bid >> 7);            // heavy tiles first, globally
    const int h = bid & 31;
    const int b = (bid >> 5) & 3;
    const int t0 = b * S_ + qt * 128;
    const int wrow = wid * 16;
    const uint32_t sb = smem_u32(fsm);

    #pragma unroll
    for (int j = 0; j < 8; j++) {
        int ch = j * 256 + tid;
        int r = ch >> 4, c = ch & 15;
        cp16(sb + (r * 136 + c * 8) * 2,
             g_Qh + (size_t)(t0 + r) * HID_ + h * D_ + c * 8);
    }

    auto kvload = [&](int kt) {
        const uint32_t dstb = sb + (FA_ST + (kt & 1) * FA_ST) * 2;
        const int tk0 = b * S_ + kt * 64;
        const __half* srcs[2] = {g_Kh, g_Vh};
        #pragma unroll
        for (int a = 0; a < 2; a++)
            #pragma unroll
            for (int j = 0; j < 4; j++) {
                int ch = j * 256 + tid;
                int r = ch >> 4, c = ch & 15;
                cp16(dstb + (a * 8704 + r * 136 + c * 8) * 2,
                     srcs[a] + (size_t)(tk0 + r) * HID_ + h * D_ + c * 8);
            }
        cp_commit();
    };

    const int ktmax = 2 * qt + 1;
    kvload(0);

    float acc[16][4] = {};
    float m_i[2] = {-1e30f, -1e30f};
    float l_i[2] = {0.f, 0.f};

    for (int kt = 0; kt <= ktmax; kt++) {
        if (kt + 1 <= ktmax) { kvload(kt + 1); cp_wait<1>(); }
        else cp_wait<0>();
        __syncthreads();

        const uint32_t stb = sb + (FA_ST + (kt & 1) * FA_ST) * 2;
        const bool active = (kt * 64 <= qt * 128 + wrow + 15);

        if (active) {
            float s[8][4] = {};
            #pragma unroll
            for (int ks = 0; ks < 8; ks++) {
                uint32_t qh[4];
                {
                    int row = wrow + (lane & 15);
                    int seg = ks * 16 + 8 * (lane >> 4);
                    ldsm4(qh, sb + (row * 136 + seg) * 2);
                }
                #pragma unroll
                for (int np = 0; np < 4; np++) {
                    uint32_t kh[4];
                    int n = np * 16 + ((lane >> 4) << 3) + (lane & 7);
                    int seg = ks * 16 + 8 * ((lane >> 3) & 1);
                    ldsm4(kh, stb + (n * 136 + seg) * 2);
                    mma16816(s[np * 2 + 0], qh, &kh[0]);
                    mma16816(s[np * 2 + 1], qh, &kh[2]);
                }
            }

            const int rbase = qt * 128 + wrow + (lane >> 2);
            if (kt * 64 + 63 > qt * 128 + wrow) {
                #pragma unroll
                for (int j = 0; j < 8; j++)
                    #pragma unroll
                    for (int cc = 0; cc < 4; cc++) {
                        int colg = kt * 64 + j * 8 + (lane & 3) * 2 + (cc & 1);
                        int rowg = rbase + (cc >> 1) * 8;
                        if (colg > rowg) s[j][cc] = -1e30f;
                    }
            }
            #pragma unroll
            for (int j = 0; j < 8; j++)
                #pragma unroll
                for (int cc = 0; cc < 4; cc++) s[j][cc] *= SC2_;

            #pragma unroll
            for (int hr = 0; hr < 2; hr++) {
                float rm = -1e30f;
                #pragma unroll
                for (int j = 0; j < 8; j++)
                    rm = fmaxf(rm, fmaxf(s[j][hr * 2], s[j][hr * 2 + 1]));
                rm = fmaxf(rm, __shfl_xor_sync(0xffffffffu, rm, 1));
                rm = fmaxf(rm, __shfl_xor_sync(0xffffffffu, rm, 2));
                float nm  = fmaxf(m_i[hr], rm);
                float fac = exp2f(m_i[hr] - nm);
                m_i[hr] = nm;
                float rs = 0.f;
                #pragma unroll
                for (int j = 0; j < 8; j++) {
                    float p0 = exp2f(s[j][hr * 2]     - nm);
                    float p1 = exp2f(s[j][hr * 2 + 1] - nm);
                    s[j][hr * 2]     = p0;
                    s[j][hr * 2 + 1] = p1;
                    rs += p0 + p1;
                }
                rs += __shfl_xor_sync(0xffffffffu, rs, 1);
                rs += __shfl_xor_sync(0xffffffffu, rs, 2);
                l_i[hr] = l_i[hr] * fac + rs;
                #pragma unroll
                for (int nt = 0; nt < 16; nt++) {
                    acc[nt][hr * 2]     *= fac;
                    acc[nt][hr * 2 + 1] *= fac;
                }
            }

            uint32_t aH[4][4];
            #pragma unroll
            for (int ks = 0; ks < 4; ks++)
                #pragma unroll
                for (int half_ = 0; half_ < 2; half_++) {
                    const float* sj = s[ks * 2 + half_];
                    aH[ks][half_ * 2 + 0] = packh2(sj[0], sj[1]);
                    aH[ks][half_ * 2 + 1] = packh2(sj[2], sj[3]);
                }

            #pragma unroll
            for (int ks = 0; ks < 4; ks++) {
                #pragma unroll
                for (int ntp = 0; ntp < 8; ntp++) {
                    uint32_t vh[4];
                    int kr = ks * 16 + (lane & 7) + 8 * ((lane >> 3) & 1);
                    int nc = ntp * 16 + 8 * (lane >> 4);
                    ldsm4t(vh, stb + (8704 + kr * 136 + nc) * 2);
                    mma16816(acc[ntp * 2 + 0], aH[ks], &vh[0]);
                    mma16816(acc[ntp * 2 + 1], aH[ks], &vh[2]);
                }
            }
        }
        __syncthreads();
    }

    float inv0 = 1.0f / l_i[0], inv1 = 1.0f / l_i[1];
    #pragma unroll
    for (int nt = 0; nt < 16; nt++) {
        float o0 = acc[nt][0] * inv0, o1 = acc[nt][1] * inv0;
        float o2 = acc[nt][2] * inv1, o3 = acc[nt][3] * inv1;
        size_t col = (size_t)h * D_ + nt * 8 + (lane & 3) * 2;
        size_t r0 = (size_t)(t0 + wrow + (lane >> 2)) * HID_ + col;
        size_t r1 = r0 + 8 * HID_;
        *(uint32_t*)(g_Ah + r0) = packh2(o0, o1);
        *(uint32_t*)(g_Ah + r1) = packh2(o2, o3);
    }
}

// ---------------------------------------------------------------------------
// Launch
// ---------------------------------------------------------------------------
extern "C" void kernel_launch(void* const* d_in, const int* in_sizes, int n_in,
                              void* d_out, int out_size)
{
    const float* hidden = (const float*)d_in[0];
    const float* cosT   = (const float*)d_in[1];
    const float* sinT   = (const float*)d_in[2];
    const float* w_qkv  = (const float*)d_in[3];
    const float* w_o    = (const float*)d_in[4];

    float* out = (float*)d_out;
    float* kc  = out + (size_t)T_ * HID_;
    float* vc  = kc + (size_t)T_ * HID_;

    float* qkvp = nullptr;
    __half *ahp = nullptr, *bhp = nullptr, *whp = nullptr;
    cudaGetSymbolAddress((void**)&qkvp, g_qkv);
    cudaGetSymbolAddress((void**)&ahp, g_Ah);
    cudaGetSymbolAddress((void**)&bhp, g_Bh);
    cudaGetSymbolAddress((void**)&whp, g_Wh);

    int smCount = 148;
    cudaDeviceGetAttribute(&smCount, cudaDevAttrMultiProcessorCount, 0);
    const int pgrid = 2 * smCount;

    cudaFuncSetAttribute(hgemm_kernel,
                         cudaFuncAttributeMaxDynamicSharedMemorySize, G_SMEM);
    cudaFuncSetAttribute(fattn_kernel,
                         cudaFuncAttributeMaxDynamicSharedMemorySize, FA_SMEM_BYTES);

    // 1) ALL conversions in one grid (hidden, w_qkv, w_o) — hi only
    conv_all_kernel<<<NB_WQKV + NB_WO + NB_H, 256>>>(hidden, w_qkv, w_o);
    // 2) QKV GEMM (persistent) -> g_qkv fp32
    hgemm_kernel<<<pgrid, 128, G_SMEM>>>(ahp, bhp, qkvp, 3 * HID_, HID_,
                                         T_ / 128, (T_ / 128) * (3 * HID_ / 128));
    // 3) RoPE + caches + fp16 attention operands
    rope_cache_kernel<<<T_ * H_ / 8, 256>>>(cosT, sinT, kc, vc);
    // 4) flash attention (fp16 MMA) -> ctx fp16 into g_Ah
    fattn_kernel<<<1024, 256, FA_SMEM_BYTES>>>();
    // 5) output projection (persistent) -> out
    hgemm_kernel<<<pgrid, 128, G_SMEM>>>(ahp, whp, out, HID_, HID_,
                                         T_ / 128, (T_ / 128) * (HID_ / 128));
}

// round 16
// speedup vs baseline: 2.0900x; 1.0371x over previous
#include <cuda_runtime.h>
#include <cuda_fp16.h>
#include <cstdint>
#include <cstddef>

// Problem constants
constexpr int H_   = 32;
constexpr int D_   = 128;
constexpr int HID_ = 4096;   // H*D
constexpr int B_   = 4;
constexpr int S_   = 1024;
constexpr int T_   = 4096;   // B*S
constexpr float SC2_   = 0.12752966089200528f;  // SCALE * log2(e)

// Scratch (allocation-free rule: __device__ globals)
__device__ float g_qkv[(size_t)T_ * 3 * HID_];   // [T, 3*HID]
__device__ __half g_Ah[(size_t)T_ * HID_];       // A hi (hidden, then ctx)
__device__ __half g_Bh[(size_t)HID_ * 3 * HID_]; // w_qkv^T hi [N][K]
__device__ __half g_Wh[(size_t)HID_ * HID_];     // w_o^T hi
__device__ __half g_Qh[(size_t)T_ * HID_];
__device__ __half g_Kh[(size_t)T_ * HID_];
__device__ __half g_Vh[(size_t)T_ * HID_];

// ---------------------------------------------------------------------------
// helpers
// ---------------------------------------------------------------------------
__device__ __forceinline__ uint32_t smem_u32(const void* p) {
    uint32_t a;
    asm("{ .reg .u64 t; cvta.to.shared.u64 t, %1; cvt.u32.u64 %0, t; }"
        : "=r"(a) : "l"(p));
    return a;
}
__device__ __forceinline__ void cp16(uint32_t dst, const void* src) {
    asm volatile("cp.async.cg.shared.global [%0], [%1], 16;" :: "r"(dst), "l"(src));
}
__device__ __forceinline__ void cp_commit() { asm volatile("cp.async.commit_group;"); }
template<int Ngrp> __device__ __forceinline__ void cp_wait() {
    asm volatile("cp.async.wait_group %0;" :: "n"(Ngrp));
}
__device__ __forceinline__ void ldsm4(uint32_t* r, uint32_t addr) {
    asm volatile("ldmatrix.sync.aligned.m8n8.x4.shared.b16 {%0,%1,%2,%3}, [%4];"
                 : "=r"(r[0]), "=r"(r[1]), "=r"(r[2]), "=r"(r[3]) : "r"(addr));
}
__device__ __forceinline__ void ldsm4t(uint32_t* r, uint32_t addr) {
    asm volatile("ldmatrix.sync.aligned.m8n8.x4.trans.shared.b16 {%0,%1,%2,%3}, [%4];"
                 : "=r"(r[0]), "=r"(r[1]), "=r"(r[2]), "=r"(r[3]) : "r"(addr));
}
__device__ __forceinline__ void mma16816(float* c, const uint32_t* a, const uint32_t* b) {
    asm volatile("mma.sync.aligned.m16n8k16.row.col.f32.f16.f16.f32 "
                 "{%0,%1,%2,%3}, {%4,%5,%6,%7}, {%8,%9}, {%0,%1,%2,%3};"
                 : "+f"(c[0]), "+f"(c[1]), "+f"(c[2]), "+f"(c[3])
                 : "r"(a[0]), "r"(a[1]), "r"(a[2]), "r"(a[3]), "r"(b[0]), "r"(b[1]));
}
__device__ __forceinline__ uint32_t packh2(float x, float y) {
    __half2 p = __halves2half2(__float2half_rn(x), __float2half_rn(y));
    return *(uint32_t*)&p;
}

// ---------------------------------------------------------------------------
// convT body (32k x 64n tile) — shared by conv_all and fattn-merged w_o conv.
// ---------------------------------------------------------------------------
__device__ __forceinline__ void convT_body(const float* __restrict__ w,
                                           __half* __restrict__ hi,
                                           int K, int N, int bk, int bn,
                                           float (*t)[65])
{
    const int k0 = bk * 32, n0 = bn * 64;
    const int tx = threadIdx.x & 63, ty = threadIdx.x >> 6;
    #pragma unroll
    for (int i = 0; i < 32; i += 4)
        t[ty + i][tx] = w[(size_t)(k0 + ty + i) * N + n0 + tx];
    __syncthreads();

    const int nl = threadIdx.x >> 2;
    const int kg = threadIdx.x & 3;
    float x[8];
    #pragma unroll
    for (int j = 0; j < 8; j++) x[j] = t[kg * 8 + j][nl];   // conflict-free
    uint4 uh;
    uint32_t* ph = (uint32_t*)&uh;
    #pragma unroll
    for (int j = 0; j < 4; j++) ph[j] = packh2(x[2*j], x[2*j+1]);
    *(uint4*)(hi + (size_t)(n0 + nl) * K + k0 + kg * 8) = uh;
}

// conv_all: w_qkv transpose + hidden convert (w_o handled inside fattn grid)
constexpr int NB_WQKV = (HID_ / 32) * (3 * HID_ / 64);      // 24576
constexpr int NB_H    = (int)((size_t)T_ * HID_ / 8 / 256); // 8192

__global__ __launch_bounds__(256)
void conv_all_kernel(const float* __restrict__ hidden,
                     const float* __restrict__ w_qkv)
{
    __shared__ float t[32][65];
    const int bid = blockIdx.x;
    if (bid < NB_WQKV) {
        convT_body(w_qkv, g_Bh, HID_, 3 * HID_, bid & 127, bid >> 7, t);
    } else {
        const int b2 = bid - NB_WQKV;
        size_t base = ((size_t)b2 * 256 + threadIdx.x) * 8;
        const float4* s = (const float4*)(hidden + base);
        float4 a = s[0], b = s[1];
        float x[8] = {a.x, a.y, a.z, a.w, b.x, b.y, b.z, b.w};
        uint4 uh;
        uint32_t* ph = (uint32_t*)&uh;
        #pragma unroll
        for (int j = 0; j < 4; j++) ph[j] = packh2(x[2*j], x[2*j+1]);
        *(uint4*)(g_Ah + base) = uh;
    }
}

// ---------------------------------------------------------------------------
// Persistent HGEMM: 1-term fp16 (ah*bh), fp32 accum. 128x128 tile, BK=64,
// 3-stage cp.async (32 KB/stage, 96 KB total, 2 CTAs/SM), 128 threads
// (2x2 warps, 64x64 warp tile). One sync per BK=64 stage (64/tile).
// MMA k-order identical to BK=32 version -> bit-identical results.
// ---------------------------------------------------------------------------
constexpr int G_STAGE = 32768;            // A 16K | B 16K
constexpr int G_SMEM  = 3 * G_STAGE;      // 96 KB

__global__ __launch_bounds__(128, 2)
void hgemm_kernel(const __half* __restrict__ Ah, const __half* __restrict__ Bh,
                  float* __restrict__ C, int N, int K, int Mtiles, int numTiles)
{
    extern __shared__ char sm[];
    const int tid  = threadIdx.x;
    const int wid  = tid >> 5, lane = tid & 31;
    const int wm = (wid >> 1) * 64;
    const int wn = (wid & 1) * 64;
    const int KT = K / 64;
    const uint32_t sb = smem_u32(sm);

    for (int tile = blockIdx.x; tile < numTiles; tile += gridDim.x) {
        const int bm = tile % Mtiles;
        const int bn = tile / Mtiles;
        const __half* aop = Ah + (size_t)bm * 128 * K;
        const __half* bop = Bh + (size_t)bn * 128 * K;

        // 16 cp16 per thread per BK=64 stage (A 8 + B 8)
        auto prefetch = [&](int kt) {
            const uint32_t st = sb + (kt % 3) * G_STAGE;
            #pragma unroll
            for (int op = 0; op < 2; op++) {
                const __half* src = (op == 0) ? aop : bop;
                #pragma unroll
                for (int h8 = 0; h8 < 8; h8++) {
                    int ch = h8 * 128 + tid;
                    int row = ch >> 3, c = ch & 7;
                    cp16(st + op * 16384 + row * 128 + ((c ^ (row & 7)) << 4),
                         src + (size_t)row * K + kt * 64 + c * 8);
                }
            }
            cp_commit();
        };

        prefetch(0);
        prefetch(1);

        float acc[4][8][4] = {};

        for (int kt = 0; kt < KT; kt++) {
            if (kt + 1 < KT) cp_wait<1>(); else cp_wait<0>();
            __syncthreads();                   // stage kt visible; kt-1 reads done
            if (kt + 2 < KT) prefetch(kt + 2);

            const uint32_t st = sb + (kt % 3) * G_STAGE;
            #pragma unroll
            for (int ks = 0; ks < 4; ks++) {   // four k16 steps per BK=64
                uint32_t ahf[4][4], bhf[4][4];
                #pragma unroll
                for (int mt = 0; mt < 4; mt++) {
                    int row = wm + mt * 16 + (lane & 15);
                    int c   = ks * 2 + (lane >> 4);
                    ldsm4(ahf[mt], st + row * 128 + ((c ^ (row & 7)) << 4));
                }
                #pragma unroll
                for (int p = 0; p < 4; p++) {
                    int n = wn + p * 16 + ((lane >> 4) << 3) + (lane & 7);
                    int c = ks * 2 + ((lane >> 3) & 1);
                    ldsm4(bhf[p], st + 16384 + n * 128 + ((c ^ (n & 7)) << 4));
                }
                #pragma unroll
                for (int mt = 0; mt < 4; mt++)
                    #pragma unroll
                    for (int nt = 0; nt < 8; nt++)
                        mma16816(acc[mt][nt], ahf[mt], &bhf[nt >> 1][(nt & 1) * 2]);
            }
        }

        #pragma unroll
        for (int mt = 0; mt < 4; mt++)
            #pragma unroll
            for (int nt = 0; nt < 8; nt++) {
                int r0  = bm * 128 + wm + mt * 16 + (lane >> 2);
                int col = bn * 128 + wn + nt * 8 + (lane & 3) * 2;
                *(float2*)(C + (size_t)r0 * N + col) =
                    make_float2(acc[mt][nt][0], acc[mt][nt][1]);
                *(float2*)(C + (size_t)(r0 + 8) * N + col) =
                    make_float2(acc[mt][nt][2], acc[mt][nt][3]);
            }
    }
}

// ---------------------------------------------------------------------------
// RoPE + cache scatter + fp16 hi emit. Warp per (t,h); 256-thread blocks.
// ---------------------------------------------------------------------------
__global__ __launch_bounds__(256)
void rope_cache_kernel(const float* __restrict__ cosT,
                       const float* __restrict__ sinT,
                       float* __restrict__ kc,
                       float* __restrict__ vc)
{
    const int gw = blockIdx.x * 8 + (threadIdx.x >> 5);
    const int t = gw >> 5;
    const int h = gw & 31;
    const int lane = threadIdx.x & 31;

    const float2 c2 = *(const float2*)(cosT + t * 64 + 2 * lane);
    const float2 s2 = *(const float2*)(sinT + t * 64 + 2 * lane);

    const size_t base = (size_t)t * 3 * HID_ + h * D_ + 4 * lane;
    const size_t co   = (size_t)t * HID_ + h * D_ + 4 * lane;

    {
        float4 q = *(const float4*)(g_qkv + base);
        float a0 = q.x * c2.x - q.y * s2.x, a1 = q.y * c2.x + q.x * s2.x;
        float a2 = q.z * c2.y - q.w * s2.y, a3 = q.w * c2.y + q.z * s2.y;
        *(uint2*)(g_Qh + co) = make_uint2(packh2(a0, a1), packh2(a2, a3));
    }
    {
        float4 k = *(const float4*)(g_qkv + base + HID_);
        float b0 = k.x * c2.x - k.y * s2.x, b1 = k.y * c2.x + k.x * s2.x;
        float b2 = k.z * c2.y - k.w * s2.y, b3 = k.w * c2.y + k.z * s2.y;
        *(float4*)(kc + co) = make_float4(b0, b1, b2, b3);
        *(uint2*)(g_Kh + co) = make_uint2(packh2(b0, b1), packh2(b2, b3));
    }
    {
        float4 v = *(const float4*)(g_qkv + base + 2 * HID_);
        *(float4*)(vc + co) = v;
        *(uint2*)(g_Vh + co) = make_uint2(packh2(v.x, v.y), packh2(v.z, v.w));
    }
}

// ---------------------------------------------------------------------------
// Flash attention (blocks [0,1024)) + merged w_o conversion (blocks >= 1024).
// fp16 MMA (1-term S, 1-term PV), fp32 accum + softmax, 1 sync/iter.
// ---------------------------------------------------------------------------
constexpr int FA_ST = 17408;                      // stage stride in halfs
constexpr int FA_SMEM_BYTES = (17408 + 2 * 17408) * 2;   // 104448
constexpr int FA_ATTN_BLOCKS = 1024;
constexpr int NB_WO_TILES = (HID_ / 32) * (HID_ / 64);   // 8192
constexpr int WO_TILES_PER_BLK = 16;
constexpr int FA_CONV_BLOCKS = NB_WO_TILES / WO_TILES_PER_BLK;   // 512

__global__ __launch_bounds__(256, 2)
void fattn_kernel(const float* __restrict__ w_o)
{
    extern __shared__ __half fsm[];
    const int bid = blockIdx.x;

    if (bid >= FA_ATTN_BLOCKS) {
        // ---- merged w_o transpose-convert (uses dynamic smem as scratch)
        float (*t)[65] = reinterpret_cast<float(*)[65]>(fsm);
        const int b2 = bid - FA_ATTN_BLOCKS;
        #pragma unroll 1
        for (int it = 0; it < WO_TILES_PER_BLK; it++) {
            int idx = b2 * WO_TILES_PER_BLK + it;
            convT_body(w_o, g_Wh, HID_, HID_, idx & 127, idx >> 7, t);
            __syncthreads();   // protect smem reuse across iterations
        }
        return;
    }

    const int tid = threadIdx.x;
    const int wid = tid >> 5, lane = tid & 31;
    const int qt = 7 - (bid >> 7);            // heavy tiles first
    const int h = bid & 31;
    const int b = (bid >> 5) & 3;
    const int t0 = b * S_ + qt * 128;
    const int wrow = wid * 16;
    const uint32_t sb = smem_u32(fsm);

    #pragma unroll
    for (int j = 0; j < 8; j++) {
        int ch = j * 256 + tid;
        int r = ch >> 4, c = ch & 15;
        cp16(sb + (r * 136 + c * 8) * 2,
             g_Qh + (size_t)(t0 + r) * HID_ + h * D_ + c * 8);
    }

    auto kvload = [&](int kt) {
        const uint32_t dstb = sb + (FA_ST + (kt & 1) * FA_ST) * 2;
        const int tk0 = b * S_ + kt * 64;
        const __half* srcs[2] = {g_Kh, g_Vh};
        #pragma unroll
        for (int a = 0; a < 2; a++)
            #pragma unroll
            for (int j = 0; j < 4; j++) {
                int ch = j * 256 + tid;
                int r = ch >> 4, c = ch & 15;
                cp16(dstb + (a * 8704 + r * 136 + c * 8) * 2,
                     srcs[a] + (size_t)(tk0 + r) * HID_ + h * D_ + c * 8);
            }
        cp_commit();
    };

    const int ktmax = 2 * qt + 1;
    kvload(0);

    float acc[16][4] = {};
    float m_i[2] = {-1e30f, -1e30f};
    float l_i[2] = {0.f, 0.f};

    for (int kt = 0; kt <= ktmax; kt++) {
        cp_wait<0>();
        __syncthreads();                   // stage kt visible; kt-1 reads done
        if (kt + 1 <= ktmax) kvload(kt + 1);

        const uint32_t stb = sb + (FA_ST + (kt & 1) * FA_ST) * 2;
        const bool active = (kt * 64 <= qt * 128 + wrow + 15);

        if (active) {
            float s[8][4] = {};
            #pragma unroll
            for (int ks = 0; ks < 8; ks++) {
                uint32_t qh[4];
                {
                    int row = wrow + (lane & 15);
                    int seg = ks * 16 + 8 * (lane >> 4);
                    ldsm4(qh, sb + (row * 136 + seg) * 2);
                }
                #pragma unroll
                for (int np = 0; np < 4; np++) {
                    uint32_t kh[4];
                    int n = np * 16 + ((lane >> 4) << 3) + (lane & 7);
                    int seg = ks * 16 + 8 * ((lane >> 3) & 1);
                    ldsm4(kh, stb + (n * 136 + seg) * 2);
                    mma16816(s[np * 2 + 0], qh, &kh[0]);
                    mma16816(s[np * 2 + 1], qh, &kh[2]);
                }
            }

            const int rbase = qt * 128 + wrow + (lane >> 2);
            if (kt * 64 + 63 > qt * 128 + wrow) {
                #pragma unroll
                for (int j = 0; j < 8; j++)
                    #pragma unroll
                    for (int cc = 0; cc < 4; cc++) {
                        int colg = kt * 64 + j * 8 + (lane & 3) * 2 + (cc & 1);
                        int rowg = rbase + (cc >> 1) * 8;
                        if (colg > rowg) s[j][cc] = -1e30f;
                    }
            }
            #pragma unroll
            for (int j = 0; j < 8; j++)
                #pragma unroll
                for (int cc = 0; cc < 4; cc++) s[j][cc] *= SC2_;

            #pragma unroll
            for (int hr = 0; hr < 2; hr++) {
                float rm = -1e30f;
                #pragma unroll
                for (int j = 0; j < 8; j++)
                    rm = fmaxf(rm, fmaxf(s[j][hr * 2], s[j][hr * 2 + 1]));
                rm = fmaxf(rm, __shfl_xor_sync(0xffffffffu, rm, 1));
                rm = fmaxf(rm, __shfl_xor_sync(0xffffffffu, rm, 2));
                float nm  = fmaxf(m_i[hr], rm);
                float fac = exp2f(m_i[hr] - nm);
                m_i[hr] = nm;
                float rs = 0.f;
                #pragma unroll
                for (int j = 0; j < 8; j++) {
                    float p0 = exp2f(s[j][hr * 2]     - nm);
                    float p1 = exp2f(s[j][hr * 2 + 1] - nm);
                    s[j][hr * 2]     = p0;
                    s[j][hr * 2 + 1] = p1;
                    rs += p0 + p1;
                }
                rs += __shfl_xor_sync(0xffffffffu, rs, 1);
                rs += __shfl_xor_sync(0xffffffffu, rs, 2);
                l_i[hr] = l_i[hr] * fac + rs;
                #pragma unroll
                for (int nt = 0; nt < 16; nt++) {
                    acc[nt][hr * 2]     *= fac;
                    acc[nt][hr * 2 + 1] *= fac;
                }
            }

            uint32_t aH[4][4];
            #pragma unroll
            for (int ks = 0; ks < 4; ks++)
                #pragma unroll
                for (int half_ = 0; half_ < 2; half_++) {
                    const float* sj = s[ks * 2 + half_];
                    aH[ks][half_ * 2 + 0] = packh2(sj[0], sj[1]);
                    aH[ks][half_ * 2 + 1] = packh2(sj[2], sj[3]);
                }

            #pragma unroll
            for (int ks = 0; ks < 4; ks++) {
                #pragma unroll
                for (int ntp = 0; ntp < 8; ntp++) {
                    uint32_t vh[4];
                    int kr = ks * 16 + (lane & 7) + 8 * ((lane >> 3) & 1);
                    int nc = ntp * 16 + 8 * (lane >> 4);
                    ldsm4t(vh, stb + (8704 + kr * 136 + nc) * 2);
                    mma16816(acc[ntp * 2 + 0], aH[ks], &vh[0]);
                    mma16816(acc[ntp * 2 + 1], aH[ks], &vh[2]);
                }
            }
        }
        __syncthreads();
    }

    float inv0 = 1.0f / l_i[0], inv1 = 1.0f / l_i[1];
    #pragma unroll
    for (int nt = 0; nt < 16; nt++) {
        float o0 = acc[nt][0] * inv0, o1 = acc[nt][1] * inv0;
        float o2 = acc[nt][2] * inv1, o3 = acc[nt][3] * inv1;
        size_t col = (size_t)h * D_ + nt * 8 + (lane & 3) * 2;
        size_t r0 = (size_t)(t0 + wrow + (lane >> 2)) * HID_ + col;
        size_t r1 = r0 + 8 * HID_;
        *(uint32_t*)(g_Ah + r0) = packh2(o0, o1);
        *(uint32_t*)(g_Ah + r1) = packh2(o2, o3);
    }
}

// ---------------------------------------------------------------------------
// Launch
// ---------------------------------------------------------------------------
extern "C" void kernel_launch(void* const* d_in, const int* in_sizes, int n_in,
                              void* d_out, int out_size)
{
    const float* hidden = (const float*)d_in[0];
    const float* cosT   = (const float*)d_in[1];
    const float* sinT   = (const float*)d_in[2];
    const float* w_qkv  = (const float*)d_in[3];
    const float* w_o    = (const float*)d_in[4];

    float* out = (float*)d_out;
    float* kc  = out + (size_t)T_ * HID_;
    float* vc  = kc + (size_t)T_ * HID_;

    float* qkvp = nullptr;
    __half *ahp = nullptr, *bhp = nullptr, *whp = nullptr;
    cudaGetSymbolAddress((void**)&qkvp, g_qkv);
    cudaGetSymbolAddress((void**)&ahp, g_Ah);
    cudaGetSymbolAddress((void**)&bhp, g_Bh);
    cudaGetSymbolAddress((void**)&whp, g_Wh);

    int smCount = 148;
    cudaDeviceGetAttribute(&smCount, cudaDevAttrMultiProcessorCount, 0);
    const int pgrid = 2 * smCount;

    cudaFuncSetAttribute(hgemm_kernel,
                         cudaFuncAttributeMaxDynamicSharedMemorySize, G_SMEM);
    cudaFuncSetAttribute(fattn_kernel,
                         cudaFuncAttributeMaxDynamicSharedMemorySize, FA_SMEM_BYTES);

    // 1) conversions: w_qkv transpose + hidden (w_o conv rides in fattn grid)
    conv_all_kernel<<<NB_WQKV + NB_H, 256>>>(hidden, w_qkv);
    // 2) QKV GEMM (persistent, BK=64) -> g_qkv fp32
    hgemm_kernel<<<pgrid, 128, G_SMEM>>>(ahp, bhp, qkvp, 3 * HID_, HID_,
                                         T_ / 128, (T_ / 128) * (3 * HID_ / 128));
    // 3) RoPE + caches + fp16 attention operands
    rope_cache_kernel<<<T_ * H_ / 8, 256>>>(cosT, sinT, kc, vc);
    // 4) flash attention + merged w_o conversion
    fattn_kernel<<<FA_ATTN_BLOCKS + FA_CONV_BLOCKS, 256, FA_SMEM_BYTES>>>(w_o);
    // 5) output projection (persistent, BK=64) -> out
    hgemm_kernel<<<pgrid, 128, G_SMEM>>>(ahp, whp, out, HID_, HID_,
                                         T_ / 128, (T_ / 128) * (HID_ / 128));
}

// round 17
// speedup vs baseline: 2.1210x; 1.0148x over previous
#include <cuda_runtime.h>
#include <cuda_fp16.h>
#include <cstdint>
#include <cstddef>

// Problem constants
constexpr int H_   = 32;
constexpr int D_   = 128;
constexpr int HID_ = 4096;   // H*D
constexpr int B_   = 4;
constexpr int S_   = 1024;
constexpr int T_   = 4096;   // B*S
constexpr float SC2_   = 0.12752966089200528f;  // SCALE * log2(e)

// Scratch (allocation-free rule: __device__ globals)
__device__ float g_qkv[(size_t)T_ * 3 * HID_];   // [T, 3*HID] (Q,K sections used)
__device__ __half g_Ah[(size_t)T_ * HID_];       // A hi (hidden, then ctx)
__device__ __half g_Bh[(size_t)HID_ * 3 * HID_]; // w_qkv^T hi [N][K]
__device__ __half g_Wh[(size_t)HID_ * HID_];     // w_o^T hi
__device__ __half g_Qh[(size_t)T_ * HID_];
__device__ __half g_Kh[(size_t)T_ * HID_];
__device__ __half g_Vh[(size_t)T_ * HID_];

// ---------------------------------------------------------------------------
// helpers
// ---------------------------------------------------------------------------
__device__ __forceinline__ uint32_t smem_u32(const void* p) {
    uint32_t a;
    asm("{ .reg .u64 t; cvta.to.shared.u64 t, %1; cvt.u32.u64 %0, t; }"
        : "=r"(a) : "l"(p));
    return a;
}
__device__ __forceinline__ void cp16(uint32_t dst, const void* src) {
    asm volatile("cp.async.cg.shared.global [%0], [%1], 16;" :: "r"(dst), "l"(src));
}
__device__ __forceinline__ void cp_commit() { asm volatile("cp.async.commit_group;"); }
template<int Ngrp> __device__ __forceinline__ void cp_wait() {
    asm volatile("cp.async.wait_group %0;" :: "n"(Ngrp));
}
__device__ __forceinline__ void ldsm4(uint32_t* r, uint32_t addr) {
    asm volatile("ldmatrix.sync.aligned.m8n8.x4.shared.b16 {%0,%1,%2,%3}, [%4];"
                 : "=r"(r[0]), "=r"(r[1]), "=r"(r[2]), "=r"(r[3]) : "r"(addr));
}
__device__ __forceinline__ void ldsm4t(uint32_t* r, uint32_t addr) {
    asm volatile("ldmatrix.sync.aligned.m8n8.x4.trans.shared.b16 {%0,%1,%2,%3}, [%4];"
                 : "=r"(r[0]), "=r"(r[1]), "=r"(r[2]), "=r"(r[3]) : "r"(addr));
}
__device__ __forceinline__ void mma16816(float* c, const uint32_t* a, const uint32_t* b) {
    asm volatile("mma.sync.aligned.m16n8k16.row.col.f32.f16.f16.f32 "
                 "{%0,%1,%2,%3}, {%4,%5,%6,%7}, {%8,%9}, {%0,%1,%2,%3};"
                 : "+f"(c[0]), "+f"(c[1]), "+f"(c[2]), "+f"(c[3])
                 : "r"(a[0]), "r"(a[1]), "r"(a[2]), "r"(a[3]), "r"(b[0]), "r"(b[1]));
}
__device__ __forceinline__ uint32_t packh2(float x, float y) {
    __half2 p = __halves2half2(__float2half_rn(x), __float2half_rn(y));
    return *(uint32_t*)&p;
}

// ---------------------------------------------------------------------------
// conv_all: one grid for all conversions (hi-only everywhere).
// ---------------------------------------------------------------------------
constexpr int NB_WQKV = (HID_ / 32) * (3 * HID_ / 64);      // 24576
constexpr int NB_WO   = (HID_ / 32) * (HID_ / 64);          // 8192
constexpr int NB_H    = (int)((size_t)T_ * HID_ / 8 / 256); // 8192

__device__ __forceinline__ void convT_body(const float* __restrict__ w,
                                           __half* __restrict__ hi,
                                           int K, int N, int bk, int bn,
                                           float (*t)[65])
{
    const int k0 = bk * 32, n0 = bn * 64;
    const int tx = threadIdx.x & 63, ty = threadIdx.x >> 6;
    #pragma unroll
    for (int i = 0; i < 32; i += 4)
        t[ty + i][tx] = w[(size_t)(k0 + ty + i) * N + n0 + tx];
    __syncthreads();

    const int nl = threadIdx.x >> 2;
    const int kg = threadIdx.x & 3;
    float x[8];
    #pragma unroll
    for (int j = 0; j < 8; j++) x[j] = t[kg * 8 + j][nl];   // conflict-free
    uint4 uh;
    uint32_t* ph = (uint32_t*)&uh;
    #pragma unroll
    for (int j = 0; j < 4; j++) ph[j] = packh2(x[2*j], x[2*j+1]);
    *(uint4*)(hi + (size_t)(n0 + nl) * K + k0 + kg * 8) = uh;
}

__global__ __launch_bounds__(256)
void conv_all_kernel(const float* __restrict__ hidden,
                     const float* __restrict__ w_qkv,
                     const float* __restrict__ w_o)
{
    __shared__ float t[32][65];
    const int bid = blockIdx.x;
    if (bid < NB_WQKV) {
        convT_body(w_qkv, g_Bh, HID_, 3 * HID_, bid & 127, bid >> 7, t);
    } else if (bid < NB_WQKV + NB_WO) {
        const int b2 = bid - NB_WQKV;
        convT_body(w_o, g_Wh, HID_, HID_, b2 & 127, b2 >> 7, t);
    } else {
        const int b2 = bid - NB_WQKV - NB_WO;
        size_t base = ((size_t)b2 * 256 + threadIdx.x) * 8;
        const float4* s = (const float4*)(hidden + base);
        float4 a = s[0], b = s[1];
        float x[8] = {a.x, a.y, a.z, a.w, b.x, b.y, b.z, b.w};
        uint4 uh;
        uint32_t* ph = (uint32_t*)&uh;
        #pragma unroll
        for (int j = 0; j < 4; j++) ph[j] = packh2(x[2*j], x[2*j+1]);
        *(uint4*)(g_Ah + base) = uh;
    }
}

// ---------------------------------------------------------------------------
// Persistent HGEMM: 1-term fp16 (ah*bh), fp32 accum. 128x128 tile, BK=64,
// 3-stage cp.async (32 KB/stage, 96 KB, 2 CTAs/SM), 128 threads (2x2 warps,
// 64x64 warp tile), 1 sync per BK=64 stage.
// QKV=true: V-section tiles (bn>=64) write v_cache fp32 + g_Vh fp16 directly
// (V needs no RoPE); Q/K tiles write g_qkv as usual.
// ---------------------------------------------------------------------------
constexpr int G_STAGE = 32768;            // A 16K | B 16K
constexpr int G_SMEM  = 3 * G_STAGE;      // 96 KB

template<bool QKV>
__global__ __launch_bounds__(128, 2)
void hgemm_kernel(const __half* __restrict__ Ah, const __half* __restrict__ Bh,
                  float* __restrict__ C, int N, int K, int Mtiles, int numTiles,
                  float* __restrict__ vc)
{
    extern __shared__ char sm[];
    const int tid  = threadIdx.x;
    const int wid  = tid >> 5, lane = tid & 31;
    const int wm = (wid >> 1) * 64;
    const int wn = (wid & 1) * 64;
    const int KT = K / 64;
    const uint32_t sb = smem_u32(sm);

    for (int tile = blockIdx.x; tile < numTiles; tile += gridDim.x) {
        const int bm = tile % Mtiles;
        const int bn = tile / Mtiles;
        const __half* aop = Ah + (size_t)bm * 128 * K;
        const __half* bop = Bh + (size_t)bn * 128 * K;

        auto prefetch = [&](int kt) {
            const uint32_t st = sb + (kt % 3) * G_STAGE;
            #pragma unroll
            for (int op = 0; op < 2; op++) {
                const __half* src = (op == 0) ? aop : bop;
                #pragma unroll
                for (int h8 = 0; h8 < 8; h8++) {
                    int ch = h8 * 128 + tid;
                    int row = ch >> 3, c = ch & 7;
                    cp16(st + op * 16384 + row * 128 + ((c ^ (row & 7)) << 4),
                         src + (size_t)row * K + kt * 64 + c * 8);
                }
            }
            cp_commit();
        };

        prefetch(0);
        prefetch(1);

        float acc[4][8][4] = {};

        for (int kt = 0; kt < KT; kt++) {
            if (kt + 1 < KT) cp_wait<1>(); else cp_wait<0>();
            __syncthreads();
            if (kt + 2 < KT) prefetch(kt + 2);

            const uint32_t st = sb + (kt % 3) * G_STAGE;
            #pragma unroll
            for (int ks = 0; ks < 4; ks++) {
                uint32_t ahf[4][4], bhf[4][4];
                #pragma unroll
                for (int mt = 0; mt < 4; mt++) {
                    int row = wm + mt * 16 + (lane & 15);
                    int c   = ks * 2 + (lane >> 4);
                    ldsm4(ahf[mt], st + row * 128 + ((c ^ (row & 7)) << 4));
                }
                #pragma unroll
                for (int p = 0; p < 4; p++) {
                    int n = wn + p * 16 + ((lane >> 4) << 3) + (lane & 7);
                    int c = ks * 2 + ((lane >> 3) & 1);
                    ldsm4(bhf[p], st + 16384 + n * 128 + ((c ^ (n & 7)) << 4));
                }
                #pragma unroll
                for (int mt = 0; mt < 4; mt++)
                    #pragma unroll
                    for (int nt = 0; nt < 8; nt++)
                        mma16816(acc[mt][nt], ahf[mt], &bhf[nt >> 1][(nt & 1) * 2]);
            }
        }

        const bool isV = QKV && (bn >= 64);
        if (isV) {
            #pragma unroll
            for (int mt = 0; mt < 4; mt++)
                #pragma unroll
                for (int nt = 0; nt < 8; nt++) {
                    int r0   = bm * 128 + wm + mt * 16 + (lane >> 2);
                    int colh = (bn - 64) * 128 + wn + nt * 8 + (lane & 3) * 2;
                    size_t o0 = (size_t)r0 * HID_ + colh;
                    size_t o1 = o0 + 8 * HID_;
                    *(float2*)(vc + o0) = make_float2(acc[mt][nt][0], acc[mt][nt][1]);
                    *(float2*)(vc + o1) = make_float2(acc[mt][nt][2], acc[mt][nt][3]);
                    *(uint32_t*)(g_Vh + o0) = packh2(acc[mt][nt][0], acc[mt][nt][1]);
                    *(uint32_t*)(g_Vh + o1) = packh2(acc[mt][nt][2], acc[mt][nt][3]);
                }
        } else {
            #pragma unroll
            for (int mt = 0; mt < 4; mt++)
                #pragma unroll
                for (int nt = 0; nt < 8; nt++) {
                    int r0  = bm * 128 + wm + mt * 16 + (lane >> 2);
                    int col = bn * 128 + wn + nt * 8 + (lane & 3) * 2;
                    *(float2*)(C + (size_t)r0 * N + col) =
                        make_float2(acc[mt][nt][0], acc[mt][nt][1]);
                    *(float2*)(C + (size_t)(r0 + 8) * N + col) =
                        make_float2(acc[mt][nt][2], acc[mt][nt][3]);
                }
        }
    }
}

// ---------------------------------------------------------------------------
// RoPE (Q, K only; V handled in GEMM epilogue). Warp per (t,h).
// ---------------------------------------------------------------------------
__global__ __launch_bounds__(256)
void rope_cache_kernel(const float* __restrict__ cosT,
                       const float* __restrict__ sinT,
                       float* __restrict__ kc)
{
    const int gw = blockIdx.x * 8 + (threadIdx.x >> 5);
    const int t = gw >> 5;
    const int h = gw & 31;
    const int lane = threadIdx.x & 31;

    const float2 c2 = *(const float2*)(cosT + t * 64 + 2 * lane);
    const float2 s2 = *(const float2*)(sinT + t * 64 + 2 * lane);

    const size_t base = (size_t)t * 3 * HID_ + h * D_ + 4 * lane;
    const size_t co   = (size_t)t * HID_ + h * D_ + 4 * lane;

    {
        float4 q = *(const float4*)(g_qkv + base);
        float a0 = q.x * c2.x - q.y * s2.x, a1 = q.y * c2.x + q.x * s2.x;
        float a2 = q.z * c2.y - q.w * s2.y, a3 = q.w * c2.y + q.z * s2.y;
        *(uint2*)(g_Qh + co) = make_uint2(packh2(a0, a1), packh2(a2, a3));
    }
    {
        float4 k = *(const float4*)(g_qkv + base + HID_);
        float b0 = k.x * c2.x - k.y * s2.x, b1 = k.y * c2.x + k.x * s2.x;
        float b2 = k.z * c2.y - k.w * s2.y, b3 = k.w * c2.y + k.z * s2.y;
        *(float4*)(kc + co) = make_float4(b0, b1, b2, b3);
        *(uint2*)(g_Kh + co) = make_uint2(packh2(b0, b1), packh2(b2, b3));
    }
}

// ---------------------------------------------------------------------------
// Flash attention, fp16 MMA (1-term S, 1-term PV), fp32 accum + softmax.
// ---------------------------------------------------------------------------
constexpr int FA_ST = 17408;                      // stage stride in halfs
constexpr int FA_SMEM_BYTES = (17408 + 2 * 17408) * 2;   // 104448

__global__ __launch_bounds__(256, 2)
void fattn_kernel()
{
    extern __shared__ __half fsm[];
    const int tid = threadIdx.x;
    const int wid = tid >> 5, lane = tid & 31;
    const int bid = blockIdx.x;
    const int qt = 7 - (bid >> 7);            // heavy tiles first
    const int h = bid & 31;
    const int b = (bid >> 5) & 3;
    const int t0 = b * S_ + qt * 128;
    const int wrow = wid * 16;
    const uint32_t sb = smem_u32(fsm);

    #pragma unroll
    for (int j = 0; j < 8; j++) {
        int ch = j * 256 + tid;
        int r = ch >> 4, c = ch & 15;
        cp16(sb + (r * 136 + c * 8) * 2,
             g_Qh + (size_t)(t0 + r) * HID_ + h * D_ + c * 8);
    }

    auto kvload = [&](int kt) {
        const uint32_t dstb = sb + (FA_ST + (kt & 1) * FA_ST) * 2;
        const int tk0 = b * S_ + kt * 64;
        const __half* srcs[2] = {g_Kh, g_Vh};
        #pragma unroll
        for (int a = 0; a < 2; a++)
            #pragma unroll
            for (int j = 0; j < 4; j++) {
                int ch = j * 256 + tid;
                int r = ch >> 4, c = ch & 15;
                cp16(dstb + (a * 8704 + r * 136 + c * 8) * 2,
                     srcs[a] + (size_t)(tk0 + r) * HID_ + h * D_ + c * 8);
            }
        cp_commit();
    };

    const int ktmax = 2 * qt + 1;
    kvload(0);

    float acc[16][4] = {};
    float m_i[2] = {-1e30f, -1e30f};
    float l_i[2] = {0.f, 0.f};

    for (int kt = 0; kt <= ktmax; kt++) {
        cp_wait<0>();
        __syncthreads();
        if (kt + 1 <= ktmax) kvload(kt + 1);

        const uint32_t stb = sb + (FA_ST + (kt & 1) * FA_ST) * 2;
        const bool active = (kt * 64 <= qt * 128 + wrow + 15);

        if (active) {
            float s[8][4] = {};
            #pragma unroll
            for (int ks = 0; ks < 8; ks++) {
                uint32_t qh[4];
                {
                    int row = wrow + (lane & 15);
                    int seg = ks * 16 + 8 * (lane >> 4);
                    ldsm4(qh, sb + (row * 136 + seg) * 2);
                }
                #pragma unroll
                for (int np = 0; np < 4; np++) {
                    uint32_t kh[4];
                    int n = np * 16 + ((lane >> 4) << 3) + (lane & 7);
                    int seg = ks * 16 + 8 * ((lane >> 3) & 1);
                    ldsm4(kh, stb + (n * 136 + seg) * 2);
                    mma16816(s[np * 2 + 0], qh, &kh[0]);
                    mma16816(s[np * 2 + 1], qh, &kh[2]);
                }
            }

            const int rbase = qt * 128 + wrow + (lane >> 2);
            if (kt * 64 + 63 > qt * 128 + wrow) {
                #pragma unroll
                for (int j = 0; j < 8; j++)
                    #pragma unroll
                    for (int cc = 0; cc < 4; cc++) {
                        int colg = kt * 64 + j * 8 + (lane & 3) * 2 + (cc & 1);
                        int rowg = rbase + (cc >> 1) * 8;
                        if (colg > rowg) s[j][cc] = -1e30f;
                    }
            }
            #pragma unroll
            for (int j = 0; j < 8; j++)
                #pragma unroll
                for (int cc = 0; cc < 4; cc++) s[j][cc] *= SC2_;

            #pragma unroll
            for (int hr = 0; hr < 2; hr++) {
                float rm = -1e30f;
                #pragma unroll
                for (int j = 0; j < 8; j++)
                    rm = fmaxf(rm, fmaxf(s[j][hr * 2], s[j][hr * 2 + 1]));
                rm = fmaxf(rm, __shfl_xor_sync(0xffffffffu, rm, 1));
                rm = fmaxf(rm, __shfl_xor_sync(0xffffffffu, rm, 2));
                float nm  = fmaxf(m_i[hr], rm);
                float fac = exp2f(m_i[hr] - nm);
                m_i[hr] = nm;
                float rs = 0.f;
                #pragma unroll
                for (int j = 0; j < 8; j++) {
                    float p0 = exp2f(s[j][hr * 2]     - nm);
                    float p1 = exp2f(s[j][hr * 2 + 1] - nm);
                    s[j][hr * 2]     = p0;
                    s[j][hr * 2 + 1] = p1;
                    rs += p0 + p1;
                }
                rs += __shfl_xor_sync(0xffffffffu, rs, 1);
                rs += __shfl_xor_sync(0xffffffffu, rs, 2);
                l_i[hr] = l_i[hr] * fac + rs;
                #pragma unroll
                for (int nt = 0; nt < 16; nt++) {
                    acc[nt][hr * 2]     *= fac;
                    acc[nt][hr * 2 + 1] *= fac;
                }
            }

            uint32_t aH[4][4];
            #pragma unroll
            for (int ks = 0; ks < 4; ks++)
                #pragma unroll
                for (int half_ = 0; half_ < 2; half_++) {
                    const float* sj = s[ks * 2 + half_];
                    aH[ks][half_ * 2 + 0] = packh2(sj[0], sj[1]);
                    aH[ks][half_ * 2 + 1] = packh2(sj[2], sj[3]);
                }

            #pragma unroll
            for (int ks = 0; ks < 4; ks++) {
                #pragma unroll
                for (int ntp = 0; ntp < 8; ntp++) {
                    uint32_t vh[4];
                    int kr = ks * 16 + (lane & 7) + 8 * ((lane >> 3) & 1);
                    int nc = ntp * 16 + 8 * (lane >> 4);
                    ldsm4t(vh, stb + (8704 + kr * 136 + nc) * 2);
                    mma16816(acc[ntp * 2 + 0], aH[ks], &vh[0]);
                    mma16816(acc[ntp * 2 + 1], aH[ks], &vh[2]);
                }
            }
        }
        __syncthreads();
    }

    float inv0 = 1.0f / l_i[0], inv1 = 1.0f / l_i[1];
    #pragma unroll
    for (int nt = 0; nt < 16; nt++) {
        float o0 = acc[nt][0] * inv0, o1 = acc[nt][1] * inv0;
        float o2 = acc[nt][2] * inv1, o3 = acc[nt][3] * inv1;
        size_t col = (size_t)h * D_ + nt * 8 + (lane & 3) * 2;
        size_t r0 = (size_t)(t0 + wrow + (lane >> 2)) * HID_ + col;
        size_t r1 = r0 + 8 * HID_;
        *(uint32_t*)(g_Ah + r0) = packh2(o0, o1);
        *(uint32_t*)(g_Ah + r1) = packh2(o2, o3);
    }
}

// ---------------------------------------------------------------------------
// Launch
// ---------------------------------------------------------------------------
extern "C" void kernel_launch(void* const* d_in, const int* in_sizes, int n_in,
                              void* d_out, int out_size)
{
    const float* hidden = (const float*)d_in[0];
    const float* cosT   = (const float*)d_in[1];
    const float* sinT   = (const float*)d_in[2];
    const float* w_qkv  = (const float*)d_in[3];
    const float* w_o    = (const float*)d_in[4];

    float* out = (float*)d_out;
    float* kc  = out + (size_t)T_ * HID_;
    float* vc  = kc + (size_t)T_ * HID_;

    float* qkvp = nullptr;
    __half *ahp = nullptr, *bhp = nullptr, *whp = nullptr;
    cudaGetSymbolAddress((void**)&qkvp, g_qkv);
    cudaGetSymbolAddress((void**)&ahp, g_Ah);
    cudaGetSymbolAddress((void**)&bhp, g_Bh);
    cudaGetSymbolAddress((void**)&whp, g_Wh);

    int smCount = 148;
    cudaDeviceGetAttribute(&smCount, cudaDevAttrMultiProcessorCount, 0);
    const int pgrid = 2 * smCount;

    cudaFuncSetAttribute(hgemm_kernel<true>,
                         cudaFuncAttributeMaxDynamicSharedMemorySize, G_SMEM);
    cudaFuncSetAttribute(hgemm_kernel<false>,
                         cudaFuncAttributeMaxDynamicSharedMemorySize, G_SMEM);
    cudaFuncSetAttribute(fattn_kernel,
                         cudaFuncAttributeMaxDynamicSharedMemorySize, FA_SMEM_BYTES);

    // 1) conversions (hidden, w_qkv, w_o) — one grid
    conv_all_kernel<<<NB_WQKV + NB_WO + NB_H, 256>>>(hidden, w_qkv, w_o);
    // 2) QKV GEMM (persistent, BK=64; V tiles write vc + g_Vh directly)
    hgemm_kernel<true><<<pgrid, 128, G_SMEM>>>(
        ahp, bhp, qkvp, 3 * HID_, HID_, T_ / 128,
        (T_ / 128) * (3 * HID_ / 128), vc);
    // 3) RoPE (Q,K) + k_cache + fp16 attention operands
    rope_cache_kernel<<<T_ * H_ / 8, 256>>>(cosT, sinT, kc);
    // 4) flash attention -> ctx fp16 into g_Ah
    fattn_kernel<<<1024, 256, FA_SMEM_BYTES>>>();
    // 5) output projection (persistent, BK=64) -> out
    hgemm_kernel<false><<<pgrid, 128, G_SMEM>>>(
        ahp, whp, out, HID_, HID_, T_ / 128,
        (T_ / 128) * (HID_ / 128), nullptr);
}